// round 2
// baseline (speedup 1.0000x reference)
#include <cuda_runtime.h>
#include <math.h>

#define Ndim 256
#define Cdim 512
#define Hdim 256
#define NC   (Ndim*Cdim)   // 131072
#define H2   512           // 2*H
#define HU   1024          // 4*H

// ---------------- scratch (static device globals; no allocs) ----------------
__device__ float g_hin[(size_t)NC*Hdim];
__device__ float g_P  [(size_t)NC*H2];
__device__ float g_Q  [(size_t)NC*H2];
__device__ float g_G  [(size_t)NC*H2];
__device__ float g_agg[(size_t)NC*Hdim];
__device__ float g_h2 [(size_t)NC*Hdim];
__device__ float g_hu [(size_t)NC*Hdim];
__device__ float g_T1 [(size_t)NC*HU];
__device__ unsigned char g_valid[NC];
__device__ int g_vmode;

__device__ __forceinline__ float gelu_exact(float x) {
    return 0.5f * x * (1.0f + erff(x * 0.70710678118654752f));
}

// ---------------- valid dtype detection + normalization ---------------------
// Scans first 4096 bytes: uint8 bool has nonzero bytes at i%4==1 (~50% odds
// per element); float32 0/1 has nonzero only at i%4∈{2,3} (0x80,0x3f);
// int32 0/1 has nonzero only at i%4==0.
__global__ void detect_vmode_kernel(const unsigned char* __restrict__ v) {
    if (threadIdx.x == 0) {
        int nz1 = 0, nz23 = 0;
        for (int i = 0; i < 4096; i += 4) {
            if (v[i+1]) nz1 = 1;
            if (v[i+2] | v[i+3]) nz23 = 1;
        }
        g_vmode = nz1 ? 0 : (nz23 ? 2 : 1);  // 0=uint8, 1=int32, 2=float32
    }
}

__global__ void conv_valid_kernel(const unsigned char* __restrict__ v) {
    int i = blockIdx.x * 256 + threadIdx.x;
    if (i >= NC) return;
    int mode = g_vmode;
    unsigned char r;
    if (mode == 0)      r = v[i] != 0;
    else if (mode == 1) r = ((const int*)v)[i] != 0;
    else                r = ((const unsigned int*)v)[i] != 0u;  // float bits
    g_valid[i] = r;
}

// ---------------- LayerNorm: one row (H=256) per 256-thread block ----------
__global__ void ln_kernel(const float* __restrict__ x,
                          const float* __restrict__ w,
                          const float* __restrict__ b,
                          float* __restrict__ y,
                          int zero_agg) {
    int row = blockIdx.x;
    int t = threadIdx.x;
    float v = x[(size_t)row*Hdim + t];

    __shared__ float red[8];
    __shared__ float stat[2];

    float s = v;
    #pragma unroll
    for (int o = 16; o > 0; o >>= 1) s += __shfl_xor_sync(0xffffffffu, s, o);
    if ((t & 31) == 0) red[t >> 5] = s;
    __syncthreads();
    if (t == 0) {
        float m = 0.f;
        #pragma unroll
        for (int i = 0; i < 8; i++) m += red[i];
        stat[0] = m * (1.0f / Hdim);
    }
    __syncthreads();
    float mu = stat[0];
    float d = v - mu;
    s = d * d;
    #pragma unroll
    for (int o = 16; o > 0; o >>= 1) s += __shfl_xor_sync(0xffffffffu, s, o);
    if ((t & 31) == 0) red[t >> 5] = s;
    __syncthreads();
    if (t == 0) {
        float q = 0.f;
        #pragma unroll
        for (int i = 0; i < 8; i++) q += red[i];
        stat[1] = rsqrtf(q * (1.0f / Hdim) + 1e-5f);
    }
    __syncthreads();
    y[(size_t)row*Hdim + t] = d * stat[1] * w[t] + b[t];
    if (zero_agg) g_agg[(size_t)row*Hdim + t] = 0.f;
}

// ---------------- edge pre-activation + GELU -> g_G -------------------------
// dir==0 (fwd): pre = P[i] + Q[j] + [ +unit,dist]@W1e + b1  (target later: i)
// dir==1 (rev): pre = P[j] + Q[i] + [ -unit,dist]@W1e + b1  (target later: j)
__global__ void edge_pre_kernel(const float* __restrict__ xyz,
                                const float* __restrict__ w1,
                                const float* __restrict__ b1,
                                int off, int dir, int Ce) {
    int m = blockIdx.x;
    int nidx = m / Ce;
    int c = m - nidx * Ce;
    int i = nidx * Cdim + c;
    int j = i + off;

    __shared__ float ef[4];
    if (threadIdx.x == 0) {
        float dx = xyz[3*j+0] - xyz[3*i+0];
        float dy = xyz[3*j+1] - xyz[3*i+1];
        float dz = xyz[3*j+2] - xyz[3*i+2];
        float d = fmaxf(sqrtf(dx*dx + dy*dy + dz*dz), 1e-6f);
        float sgn = dir ? -1.0f : 1.0f;
        float inv = sgn / d;
        ef[0] = dx * inv; ef[1] = dy * inv; ef[2] = dz * inv; ef[3] = d;
    }
    __syncthreads();

    int pi = dir ? j : i;
    int qi = dir ? i : j;
    int f = threadIdx.x * 4;

    float4 p  = *(const float4*)(g_P + (size_t)pi*H2 + f);
    float4 q  = *(const float4*)(g_Q + (size_t)qi*H2 + f);
    float4 bb = *(const float4*)(b1 + f);
    float4 w0 = *(const float4*)(w1 + (size_t)(2*Hdim + 0)*H2 + f);
    float4 w1r= *(const float4*)(w1 + (size_t)(2*Hdim + 1)*H2 + f);
    float4 w2r= *(const float4*)(w1 + (size_t)(2*Hdim + 2)*H2 + f);
    float4 w3r= *(const float4*)(w1 + (size_t)(2*Hdim + 3)*H2 + f);
    float e0 = ef[0], e1 = ef[1], e2 = ef[2], e3 = ef[3];

    float4 r;
    r.x = gelu_exact(p.x + q.x + bb.x + e0*w0.x + e1*w1r.x + e2*w2r.x + e3*w3r.x);
    r.y = gelu_exact(p.y + q.y + bb.y + e0*w0.y + e1*w1r.y + e2*w2r.y + e3*w3r.y);
    r.z = gelu_exact(p.z + q.z + bb.z + e0*w0.z + e1*w1r.z + e2*w2r.z + e3*w3r.z);
    r.w = gelu_exact(p.w + q.w + bb.w + e0*w0.w + e1*w1r.w + e2*w2r.w + e3*w3r.w);
    *(float4*)(g_G + (size_t)m*H2 + f) = r;
}

// ---------------- h2 = h + agg*valid ----------------------------------------
__global__ void h2_kernel(const float* __restrict__ h) {
    int row = blockIdx.x;
    int t = threadIdx.x;
    size_t idx = (size_t)row*Hdim + t;
    float vf = g_valid[row] ? 1.0f : 0.0f;
    g_h2[idx] = h[idx] + g_agg[idx] * vf;
}

// ---------------- tiled GEMM: C = A(MxK) @ B(KxN), row-major ----------------
// EPI 0: plain store; 1: gelu(acc+bias) store; 2: agg[target] += (acc+bias)*v;
// EPI 3: out = (aux + acc + bias) * valid
#define BM 64
#define BN 64
#define BK 16

template<int EPI>
__global__ void __launch_bounds__(256)
gemm_kernel(const float* __restrict__ A, int lda,
            const float* __restrict__ B, int ldb,
            const float* __restrict__ bias,
            float* __restrict__ Cout, int ldc,
            const float* __restrict__ aux,
            int K, int off, int dir, int Ce) {
    __shared__ float As[BK][BM];
    __shared__ float Bs[BK][BN];

    int tid = threadIdx.x;
    int m0 = blockIdx.y * BM, n0 = blockIdx.x * BN;
    int arow = tid >> 2,  ak = (tid & 3) << 2;
    int brow = tid >> 4,  bn = (tid & 15) << 2;
    int tr   = tid >> 4,  tc = tid & 15;

    float acc[4][4] = {};
    const float* Aptr = A + (size_t)(m0 + arow) * lda + ak;
    const float* Bptr = B + (size_t)brow * ldb + n0 + bn;

    for (int k0 = 0; k0 < K; k0 += BK) {
        float4 av = *(const float4*)(Aptr + k0);
        As[ak+0][arow] = av.x; As[ak+1][arow] = av.y;
        As[ak+2][arow] = av.z; As[ak+3][arow] = av.w;
        float4 bv = *(const float4*)(Bptr + (size_t)k0 * ldb);
        *(float4*)&Bs[brow][bn] = bv;
        __syncthreads();
        #pragma unroll
        for (int kk = 0; kk < BK; kk++) {
            float4 a = *(const float4*)&As[kk][tr*4];
            float4 b = *(const float4*)&Bs[kk][tc*4];
            float ar[4] = {a.x, a.y, a.z, a.w};
            float br[4] = {b.x, b.y, b.z, b.w};
            #pragma unroll
            for (int i = 0; i < 4; i++)
                #pragma unroll
                for (int j = 0; j < 4; j++)
                    acc[i][j] += ar[i] * br[j];
        }
        __syncthreads();
    }

    int col0 = n0 + tc * 4;
    #pragma unroll
    for (int i = 0; i < 4; i++) {
        int m = m0 + tr * 4 + i;
        if (EPI == 0) {
            float4 r = {acc[i][0], acc[i][1], acc[i][2], acc[i][3]};
            *(float4*)(Cout + (size_t)m * ldc + col0) = r;
        } else if (EPI == 1) {
            float4 r;
            r.x = gelu_exact(acc[i][0] + bias[col0+0]);
            r.y = gelu_exact(acc[i][1] + bias[col0+1]);
            r.z = gelu_exact(acc[i][2] + bias[col0+2]);
            r.w = gelu_exact(acc[i][3] + bias[col0+3]);
            *(float4*)(Cout + (size_t)m * ldc + col0) = r;
        } else if (EPI == 2) {
            int nidx = m / Ce;
            int c = m - nidx * Ce;
            int ii = nidx * Cdim + c;
            int jj = ii + off;
            if (g_valid[ii] && g_valid[jj]) {
                int tgt = dir ? jj : ii;
                float* d = g_agg + (size_t)tgt * Hdim + col0;
                d[0] += acc[i][0] + bias[col0+0];
                d[1] += acc[i][1] + bias[col0+1];
                d[2] += acc[i][2] + bias[col0+2];
                d[3] += acc[i][3] + bias[col0+3];
            }
        } else { // EPI == 3
            float vf = g_valid[m] ? 1.0f : 0.0f;
            const float* a2 = aux + (size_t)m * Hdim + col0;
            float4 r;
            r.x = (a2[0] + acc[i][0] + bias[col0+0]) * vf;
            r.y = (a2[1] + acc[i][1] + bias[col0+1]) * vf;
            r.z = (a2[2] + acc[i][2] + bias[col0+2]) * vf;
            r.w = (a2[3] + acc[i][3] + bias[col0+3]) * vf;
            *(float4*)(Cout + (size_t)m * ldc + col0) = r;
        }
    }
}

// ---------------- launch -----------------------------------------------------
extern "C" void kernel_launch(void* const* d_in, const int* in_sizes, int n_in,
                              void* d_out, int out_size) {
    const float*         h      = (const float*)d_in[0];
    const float*         xyz    = (const float*)d_in[1];
    const unsigned char* validb = (const unsigned char*)d_in[2];
    const float*         ln_n_w = (const float*)d_in[3];
    const float*         ln_n_b = (const float*)d_in[4];
    const float*         w1     = (const float*)d_in[5];
    const float*         b1     = (const float*)d_in[6];
    const float*         w2     = (const float*)d_in[7];
    const float*         b2     = (const float*)d_in[8];
    const float*         ln_u_w = (const float*)d_in[9];
    const float*         ln_u_b = (const float*)d_in[10];
    const float*         u1     = (const float*)d_in[11];
    const float*         bu1    = (const float*)d_in[12];
    const float*         u2     = (const float*)d_in[13];
    const float*         bu2    = (const float*)d_in[14];
    float* out = (float*)d_out;

    float *pHin, *pP, *pQ, *pG, *pH2, *pHu, *pT1;
    cudaGetSymbolAddress((void**)&pHin, g_hin);
    cudaGetSymbolAddress((void**)&pP,   g_P);
    cudaGetSymbolAddress((void**)&pQ,   g_Q);
    cudaGetSymbolAddress((void**)&pG,   g_G);
    cudaGetSymbolAddress((void**)&pH2,  g_h2);
    cudaGetSymbolAddress((void**)&pHu,  g_hu);
    cudaGetSymbolAddress((void**)&pT1,  g_T1);

    // 0. normalize valid -> g_valid (uint8), robust to uint8/int32/float32
    detect_vmode_kernel<<<1, 32>>>(validb);
    conv_valid_kernel<<<(NC + 255) / 256, 256>>>(validb);

    // 1. h_in = LN(h), and zero agg
    ln_kernel<<<NC, 256>>>(h, ln_n_w, ln_n_b, pHin, 1);

    // 2. P = h_in @ w1[0:256,:], Q = h_in @ w1[256:512,:]
    gemm_kernel<0><<<dim3(H2/BN, NC/BM), 256>>>(pHin, Hdim, w1, H2,
                                                nullptr, pP, H2, nullptr,
                                                Hdim, 0, 0, 0);
    gemm_kernel<0><<<dim3(H2/BN, NC/BM), 256>>>(pHin, Hdim, w1 + (size_t)Hdim*H2, H2,
                                                nullptr, pQ, H2, nullptr,
                                                Hdim, 0, 0, 0);

    // 3. edge messages: per (offset, direction) -> G = gelu(pre); agg += (G@w2 + b2)*v
    const int offs[4] = {1, 2, 4, 8};
    for (int oi = 0; oi < 4; oi++) {
        int off = offs[oi];
        int Ce = Cdim - off;
        int Me = Ndim * Ce;              // multiple of 64
        for (int dir = 0; dir < 2; dir++) {
            edge_pre_kernel<<<Me, 128>>>(xyz, w1, b1, off, dir, Ce);
            gemm_kernel<2><<<dim3(Hdim/BN, Me/BM), 256>>>(pG, H2, w2, Hdim,
                                                          b2, nullptr, Hdim, nullptr,
                                                          H2, off, dir, Ce);
        }
    }

    // 4. h2 = h + agg * valid
    h2_kernel<<<NC, 256>>>(h);

    // 5. update MLP: hu = LN(h2); T1 = gelu(hu@u1+bu1); out = (h2 + T1@u2+bu2)*valid
    ln_kernel<<<NC, 256>>>(pH2, ln_u_w, ln_u_b, pHu, 0);
    gemm_kernel<1><<<dim3(HU/BN, NC/BM), 256>>>(pHu, Hdim, u1, HU,
                                                bu1, pT1, HU, nullptr,
                                                Hdim, 0, 0, 0);
    gemm_kernel<3><<<dim3(Hdim/BN, NC/BM), 256>>>(pT1, HU, u2, Hdim,
                                                  bu2, out, Hdim, pH2,
                                                  HU, 0, 0, 0);
    (void)in_sizes; (void)n_in; (void)out_size;
}

// round 4
// speedup vs baseline: 2.2324x; 2.2324x over previous
#include <cuda_runtime.h>
#include <math.h>
#include <stdint.h>

#define Ndim 256
#define Cdim 512
#define Hdim 256
#define NC   (Ndim*Cdim)   // 131072
#define H2   512           // 2*H
#define HU   1024          // 4*H

#if defined(__CUDA_ARCH_FEAT_SM103_ALL) || defined(__CUDA_ARCH_FEAT_SM100_ALL) || \
    (defined(__CUDA_ARCH_SPECIFIC__) && (__CUDA_ARCH_SPECIFIC__ >= 1000))
#define HAS_TC 1
#else
#define HAS_TC 0
#endif

// ---------------- scratch (static device globals; no allocs) ----------------
__device__ float g_hin[(size_t)NC*Hdim];
__device__ float g_P  [(size_t)NC*H2];
__device__ float g_Q  [(size_t)NC*H2];
__device__ float g_G  [(size_t)NC*H2];
__device__ float g_agg[(size_t)NC*Hdim];
__device__ float g_h2 [(size_t)NC*Hdim];
__device__ float g_hu [(size_t)NC*Hdim];
__device__ float g_T1 [(size_t)NC*HU];
__device__ float g_w1at[(size_t)H2*Hdim];   // [512,256]  (W1a^T)
__device__ float g_w1bt[(size_t)H2*Hdim];   // [512,256]  (W1b^T)
__device__ float g_w2t [(size_t)Hdim*H2];   // [256,512]  (w2^T)
__device__ float g_u1t [(size_t)HU*Hdim];   // [1024,256] (u1^T)
__device__ float g_u2t [(size_t)Hdim*HU];   // [256,1024] (u2^T)
__device__ unsigned char g_valid[NC];
__device__ int g_vmode;

__device__ __forceinline__ float gelu_exact(float x) {
    return 0.5f * x * (1.0f + erff(x * 0.70710678118654752f));
}

// ---------------- valid dtype detection + normalization ---------------------
__global__ void detect_vmode_kernel(const unsigned char* __restrict__ v) {
    if (threadIdx.x == 0) {
        int nz1 = 0, nz23 = 0;
        for (int i = 0; i < 4096; i += 4) {
            if (v[i+1]) nz1 = 1;
            if (v[i+2] | v[i+3]) nz23 = 1;
        }
        g_vmode = nz1 ? 0 : (nz23 ? 2 : 1);  // 0=uint8, 1=int32, 2=float32
    }
}

__global__ void conv_valid_kernel(const unsigned char* __restrict__ v) {
    int i = blockIdx.x * 256 + threadIdx.x;
    if (i >= NC) return;
    int mode = g_vmode;
    unsigned char r;
    if (mode == 0)      r = v[i] != 0;
    else if (mode == 1) r = ((const int*)v)[i] != 0;
    else                r = ((const unsigned int*)v)[i] != 0u;
    g_valid[i] = r;
}

// ---------------- weight transpose: Bt[n*K+k] = B[k*N+n] --------------------
__global__ void transpose_kernel(const float* __restrict__ B,
                                 float* __restrict__ Bt, int K, int N) {
    int idx = blockIdx.x * 256 + threadIdx.x;
    if (idx >= K * N) return;
    int k = idx / N, n = idx - k * N;
    Bt[(size_t)n * K + k] = B[idx];
}

// ---------------- LayerNorm --------------------------------------------------
__global__ void ln_kernel(const float* __restrict__ x,
                          const float* __restrict__ w,
                          const float* __restrict__ b,
                          float* __restrict__ y,
                          int zero_agg) {
    int row = blockIdx.x;
    int t = threadIdx.x;
    float v = x[(size_t)row*Hdim + t];

    __shared__ float red[8];
    __shared__ float stat[2];

    float s = v;
    #pragma unroll
    for (int o = 16; o > 0; o >>= 1) s += __shfl_xor_sync(0xffffffffu, s, o);
    if ((t & 31) == 0) red[t >> 5] = s;
    __syncthreads();
    if (t == 0) {
        float m = 0.f;
        #pragma unroll
        for (int i = 0; i < 8; i++) m += red[i];
        stat[0] = m * (1.0f / Hdim);
    }
    __syncthreads();
    float mu = stat[0];
    float d = v - mu;
    s = d * d;
    #pragma unroll
    for (int o = 16; o > 0; o >>= 1) s += __shfl_xor_sync(0xffffffffu, s, o);
    if ((t & 31) == 0) red[t >> 5] = s;
    __syncthreads();
    if (t == 0) {
        float q = 0.f;
        #pragma unroll
        for (int i = 0; i < 8; i++) q += red[i];
        stat[1] = rsqrtf(q * (1.0f / Hdim) + 1e-5f);
    }
    __syncthreads();
    y[(size_t)row*Hdim + t] = d * stat[1] * w[t] + b[t];
    if (zero_agg) g_agg[(size_t)row*Hdim + t] = 0.f;
}

// ---------------- edge pre-activation + GELU -> g_G -------------------------
__global__ void edge_pre_kernel(const float* __restrict__ xyz,
                                const float* __restrict__ w1,
                                const float* __restrict__ b1,
                                int off, int dir, int Ce) {
    int m = blockIdx.x;
    int nidx = m / Ce;
    int c = m - nidx * Ce;
    int i = nidx * Cdim + c;
    int j = i + off;

    __shared__ float ef[4];
    if (threadIdx.x == 0) {
        float dx = xyz[3*j+0] - xyz[3*i+0];
        float dy = xyz[3*j+1] - xyz[3*i+1];
        float dz = xyz[3*j+2] - xyz[3*i+2];
        float d = fmaxf(sqrtf(dx*dx + dy*dy + dz*dz), 1e-6f);
        float sgn = dir ? -1.0f : 1.0f;
        float inv = sgn / d;
        ef[0] = dx * inv; ef[1] = dy * inv; ef[2] = dz * inv; ef[3] = d;
    }
    __syncthreads();

    int pi = dir ? j : i;
    int qi = dir ? i : j;
    int f = threadIdx.x * 4;

    float4 p  = *(const float4*)(g_P + (size_t)pi*H2 + f);
    float4 q  = *(const float4*)(g_Q + (size_t)qi*H2 + f);
    float4 bb = *(const float4*)(b1 + f);
    float4 w0 = *(const float4*)(w1 + (size_t)(2*Hdim + 0)*H2 + f);
    float4 w1r= *(const float4*)(w1 + (size_t)(2*Hdim + 1)*H2 + f);
    float4 w2r= *(const float4*)(w1 + (size_t)(2*Hdim + 2)*H2 + f);
    float4 w3r= *(const float4*)(w1 + (size_t)(2*Hdim + 3)*H2 + f);
    float e0 = ef[0], e1 = ef[1], e2 = ef[2], e3 = ef[3];

    float4 r;
    r.x = gelu_exact(p.x + q.x + bb.x + e0*w0.x + e1*w1r.x + e2*w2r.x + e3*w3r.x);
    r.y = gelu_exact(p.y + q.y + bb.y + e0*w0.y + e1*w1r.y + e2*w2r.y + e3*w3r.y);
    r.z = gelu_exact(p.z + q.z + bb.z + e0*w0.z + e1*w1r.z + e2*w2r.z + e3*w3r.z);
    r.w = gelu_exact(p.w + q.w + bb.w + e0*w0.w + e1*w1r.w + e2*w2r.w + e3*w3r.w);
    *(float4*)(g_G + (size_t)m*H2 + f) = r;
}

// ---------------- h2 = h + agg*valid -----------------------------------------
__global__ void h2_kernel(const float* __restrict__ h) {
    int row = blockIdx.x;
    int t = threadIdx.x;
    size_t idx = (size_t)row*Hdim + t;
    float vf = g_valid[row] ? 1.0f : 0.0f;
    g_h2[idx] = h[idx] + g_agg[idx] * vf;
}

// ============================================================================
// GEMM: C[M,N] = A[M,K] @ Bt[N,K]^T.
// sm_103a cubin pass: tcgen05 tf32 SS MMA, 128x128 tile, 2-stage pipeline.
// compute_103 PTX pass / other: SIMT fallback (same tile, 8x8 per thread).
// ============================================================================
__device__ __forceinline__ uint32_t f2tf(float f) {
    uint32_t r;
    asm("cvt.rna.tf32.f32 %0, %1;" : "=r"(r) : "f"(f));
    return r;
}
__device__ __forceinline__ uint32_t smem_u32(const void* p) {
    uint32_t a;
    asm("{ .reg .u64 t; cvta.to.shared.u64 t, %1; cvt.u32.u64 %0, t; }" : "=r"(a) : "l"(p));
    return a;
}
__device__ __forceinline__ void mbar_wait(uint32_t mbar, uint32_t parity) {
    asm volatile(
        "{\n\t.reg .pred P1;\n\t"
        "W_%=:\n\t"
        "mbarrier.try_wait.parity.acquire.cta.shared::cta.b64 P1, [%0], %1, 0x989680;\n\t"
        "@P1 bra.uni D_%=;\n\t"
        "bra.uni W_%=;\n\t"
        "D_%=:\n\t}"
        :: "r"(mbar), "r"(parity) : "memory");
}

#if HAS_TC
__device__ __forceinline__ void mma_tf32_ss(uint32_t d_tmem, uint64_t a_desc,
                                            uint64_t b_desc, uint32_t idesc, bool acc) {
    uint32_t en = acc ? 1u : 0u;
    asm volatile(
        "{\n\t.reg .pred p;\n\t"
        "setp.ne.u32 p, %5, 0;\n\t"
        "tcgen05.mma.cta_group::1.kind::tf32 [%0], %1, %2, %3, {%4, %4, %4, %4}, p;\n\t"
        "}"
        :: "r"(d_tmem), "l"(a_desc), "l"(b_desc), "r"(idesc), "r"(0u), "r"(en)
        : "memory");
}
#define LDTM_X32(r, addr) \
    asm volatile( \
        "tcgen05.ld.sync.aligned.32x32b.x32.b32 " \
        "{%0, %1, %2, %3, %4, %5, %6, %7, " \
        " %8, %9, %10, %11, %12, %13, %14, %15, " \
        " %16, %17, %18, %19, %20, %21, %22, %23, " \
        " %24, %25, %26, %27, %28, %29, %30, %31}, [%32];" \
        : "=r"((r)[0]),  "=r"((r)[1]),  "=r"((r)[2]),  "=r"((r)[3]), \
          "=r"((r)[4]),  "=r"((r)[5]),  "=r"((r)[6]),  "=r"((r)[7]), \
          "=r"((r)[8]),  "=r"((r)[9]),  "=r"((r)[10]), "=r"((r)[11]), \
          "=r"((r)[12]), "=r"((r)[13]), "=r"((r)[14]), "=r"((r)[15]), \
          "=r"((r)[16]), "=r"((r)[17]), "=r"((r)[18]), "=r"((r)[19]), \
          "=r"((r)[20]), "=r"((r)[21]), "=r"((r)[22]), "=r"((r)[23]), \
          "=r"((r)[24]), "=r"((r)[25]), "=r"((r)[26]), "=r"((r)[27]), \
          "=r"((r)[28]), "=r"((r)[29]), "=r"((r)[30]), "=r"((r)[31]) \
        : "r"(addr))
#endif

static constexpr unsigned long long DESC_BASE =
    (2ull << 61) | (1ull << 46) | (64ull << 32) | (1ull << 16);  // SW128 K-major
// idesc: cfmt=F32(1)<<4, a=TF32(2)<<7, b=TF32(2)<<10, N=128 -> 16<<17, M=128 -> 8<<24
#define MMA_IDESC ((1u<<4) | (2u<<7) | (2u<<10) | (16u<<17) | (8u<<24))
#define SMEM_DYN  (1024 + 65536 + 64)

// EPI 0: plain store; 1: gelu(acc+bias); 2: agg[target] += (acc+bias) if valid;
// EPI 3: out = (aux + acc + bias) * valid
template<int EPI>
__global__ void __launch_bounds__(256)
mma_gemm(const float* __restrict__ A, int lda,
         const float* __restrict__ Bt,   // [N, K] row-major
         const float* __restrict__ bias,
         float* __restrict__ Cout, int ldc,
         const float* __restrict__ aux,
         int K, int off, int dir, int Ce) {
    extern __shared__ char dyn[];
    int tid = threadIdx.x;
    int m0 = blockIdx.y * 128;
    int n0 = blockIdx.x * 128;

#if HAS_TC
    uint32_t u0 = smem_u32(dyn);
    uint32_t pad = (1024u - (u0 & 1023u)) & 1023u;
    char* base = dyn + pad;
    uint32_t ub = u0 + pad;

    // layout: A0 @0, A1 @16K, B0 @32K, B1 @48K, ctrl @64K (tmem ptr, mbar0, mbar1)
    uint32_t ctrl  = ub + 65536;
    uint32_t mbar0 = ctrl + 8;

    int wid = tid >> 5;
    int lane = tid & 31;

    if (tid == 0) {
        asm volatile("mbarrier.init.shared.b64 [%0], 1;" :: "r"(mbar0)     : "memory");
        asm volatile("mbarrier.init.shared.b64 [%0], 1;" :: "r"(mbar0 + 8) : "memory");
    }
    if (wid == 0) {
        asm volatile("tcgen05.alloc.cta_group::1.sync.aligned.shared::cta.b32 [%0], %1;"
                     :: "r"(ctrl), "r"(128u) : "memory");
        asm volatile("tcgen05.relinquish_alloc_permit.cta_group::1.sync.aligned;");
    }
    __syncthreads();
    uint32_t tmem;
    asm volatile("ld.shared.b32 %0, [%1];" : "=r"(tmem) : "r"(ctrl));

    const int NCH = K >> 5;
    for (int c = 0; c < NCH; c++) {
        int buf = c & 1;
        if (c >= 2) mbar_wait(mbar0 + 8u * buf, (uint32_t)(((c - 2) >> 1) & 1));
        char* sA = base + buf * 16384;
        char* sB = base + 32768 + buf * 16384;
        int k0 = c << 5;

        #pragma unroll
        for (int i = 0; i < 4; i++) {
            int idx = tid + i * 256;
            int r = idx >> 3, f4 = idx & 7;
            float4 av = *(const float4*)(A + (size_t)(m0 + r) * lda + k0 + f4 * 4);
            uint4 tv;
            tv.x = f2tf(av.x); tv.y = f2tf(av.y); tv.z = f2tf(av.z); tv.w = f2tf(av.w);
            uint32_t so = (uint32_t)(r * 128 + f4 * 16);
            so ^= (so >> 3) & 0x70u;
            *(uint4*)(sA + so) = tv;

            float4 bv = *(const float4*)(Bt + (size_t)(n0 + r) * K + k0 + f4 * 4);
            uint4 tb;
            tb.x = f2tf(bv.x); tb.y = f2tf(bv.y); tb.z = f2tf(bv.z); tb.w = f2tf(bv.w);
            *(uint4*)(sB + so) = tb;
        }
        asm volatile("fence.proxy.async.shared::cta;" ::: "memory");
        __syncthreads();

        if (tid == 0) {
            uint32_t aaddr = ub + (uint32_t)(buf * 16384);
            uint32_t baddr = ub + (uint32_t)(32768 + buf * 16384);
            uint64_t adesc = DESC_BASE | (uint64_t)((aaddr >> 4) & 0x3FFFu);
            uint64_t bdesc = DESC_BASE | (uint64_t)((baddr >> 4) & 0x3FFFu);
            #pragma unroll
            for (int s = 0; s < 4; s++) {
                mma_tf32_ss(tmem, adesc + 2u * s, bdesc + 2u * s, MMA_IDESC,
                            !(c == 0 && s == 0));
            }
            asm volatile(
                "tcgen05.commit.cta_group::1.mbarrier::arrive::one.shared::cluster.b64 [%0];"
                :: "r"(mbar0 + 8u * buf) : "memory");
        }
    }
    mbar_wait(mbar0 + 8u * ((NCH - 2) & 1), (uint32_t)(((NCH - 2) >> 1) & 1));
    mbar_wait(mbar0 + 8u * ((NCH - 1) & 1), (uint32_t)(((NCH - 1) >> 1) & 1));
    asm volatile("tcgen05.fence::after_thread_sync;" ::: "memory");

    // ---------------- epilogue: warps 0-3 read TMEM D ----------------
    if (wid < 4) {
        int trow = wid * 32 + lane;
        int m = m0 + trow;
        int tgt = 0; bool do_write = true;
        if (EPI == 2) {
            int nidx = m / Ce;
            int cc2 = m - nidx * Ce;
            int ii = nidx * Cdim + cc2;
            int jj = ii + off;
            do_write = (g_valid[ii] && g_valid[jj]);
            tgt = dir ? jj : ii;
        }
        float vf = 1.0f;
        if (EPI == 3) vf = g_valid[m] ? 1.0f : 0.0f;

        #pragma unroll
        for (int cc = 0; cc < 128; cc += 32) {
            uint32_t r[32];
            LDTM_X32(r, tmem + (uint32_t)cc);
            asm volatile("tcgen05.wait::ld.sync.aligned;" ::: "memory");
            int col0 = n0 + cc;
            if (EPI == 0) {
                #pragma unroll
                for (int j = 0; j < 32; j += 4) {
                    float4 o = {__uint_as_float(r[j]), __uint_as_float(r[j+1]),
                                __uint_as_float(r[j+2]), __uint_as_float(r[j+3])};
                    *(float4*)(Cout + (size_t)m * ldc + col0 + j) = o;
                }
            } else if (EPI == 1) {
                #pragma unroll
                for (int j = 0; j < 32; j += 4) {
                    float4 o;
                    o.x = gelu_exact(__uint_as_float(r[j])   + __ldg(&bias[col0+j]));
                    o.y = gelu_exact(__uint_as_float(r[j+1]) + __ldg(&bias[col0+j+1]));
                    o.z = gelu_exact(__uint_as_float(r[j+2]) + __ldg(&bias[col0+j+2]));
                    o.w = gelu_exact(__uint_as_float(r[j+3]) + __ldg(&bias[col0+j+3]));
                    *(float4*)(Cout + (size_t)m * ldc + col0 + j) = o;
                }
            } else if (EPI == 2) {
                if (do_write) {
                    float* d = g_agg + (size_t)tgt * Hdim + col0;
                    #pragma unroll
                    for (int j = 0; j < 32; j += 4) {
                        float4 old = *(float4*)(d + j);
                        old.x += __uint_as_float(r[j])   + __ldg(&bias[col0+j]);
                        old.y += __uint_as_float(r[j+1]) + __ldg(&bias[col0+j+1]);
                        old.z += __uint_as_float(r[j+2]) + __ldg(&bias[col0+j+2]);
                        old.w += __uint_as_float(r[j+3]) + __ldg(&bias[col0+j+3]);
                        *(float4*)(d + j) = old;
                    }
                }
            } else { // EPI == 3
                const float* a2 = aux + (size_t)m * Hdim + col0;
                #pragma unroll
                for (int j = 0; j < 32; j += 4) {
                    float4 av = *(const float4*)(a2 + j);
                    float4 o;
                    o.x = (av.x + __uint_as_float(r[j])   + __ldg(&bias[col0+j]))   * vf;
                    o.y = (av.y + __uint_as_float(r[j+1]) + __ldg(&bias[col0+j+1])) * vf;
                    o.z = (av.z + __uint_as_float(r[j+2]) + __ldg(&bias[col0+j+2])) * vf;
                    o.w = (av.w + __uint_as_float(r[j+3]) + __ldg(&bias[col0+j+3])) * vf;
                    *(float4*)(Cout + (size_t)m * ldc + col0 + j) = o;
                }
            }
        }
    }
    __syncthreads();
    if (wid == 0) {
        asm volatile("tcgen05.dealloc.cta_group::1.sync.aligned.b32 %0, %1;"
                     :: "r"(tmem), "r"(128u));
    }

#else  // ---------------- SIMT fallback (compute_103 PTX pass) ----------------
    float* As = (float*)dyn;            // [16][128]
    float* Bs = (float*)(dyn + 8192);   // [16][128]

    int tr = tid >> 4, tc = tid & 15;
    float acc[8][8] = {};

    int lrow = tid >> 1;
    int lk   = (tid & 1) * 8;

    for (int k0 = 0; k0 < K; k0 += 16) {
        #pragma unroll
        for (int e = 0; e < 8; e += 4) {
            float4 av = *(const float4*)(A + (size_t)(m0 + lrow) * lda + k0 + lk + e);
            As[(lk+e+0)*128 + lrow] = av.x;
            As[(lk+e+1)*128 + lrow] = av.y;
            As[(lk+e+2)*128 + lrow] = av.z;
            As[(lk+e+3)*128 + lrow] = av.w;
            float4 bv = *(const float4*)(Bt + (size_t)(n0 + lrow) * K + k0 + lk + e);
            Bs[(lk+e+0)*128 + lrow] = bv.x;
            Bs[(lk+e+1)*128 + lrow] = bv.y;
            Bs[(lk+e+2)*128 + lrow] = bv.z;
            Bs[(lk+e+3)*128 + lrow] = bv.w;
        }
        __syncthreads();
        #pragma unroll
        for (int k = 0; k < 16; k++) {
            float a[8], b[8];
            #pragma unroll
            for (int i = 0; i < 8; i++) a[i] = As[k*128 + tr*8 + i];
            #pragma unroll
            for (int j = 0; j < 8; j++) b[j] = Bs[k*128 + tc*8 + j];
            #pragma unroll
            for (int i = 0; i < 8; i++)
                #pragma unroll
                for (int j = 0; j < 8; j++)
                    acc[i][j] += a[i] * b[j];
        }
        __syncthreads();
    }

    int col0 = n0 + tc * 8;
    #pragma unroll
    for (int i = 0; i < 8; i++) {
        int m = m0 + tr * 8 + i;
        if (EPI == 0) {
            #pragma unroll
            for (int j = 0; j < 8; j++)
                Cout[(size_t)m * ldc + col0 + j] = acc[i][j];
        } else if (EPI == 1) {
            #pragma unroll
            for (int j = 0; j < 8; j++)
                Cout[(size_t)m * ldc + col0 + j] =
                    gelu_exact(acc[i][j] + bias[col0 + j]);
        } else if (EPI == 2) {
            int nidx = m / Ce;
            int cc2 = m - nidx * Ce;
            int ii = nidx * Cdim + cc2;
            int jj = ii + off;
            if (g_valid[ii] && g_valid[jj]) {
                int tgt = dir ? jj : ii;
                float* d = g_agg + (size_t)tgt * Hdim + col0;
                #pragma unroll
                for (int j = 0; j < 8; j++)
                    d[j] += acc[i][j] + bias[col0 + j];
            }
        } else {
            float vf = g_valid[m] ? 1.0f : 0.0f;
            const float* a2 = aux + (size_t)m * Hdim + col0;
            #pragma unroll
            for (int j = 0; j < 8; j++)
                Cout[(size_t)m * ldc + col0 + j] =
                    (a2[j] + acc[i][j] + bias[col0 + j]) * vf;
        }
    }
#endif
}

// ---------------- launch -----------------------------------------------------
extern "C" void kernel_launch(void* const* d_in, const int* in_sizes, int n_in,
                              void* d_out, int out_size) {
    const float*         h      = (const float*)d_in[0];
    const float*         xyz    = (const float*)d_in[1];
    const unsigned char* validb = (const unsigned char*)d_in[2];
    const float*         ln_n_w = (const float*)d_in[3];
    const float*         ln_n_b = (const float*)d_in[4];
    const float*         w1     = (const float*)d_in[5];
    const float*         b1     = (const float*)d_in[6];
    const float*         w2     = (const float*)d_in[7];
    const float*         b2     = (const float*)d_in[8];
    const float*         ln_u_w = (const float*)d_in[9];
    const float*         ln_u_b = (const float*)d_in[10];
    const float*         u1     = (const float*)d_in[11];
    const float*         bu1    = (const float*)d_in[12];
    const float*         u2     = (const float*)d_in[13];
    const float*         bu2    = (const float*)d_in[14];
    float* out = (float*)d_out;

    float *pHin, *pP, *pQ, *pG, *pH2, *pHu, *pT1;
    float *pW1at, *pW1bt, *pW2t, *pU1t, *pU2t;
    cudaGetSymbolAddress((void**)&pHin, g_hin);
    cudaGetSymbolAddress((void**)&pP,   g_P);
    cudaGetSymbolAddress((void**)&pQ,   g_Q);
    cudaGetSymbolAddress((void**)&pG,   g_G);
    cudaGetSymbolAddress((void**)&pH2,  g_h2);
    cudaGetSymbolAddress((void**)&pHu,  g_hu);
    cudaGetSymbolAddress((void**)&pT1,  g_T1);
    cudaGetSymbolAddress((void**)&pW1at, g_w1at);
    cudaGetSymbolAddress((void**)&pW1bt, g_w1bt);
    cudaGetSymbolAddress((void**)&pW2t,  g_w2t);
    cudaGetSymbolAddress((void**)&pU1t,  g_u1t);
    cudaGetSymbolAddress((void**)&pU2t,  g_u2t);

    cudaFuncSetAttribute(mma_gemm<0>, cudaFuncAttributeMaxDynamicSharedMemorySize, SMEM_DYN);
    cudaFuncSetAttribute(mma_gemm<1>, cudaFuncAttributeMaxDynamicSharedMemorySize, SMEM_DYN);
    cudaFuncSetAttribute(mma_gemm<2>, cudaFuncAttributeMaxDynamicSharedMemorySize, SMEM_DYN);
    cudaFuncSetAttribute(mma_gemm<3>, cudaFuncAttributeMaxDynamicSharedMemorySize, SMEM_DYN);

    // 0. normalize valid
    detect_vmode_kernel<<<1, 32>>>(validb);
    conv_valid_kernel<<<(NC + 255) / 256, 256>>>(validb);

    // 0b. transpose weights to [N,K]
    transpose_kernel<<<(Hdim*H2 + 255)/256, 256>>>(w1,                    pW1at, Hdim, H2);
    transpose_kernel<<<(Hdim*H2 + 255)/256, 256>>>(w1 + (size_t)Hdim*H2,  pW1bt, Hdim, H2);
    transpose_kernel<<<(H2*Hdim + 255)/256, 256>>>(w2,                    pW2t,  H2, Hdim);
    transpose_kernel<<<(Hdim*HU + 255)/256, 256>>>(u1,                    pU1t,  Hdim, HU);
    transpose_kernel<<<(HU*Hdim + 255)/256, 256>>>(u2,                    pU2t,  HU, Hdim);

    // 1. h_in = LN(h), zero agg
    ln_kernel<<<NC, 256>>>(h, ln_n_w, ln_n_b, pHin, 1);

    // 2. P = h_in @ W1a, Q = h_in @ W1b   (M=NC, K=256, N=512)
    mma_gemm<0><<<dim3(H2/128, NC/128), 256, SMEM_DYN>>>(pHin, Hdim, pW1at,
                                                         nullptr, pP, H2, nullptr,
                                                         Hdim, 0, 0, 0);
    mma_gemm<0><<<dim3(H2/128, NC/128), 256, SMEM_DYN>>>(pHin, Hdim, pW1bt,
                                                         nullptr, pQ, H2, nullptr,
                                                         Hdim, 0, 0, 0);

    // 3. edge messages
    const int offs[4] = {1, 2, 4, 8};
    for (int oi = 0; oi < 4; oi++) {
        int off = offs[oi];
        int Ce = Cdim - off;
        int Me = Ndim * Ce;   // multiple of 128
        for (int dir = 0; dir < 2; dir++) {
            edge_pre_kernel<<<Me, 128>>>(xyz, w1, b1, off, dir, Ce);
            mma_gemm<2><<<dim3(Hdim/128, Me/128), 256, SMEM_DYN>>>(pG, H2, pW2t,
                                                                   b2, nullptr, Hdim, nullptr,
                                                                   H2, off, dir, Ce);
        }
    }

    // 4. h2 = h + agg * valid
    h2_kernel<<<NC, 256>>>(h);

    // 5. update MLP
    ln_kernel<<<NC, 256>>>(pH2, ln_u_w, ln_u_b, pHu, 0);
    mma_gemm<1><<<dim3(HU/128, NC/128), 256, SMEM_DYN>>>(pHu, Hdim, pU1t,
                                                         bu1, pT1, HU, nullptr,
                                                         Hdim, 0, 0, 0);
    mma_gemm<3><<<dim3(Hdim/128, NC/128), 256, SMEM_DYN>>>(pT1, HU, pU2t,
                                                           bu2, out, Hdim, pH2,
                                                           HU, 0, 0, 0);
    (void)in_sizes; (void)n_in; (void)out_size;
}

// round 5
// speedup vs baseline: 2.2803x; 1.0215x over previous
#include <cuda_runtime.h>
#include <math.h>
#include <stdint.h>

#define Ndim 256
#define Cdim 512
#define Hdim 256
#define NC   (Ndim*Cdim)   // 131072
#define H2   512           // 2*H
#define HU   1024          // 4*H

#if defined(__CUDA_ARCH_FEAT_SM103_ALL) || defined(__CUDA_ARCH_FEAT_SM100_ALL) || \
    (defined(__CUDA_ARCH_SPECIFIC__) && (__CUDA_ARCH_SPECIFIC__ >= 1000))
#define HAS_TC 1
#else
#define HAS_TC 0
#endif

// ---------------- scratch (static device globals; no allocs) ----------------
__device__ float g_hin[(size_t)NC*Hdim];
__device__ float g_P  [(size_t)NC*H2];
__device__ float g_Q  [(size_t)NC*H2];
__device__ float g_G  [(size_t)NC*H2];      // fwd edge activations
__device__ float g_agg[(size_t)NC*Hdim];
__device__ float g_h2 [(size_t)NC*Hdim];
__device__ float g_hu [(size_t)NC*Hdim];
__device__ float g_T1 [(size_t)NC*HU];      // rev edge activations / update hidden
__device__ float g_w1at[(size_t)H2*Hdim];
__device__ float g_w1bt[(size_t)H2*Hdim];
__device__ float g_w2t [(size_t)Hdim*H2];
__device__ float g_u1t [(size_t)HU*Hdim];
__device__ float g_u2t [(size_t)Hdim*HU];
__device__ unsigned char g_valid[NC];
__device__ int g_vmode;

__device__ __forceinline__ float gelu_exact(float x) {
    return 0.5f * x * (1.0f + erff(x * 0.70710678118654752f));
}
__device__ __forceinline__ uint32_t f2tf(float f) {
    uint32_t r;
    asm("cvt.rna.tf32.f32 %0, %1;" : "=r"(r) : "f"(f));
    return r;
}
__device__ __forceinline__ float f2tf_f(float f) {
    return __uint_as_float(f2tf(f));
}

// ---------------- valid dtype detection + normalization ---------------------
__global__ void detect_vmode_kernel(const unsigned char* __restrict__ v) {
    if (threadIdx.x == 0) {
        int nz1 = 0, nz23 = 0;
        for (int i = 0; i < 4096; i += 4) {
            if (v[i+1]) nz1 = 1;
            if (v[i+2] | v[i+3]) nz23 = 1;
        }
        g_vmode = nz1 ? 0 : (nz23 ? 2 : 1);  // 0=uint8, 1=int32, 2=float32
    }
}

__global__ void conv_valid_kernel(const unsigned char* __restrict__ v) {
    int i = blockIdx.x * 256 + threadIdx.x;
    if (i >= NC) return;
    int mode = g_vmode;
    unsigned char r;
    if (mode == 0)      r = v[i] != 0;
    else if (mode == 1) r = ((const int*)v)[i] != 0;
    else                r = ((const unsigned int*)v)[i] != 0u;
    g_valid[i] = r;
}

// ---------------- weight transpose (tf32-rounded): Bt[n*K+k] = B[k*N+n] -----
__global__ void transpose_kernel(const float* __restrict__ B,
                                 float* __restrict__ Bt, int K, int N) {
    int idx = blockIdx.x * 256 + threadIdx.x;
    if (idx >= K * N) return;
    int k = idx / N, n = idx - k * N;
    Bt[(size_t)n * K + k] = f2tf_f(B[idx]);
}

// ---------------- LayerNorm (output tf32-rounded; feeds MMA only) ----------
__global__ void ln_kernel(const float* __restrict__ x,
                          const float* __restrict__ w,
                          const float* __restrict__ b,
                          float* __restrict__ y,
                          int zero_agg) {
    int row = blockIdx.x;
    int t = threadIdx.x;
    float v = x[(size_t)row*Hdim + t];

    __shared__ float red[8];
    __shared__ float stat[2];

    float s = v;
    #pragma unroll
    for (int o = 16; o > 0; o >>= 1) s += __shfl_xor_sync(0xffffffffu, s, o);
    if ((t & 31) == 0) red[t >> 5] = s;
    __syncthreads();
    if (t == 0) {
        float m = 0.f;
        #pragma unroll
        for (int i = 0; i < 8; i++) m += red[i];
        stat[0] = m * (1.0f / Hdim);
    }
    __syncthreads();
    float mu = stat[0];
    float d = v - mu;
    s = d * d;
    #pragma unroll
    for (int o = 16; o > 0; o >>= 1) s += __shfl_xor_sync(0xffffffffu, s, o);
    if ((t & 31) == 0) red[t >> 5] = s;
    __syncthreads();
    if (t == 0) {
        float q = 0.f;
        #pragma unroll
        for (int i = 0; i < 8; i++) q += red[i];
        stat[1] = rsqrtf(q * (1.0f / Hdim) + 1e-5f);
    }
    __syncthreads();
    y[(size_t)row*Hdim + t] = f2tf_f(d * stat[1] * w[t] + b[t]);
    if (zero_agg) g_agg[(size_t)row*Hdim + t] = 0.f;
}

// ---------------- fused fwd+rev edge pre-activation + GELU ------------------
// fwd: gelu(P[i] + Q[j] + [+unit,dist]@W1e + b1) -> g_G[m]
// rev: gelu(P[j] + Q[i] + [-unit,dist]@W1e + b1) -> g_T1[m]
__global__ void edge_pre2_kernel(const float* __restrict__ xyz,
                                 const float* __restrict__ w1,
                                 const float* __restrict__ b1,
                                 int off, int Ce) {
    int m = blockIdx.x;
    int nidx = m / Ce;
    int c = m - nidx * Ce;
    int i = nidx * Cdim + c;
    int j = i + off;

    __shared__ float ef[4];
    if (threadIdx.x == 0) {
        float dx = xyz[3*j+0] - xyz[3*i+0];
        float dy = xyz[3*j+1] - xyz[3*i+1];
        float dz = xyz[3*j+2] - xyz[3*i+2];
        float d = fmaxf(sqrtf(dx*dx + dy*dy + dz*dz), 1e-6f);
        float inv = 1.0f / d;
        ef[0] = dx * inv; ef[1] = dy * inv; ef[2] = dz * inv; ef[3] = d;
    }
    __syncthreads();

    int f = threadIdx.x * 4;
    float4 pi  = *(const float4*)(g_P + (size_t)i*H2 + f);
    float4 qi  = *(const float4*)(g_Q + (size_t)i*H2 + f);
    float4 pj  = *(const float4*)(g_P + (size_t)j*H2 + f);
    float4 qj  = *(const float4*)(g_Q + (size_t)j*H2 + f);
    float4 bb = *(const float4*)(b1 + f);
    float4 w0 = *(const float4*)(w1 + (size_t)(2*Hdim + 0)*H2 + f);
    float4 w1r= *(const float4*)(w1 + (size_t)(2*Hdim + 1)*H2 + f);
    float4 w2r= *(const float4*)(w1 + (size_t)(2*Hdim + 2)*H2 + f);
    float4 w3r= *(const float4*)(w1 + (size_t)(2*Hdim + 3)*H2 + f);
    float e0 = ef[0], e1 = ef[1], e2 = ef[2], e3 = ef[3];

    float4 eu, ed;
    eu.x = e0*w0.x + e1*w1r.x + e2*w2r.x;  ed.x = e3*w3r.x + bb.x;
    eu.y = e0*w0.y + e1*w1r.y + e2*w2r.y;  ed.y = e3*w3r.y + bb.y;
    eu.z = e0*w0.z + e1*w1r.z + e2*w2r.z;  ed.z = e3*w3r.z + bb.z;
    eu.w = e0*w0.w + e1*w1r.w + e2*w2r.w;  ed.w = e3*w3r.w + bb.w;

    float4 rf, rr;
    rf.x = f2tf_f(gelu_exact(pi.x + qj.x + eu.x + ed.x));
    rf.y = f2tf_f(gelu_exact(pi.y + qj.y + eu.y + ed.y));
    rf.z = f2tf_f(gelu_exact(pi.z + qj.z + eu.z + ed.z));
    rf.w = f2tf_f(gelu_exact(pi.w + qj.w + eu.w + ed.w));
    rr.x = f2tf_f(gelu_exact(pj.x + qi.x - eu.x + ed.x));
    rr.y = f2tf_f(gelu_exact(pj.y + qi.y - eu.y + ed.y));
    rr.z = f2tf_f(gelu_exact(pj.z + qi.z - eu.z + ed.z));
    rr.w = f2tf_f(gelu_exact(pj.w + qi.w - eu.w + ed.w));
    *(float4*)(g_G  + (size_t)m*H2 + f) = rf;
    *(float4*)(g_T1 + (size_t)m*H2 + f) = rr;
}

// ---------------- h2 = h + agg*valid -----------------------------------------
__global__ void h2_kernel(const float* __restrict__ h) {
    int row = blockIdx.x;
    int t = threadIdx.x;
    size_t idx = (size_t)row*Hdim + t;
    float vf = g_valid[row] ? 1.0f : 0.0f;
    g_h2[idx] = h[idx] + g_agg[idx] * vf;
}

// ============================================================================
// tcgen05 tf32 GEMM: C[M,N] = A[M,K] @ Bt[N,K]^T. Inputs pre-rounded to tf32.
// Tile 128x256, BK=32 (4 MMA dispatches of K=8, N=256), double-buffered.
// ============================================================================
__device__ __forceinline__ uint32_t smem_u32(const void* p) {
    uint32_t a;
    asm("{ .reg .u64 t; cvta.to.shared.u64 t, %1; cvt.u32.u64 %0, t; }" : "=r"(a) : "l"(p));
    return a;
}
__device__ __forceinline__ void mbar_wait(uint32_t mbar, uint32_t parity) {
    asm volatile(
        "{\n\t.reg .pred P1;\n\t"
        "W_%=:\n\t"
        "mbarrier.try_wait.parity.acquire.cta.shared::cta.b64 P1, [%0], %1, 0x989680;\n\t"
        "@P1 bra.uni D_%=;\n\t"
        "bra.uni W_%=;\n\t"
        "D_%=:\n\t}"
        :: "r"(mbar), "r"(parity) : "memory");
}

#if HAS_TC
__device__ __forceinline__ void mma_tf32_ss(uint32_t d_tmem, uint64_t a_desc,
                                            uint64_t b_desc, uint32_t idesc, bool acc) {
    uint32_t en = acc ? 1u : 0u;
    asm volatile(
        "{\n\t.reg .pred p;\n\t"
        "setp.ne.u32 p, %5, 0;\n\t"
        "tcgen05.mma.cta_group::1.kind::tf32 [%0], %1, %2, %3, {%4, %4, %4, %4}, p;\n\t"
        "}"
        :: "r"(d_tmem), "l"(a_desc), "l"(b_desc), "r"(idesc), "r"(0u), "r"(en)
        : "memory");
}
#define LDTM_X32(r, addr) \
    asm volatile( \
        "tcgen05.ld.sync.aligned.32x32b.x32.b32 " \
        "{%0, %1, %2, %3, %4, %5, %6, %7, " \
        " %8, %9, %10, %11, %12, %13, %14, %15, " \
        " %16, %17, %18, %19, %20, %21, %22, %23, " \
        " %24, %25, %26, %27, %28, %29, %30, %31}, [%32];" \
        : "=r"((r)[0]),  "=r"((r)[1]),  "=r"((r)[2]),  "=r"((r)[3]), \
          "=r"((r)[4]),  "=r"((r)[5]),  "=r"((r)[6]),  "=r"((r)[7]), \
          "=r"((r)[8]),  "=r"((r)[9]),  "=r"((r)[10]), "=r"((r)[11]), \
          "=r"((r)[12]), "=r"((r)[13]), "=r"((r)[14]), "=r"((r)[15]), \
          "=r"((r)[16]), "=r"((r)[17]), "=r"((r)[18]), "=r"((r)[19]), \
          "=r"((r)[20]), "=r"((r)[21]), "=r"((r)[22]), "=r"((r)[23]), \
          "=r"((r)[24]), "=r"((r)[25]), "=r"((r)[26]), "=r"((r)[27]), \
          "=r"((r)[28]), "=r"((r)[29]), "=r"((r)[30]), "=r"((r)[31]) \
        : "r"(addr))
#endif

static constexpr unsigned long long DESC_BASE =
    (2ull << 61) | (1ull << 46) | (64ull << 32) | (1ull << 16);  // SW128 K-major
// idesc: cfmt=F32(1)<<4, a=TF32(2)<<7, b=TF32(2)<<10, N=256 -> 32<<17, M=128 -> 8<<24
#define MMA_IDESC ((1u<<4) | (2u<<7) | (2u<<10) | (32u<<17) | (8u<<24))
// smem: pad(1024) + A0(16K) A1(16K) B0(32K) B1(32K) + ctrl(64)
#define SMEM_DYN  (1024 + 98304 + 64)

// EPI 0: plain store; 1: round(gelu(acc+bias)); 2: agg[target] += (acc+bias) if valid;
// EPI 3: out = (aux + acc + bias) * valid
template<int EPI>
__global__ void __launch_bounds__(256)
mma_gemm(const float* __restrict__ A, int lda,
         const float* __restrict__ Bt,   // [N, K] row-major, tf32-rounded
         const float* __restrict__ bias,
         float* __restrict__ Cout, int ldc,
         const float* __restrict__ aux,
         int K, int off, int dir, int Ce) {
    extern __shared__ char dyn[];
    int tid = threadIdx.x;
    int m0 = blockIdx.y * 128;
    int n0 = blockIdx.x * 256;

#if HAS_TC
    uint32_t u0 = smem_u32(dyn);
    uint32_t pad = (1024u - (u0 & 1023u)) & 1023u;
    char* base = dyn + pad;
    uint32_t ub = u0 + pad;

    uint32_t ctrl  = ub + 98304;
    uint32_t mbar0 = ctrl + 8;

    int wid = tid >> 5;
    int lane = tid & 31;

    if (tid == 0) {
        asm volatile("mbarrier.init.shared.b64 [%0], 1;" :: "r"(mbar0)     : "memory");
        asm volatile("mbarrier.init.shared.b64 [%0], 1;" :: "r"(mbar0 + 8) : "memory");
    }
    if (wid == 0) {
        asm volatile("tcgen05.alloc.cta_group::1.sync.aligned.shared::cta.b32 [%0], %1;"
                     :: "r"(ctrl), "r"(256u) : "memory");
        asm volatile("tcgen05.relinquish_alloc_permit.cta_group::1.sync.aligned;");
    }
    __syncthreads();
    uint32_t tmem;
    asm volatile("ld.shared.b32 %0, [%1];" : "=r"(tmem) : "r"(ctrl));

    const int NCH = K >> 5;
    for (int c = 0; c < NCH; c++) {
        int buf = c & 1;
        if (c >= 2) mbar_wait(mbar0 + 8u * buf, (uint32_t)(((c - 2) >> 1) & 1));
        char* sA = base + buf * 16384;
        char* sB = base + 32768 + buf * 32768;
        int k0 = c << 5;

        // A tile: 128 rows x 32 cols (4096 elems = 4 float4/thread)
        #pragma unroll
        for (int i = 0; i < 4; i++) {
            int idx = tid + i * 256;
            int r = idx >> 3, f4 = idx & 7;
            uint4 av = *(const uint4*)(A + (size_t)(m0 + r) * lda + k0 + f4 * 4);
            uint32_t so = (uint32_t)(r * 128 + f4 * 16);
            so ^= (so >> 3) & 0x70u;
            *(uint4*)(sA + so) = av;
        }
        // B tile: 256 rows x 32 cols (8192 elems = 8 float4/thread)
        #pragma unroll
        for (int i = 0; i < 8; i++) {
            int idx = tid + i * 256;
            int r = idx >> 3, f4 = idx & 7;
            uint4 bv = *(const uint4*)(Bt + (size_t)(n0 + r) * K + k0 + f4 * 4);
            uint32_t so = (uint32_t)(r * 128 + f4 * 16);
            so ^= (so >> 3) & 0x70u;
            *(uint4*)(sB + so) = bv;
        }
        asm volatile("fence.proxy.async.shared::cta;" ::: "memory");
        __syncthreads();

        if (tid == 0) {
            uint32_t aaddr = ub + (uint32_t)(buf * 16384);
            uint32_t baddr = ub + (uint32_t)(32768 + buf * 32768);
            uint64_t adesc = DESC_BASE | (uint64_t)((aaddr >> 4) & 0x3FFFu);
            uint64_t bdesc = DESC_BASE | (uint64_t)((baddr >> 4) & 0x3FFFu);
            #pragma unroll
            for (int s = 0; s < 4; s++) {
                mma_tf32_ss(tmem, adesc + 2u * s, bdesc + 2u * s, MMA_IDESC,
                            !(c == 0 && s == 0));
            }
            asm volatile(
                "tcgen05.commit.cta_group::1.mbarrier::arrive::one.shared::cluster.b64 [%0];"
                :: "r"(mbar0 + 8u * buf) : "memory");
        }
    }
    mbar_wait(mbar0 + 8u * ((NCH - 2) & 1), (uint32_t)(((NCH - 2) >> 1) & 1));
    mbar_wait(mbar0 + 8u * ((NCH - 1) & 1), (uint32_t)(((NCH - 1) >> 1) & 1));
    asm volatile("tcgen05.fence::after_thread_sync;" ::: "memory");

    // ---------------- epilogue: warps 0-3 read TMEM D (256 cols) ----------------
    if (wid < 4) {
        int trow = wid * 32 + lane;
        int m = m0 + trow;
        int tgt = 0; bool do_write = true;
        if (EPI == 2) {
            int nidx = m / Ce;
            int cc2 = m - nidx * Ce;
            int ii = nidx * Cdim + cc2;
            int jj = ii + off;
            do_write = (g_valid[ii] && g_valid[jj]);
            tgt = dir ? jj : ii;
        }
        float vf = 1.0f;
        if (EPI == 3) vf = g_valid[m] ? 1.0f : 0.0f;

        #pragma unroll
        for (int cc = 0; cc < 256; cc += 32) {
            uint32_t r[32];
            LDTM_X32(r, tmem + (uint32_t)cc);
            asm volatile("tcgen05.wait::ld.sync.aligned;" ::: "memory");
            int col0 = n0 + cc;
            if (EPI == 0) {
                #pragma unroll
                for (int j = 0; j < 32; j += 4) {
                    float4 o = {__uint_as_float(r[j]), __uint_as_float(r[j+1]),
                                __uint_as_float(r[j+2]), __uint_as_float(r[j+3])};
                    *(float4*)(Cout + (size_t)m * ldc + col0 + j) = o;
                }
            } else if (EPI == 1) {
                #pragma unroll
                for (int j = 0; j < 32; j += 4) {
                    float4 o;
                    o.x = f2tf_f(gelu_exact(__uint_as_float(r[j])   + __ldg(&bias[col0+j])));
                    o.y = f2tf_f(gelu_exact(__uint_as_float(r[j+1]) + __ldg(&bias[col0+j+1])));
                    o.z = f2tf_f(gelu_exact(__uint_as_float(r[j+2]) + __ldg(&bias[col0+j+2])));
                    o.w = f2tf_f(gelu_exact(__uint_as_float(r[j+3]) + __ldg(&bias[col0+j+3])));
                    *(float4*)(Cout + (size_t)m * ldc + col0 + j) = o;
                }
            } else if (EPI == 2) {
                if (do_write) {
                    float* d = g_agg + (size_t)tgt * Hdim + col0;
                    #pragma unroll
                    for (int j = 0; j < 32; j += 4) {
                        float4 old = *(float4*)(d + j);
                        old.x += __uint_as_float(r[j])   + __ldg(&bias[col0+j]);
                        old.y += __uint_as_float(r[j+1]) + __ldg(&bias[col0+j+1]);
                        old.z += __uint_as_float(r[j+2]) + __ldg(&bias[col0+j+2]);
                        old.w += __uint_as_float(r[j+3]) + __ldg(&bias[col0+j+3]);
                        *(float4*)(d + j) = old;
                    }
                }
            } else { // EPI == 3
                const float* a2 = aux + (size_t)m * Hdim + col0;
                #pragma unroll
                for (int j = 0; j < 32; j += 4) {
                    float4 av = *(const float4*)(a2 + j);
                    float4 o;
                    o.x = (av.x + __uint_as_float(r[j])   + __ldg(&bias[col0+j]))   * vf;
                    o.y = (av.y + __uint_as_float(r[j+1]) + __ldg(&bias[col0+j+1])) * vf;
                    o.z = (av.z + __uint_as_float(r[j+2]) + __ldg(&bias[col0+j+2])) * vf;
                    o.w = (av.w + __uint_as_float(r[j+3]) + __ldg(&bias[col0+j+3])) * vf;
                    *(float4*)(Cout + (size_t)m * ldc + col0 + j) = o;
                }
            }
        }
    }
    __syncthreads();
    if (wid == 0) {
        asm volatile("tcgen05.dealloc.cta_group::1.sync.aligned.b32 %0, %1;"
                     :: "r"(tmem), "r"(256u));
    }

#else  // ---------------- SIMT fallback (compute_103 PTX pass) ----------------
    float* As = (float*)dyn;            // [16][128]
    float* Bs = (float*)(dyn + 8192);   // [16][128]

    int tr = tid >> 4, tc = tid & 15;
    int lrow = tid >> 1;
    int lk   = (tid & 1) * 8;

    for (int half = 0; half < 2; half++) {
        int n0h = n0 + half * 128;
        float acc[8][8] = {};
        for (int k0 = 0; k0 < K; k0 += 16) {
            #pragma unroll
            for (int e = 0; e < 8; e += 4) {
                float4 av = *(const float4*)(A + (size_t)(m0 + lrow) * lda + k0 + lk + e);
                As[(lk+e+0)*128 + lrow] = av.x;
                As[(lk+e+1)*128 + lrow] = av.y;
                As[(lk+e+2)*128 + lrow] = av.z;
                As[(lk+e+3)*128 + lrow] = av.w;
                float4 bv = *(const float4*)(Bt + (size_t)(n0h + lrow) * K + k0 + lk + e);
                Bs[(lk+e+0)*128 + lrow] = bv.x;
                Bs[(lk+e+1)*128 + lrow] = bv.y;
                Bs[(lk+e+2)*128 + lrow] = bv.z;
                Bs[(lk+e+3)*128 + lrow] = bv.w;
            }
            __syncthreads();
            #pragma unroll
            for (int k = 0; k < 16; k++) {
                float a[8], b[8];
                #pragma unroll
                for (int i = 0; i < 8; i++) a[i] = As[k*128 + tr*8 + i];
                #pragma unroll
                for (int j = 0; j < 8; j++) b[j] = Bs[k*128 + tc*8 + j];
                #pragma unroll
                for (int i = 0; i < 8; i++)
                    #pragma unroll
                    for (int j = 0; j < 8; j++)
                        acc[i][j] += a[i] * b[j];
            }
            __syncthreads();
        }

        int col0 = n0h + tc * 8;
        #pragma unroll
        for (int i = 0; i < 8; i++) {
            int m = m0 + tr * 8 + i;
            if (EPI == 0) {
                #pragma unroll
                for (int j = 0; j < 8; j++)
                    Cout[(size_t)m * ldc + col0 + j] = acc[i][j];
            } else if (EPI == 1) {
                #pragma unroll
                for (int j = 0; j < 8; j++)
                    Cout[(size_t)m * ldc + col0 + j] =
                        gelu_exact(acc[i][j] + bias[col0 + j]);
            } else if (EPI == 2) {
                int nidx = m / Ce;
                int cc2 = m - nidx * Ce;
                int ii = nidx * Cdim + cc2;
                int jj = ii + off;
                if (g_valid[ii] && g_valid[jj]) {
                    int tgt = dir ? jj : ii;
                    float* d = g_agg + (size_t)tgt * Hdim + col0;
                    #pragma unroll
                    for (int j = 0; j < 8; j++)
                        d[j] += acc[i][j] + bias[col0 + j];
                }
            } else {
                float vf = g_valid[m] ? 1.0f : 0.0f;
                const float* a2 = aux + (size_t)m * Hdim + col0;
                #pragma unroll
                for (int j = 0; j < 8; j++)
                    Cout[(size_t)m * ldc + col0 + j] =
                        (a2[j] + acc[i][j] + bias[col0 + j]) * vf;
            }
        }
        __syncthreads();
    }
#endif
}

// ---------------- launch -----------------------------------------------------
extern "C" void kernel_launch(void* const* d_in, const int* in_sizes, int n_in,
                              void* d_out, int out_size) {
    const float*         h      = (const float*)d_in[0];
    const float*         xyz    = (const float*)d_in[1];
    const unsigned char* validb = (const unsigned char*)d_in[2];
    const float*         ln_n_w = (const float*)d_in[3];
    const float*         ln_n_b = (const float*)d_in[4];
    const float*         w1     = (const float*)d_in[5];
    const float*         b1     = (const float*)d_in[6];
    const float*         w2     = (const float*)d_in[7];
    const float*         b2     = (const float*)d_in[8];
    const float*         ln_u_w = (const float*)d_in[9];
    const float*         ln_u_b = (const float*)d_in[10];
    const float*         u1     = (const float*)d_in[11];
    const float*         bu1    = (const float*)d_in[12];
    const float*         u2     = (const float*)d_in[13];
    const float*         bu2    = (const float*)d_in[14];
    float* out = (float*)d_out;

    float *pHin, *pP, *pQ, *pG, *pH2, *pHu, *pT1;
    float *pW1at, *pW1bt, *pW2t, *pU1t, *pU2t;
    cudaGetSymbolAddress((void**)&pHin, g_hin);
    cudaGetSymbolAddress((void**)&pP,   g_P);
    cudaGetSymbolAddress((void**)&pQ,   g_Q);
    cudaGetSymbolAddress((void**)&pG,   g_G);
    cudaGetSymbolAddress((void**)&pH2,  g_h2);
    cudaGetSymbolAddress((void**)&pHu,  g_hu);
    cudaGetSymbolAddress((void**)&pT1,  g_T1);
    cudaGetSymbolAddress((void**)&pW1at, g_w1at);
    cudaGetSymbolAddress((void**)&pW1bt, g_w1bt);
    cudaGetSymbolAddress((void**)&pW2t,  g_w2t);
    cudaGetSymbolAddress((void**)&pU1t,  g_u1t);
    cudaGetSymbolAddress((void**)&pU2t,  g_u2t);

    cudaFuncSetAttribute(mma_gemm<0>, cudaFuncAttributeMaxDynamicSharedMemorySize, SMEM_DYN);
    cudaFuncSetAttribute(mma_gemm<1>, cudaFuncAttributeMaxDynamicSharedMemorySize, SMEM_DYN);
    cudaFuncSetAttribute(mma_gemm<2>, cudaFuncAttributeMaxDynamicSharedMemorySize, SMEM_DYN);
    cudaFuncSetAttribute(mma_gemm<3>, cudaFuncAttributeMaxDynamicSharedMemorySize, SMEM_DYN);

    // 0. normalize valid
    detect_vmode_kernel<<<1, 32>>>(validb);
    conv_valid_kernel<<<(NC + 255) / 256, 256>>>(validb);

    // 0b. transpose weights to [N,K] (tf32-rounded)
    transpose_kernel<<<(Hdim*H2 + 255)/256, 256>>>(w1,                    pW1at, Hdim, H2);
    transpose_kernel<<<(Hdim*H2 + 255)/256, 256>>>(w1 + (size_t)Hdim*H2,  pW1bt, Hdim, H2);
    transpose_kernel<<<(H2*Hdim + 255)/256, 256>>>(w2,                    pW2t,  H2, Hdim);
    transpose_kernel<<<(Hdim*HU + 255)/256, 256>>>(u1,                    pU1t,  Hdim, HU);
    transpose_kernel<<<(HU*Hdim + 255)/256, 256>>>(u2,                    pU2t,  HU, Hdim);

    // 1. h_in = LN(h) (tf32-rounded), zero agg
    ln_kernel<<<NC, 256>>>(h, ln_n_w, ln_n_b, pHin, 1);

    // 2. P = h_in @ W1a, Q = h_in @ W1b   (M=NC, K=256, N=512)
    mma_gemm<0><<<dim3(H2/256, NC/128), 256, SMEM_DYN>>>(pHin, Hdim, pW1at,
                                                         nullptr, pP, H2, nullptr,
                                                         Hdim, 0, 0, 0);
    mma_gemm<0><<<dim3(H2/256, NC/128), 256, SMEM_DYN>>>(pHin, Hdim, pW1bt,
                                                         nullptr, pQ, H2, nullptr,
                                                         Hdim, 0, 0, 0);

    // 3. edge messages: fused fwd+rev pre, then two GEMMs with agg-RMW epilogue
    const int offs[4] = {1, 2, 4, 8};
    for (int oi = 0; oi < 4; oi++) {
        int off = offs[oi];
        int Ce = Cdim - off;
        int Me = Ndim * Ce;   // multiple of 128
        edge_pre2_kernel<<<Me, 128>>>(xyz, w1, b1, off, Ce);
        mma_gemm<2><<<dim3(Hdim/256, Me/128), 256, SMEM_DYN>>>(pG, H2, pW2t,
                                                               b2, nullptr, Hdim, nullptr,
                                                               H2, off, 0, Ce);
        mma_gemm<2><<<dim3(Hdim/256, Me/128), 256, SMEM_DYN>>>(pT1, H2, pW2t,
                                                               b2, nullptr, Hdim, nullptr,
                                                               H2, off, 1, Ce);
    }

    // 4. h2 = h + agg * valid
    h2_kernel<<<NC, 256>>>(h);

    // 5. update MLP
    ln_kernel<<<NC, 256>>>(pH2, ln_u_w, ln_u_b, pHu, 0);
    mma_gemm<1><<<dim3(HU/256, NC/128), 256, SMEM_DYN>>>(pHu, Hdim, pU1t,
                                                         bu1, pT1, HU, nullptr,
                                                         Hdim, 0, 0, 0);
    mma_gemm<3><<<dim3(Hdim/256, NC/128), 256, SMEM_DYN>>>(pT1, HU, pU2t,
                                                           bu2, out, Hdim, pH2,
                                                           HU, 0, 0, 0);
    (void)in_sizes; (void)n_in; (void)out_size;
}

// round 6
// speedup vs baseline: 2.6648x; 1.1686x over previous
#include <cuda_runtime.h>
#include <cuda_fp16.h>
#include <math.h>
#include <stdint.h>

#define Ndim 256
#define Cdim 512
#define Hdim 256
#define NC   (Ndim*Cdim)   // 131072
#define H2   512           // 2*H
#define HU   1024          // 4*H

#if defined(__CUDA_ARCH_FEAT_SM103_ALL) || defined(__CUDA_ARCH_FEAT_SM100_ALL) || \
    (defined(__CUDA_ARCH_SPECIFIC__) && (__CUDA_ARCH_SPECIFIC__ >= 1000))
#define HAS_TC 1
#else
#define HAS_TC 0
#endif

// ---------------- scratch (static device globals; no allocs) ----------------
__device__ __half g_hin[(size_t)NC*Hdim];
__device__ __half g_P  [(size_t)NC*H2];
__device__ __half g_Q  [(size_t)NC*H2];
__device__ __half g_G  [(size_t)NC*H2];     // fwd edge activations
__device__ float  g_agg[(size_t)NC*Hdim];
__device__ float  g_h2 [(size_t)NC*Hdim];
__device__ __half g_hu [(size_t)NC*Hdim];
__device__ __half g_T1 [(size_t)NC*HU];     // rev edge activations / update hidden
__device__ __half g_w1at[(size_t)H2*Hdim];
__device__ __half g_w1bt[(size_t)H2*Hdim];
__device__ __half g_w2t [(size_t)Hdim*H2];
__device__ __half g_u1t [(size_t)HU*Hdim];
__device__ __half g_u2t [(size_t)Hdim*HU];
__device__ unsigned char g_valid[NC];
__device__ int g_vmode;

__device__ __forceinline__ float gelu_exact(float x) {
    return 0.5f * x * (1.0f + erff(x * 0.70710678118654752f));
}
__device__ __forceinline__ void ld4h(const __half* p, float* f) {
    uint2 u = *(const uint2*)p;
    float2 fa = __half22float2(*(__half2*)&u.x);
    float2 fb = __half22float2(*(__half2*)&u.y);
    f[0] = fa.x; f[1] = fa.y; f[2] = fb.x; f[3] = fb.y;
}
__device__ __forceinline__ void st4h(__half* p, const float* f) {
    uint2 u;
    *(__half2*)&u.x = __float22half2_rn(make_float2(f[0], f[1]));
    *(__half2*)&u.y = __float22half2_rn(make_float2(f[2], f[3]));
    *(uint2*)p = u;
}

// ---------------- valid dtype detection + normalization ---------------------
__global__ void detect_vmode_kernel(const unsigned char* __restrict__ v) {
    if (threadIdx.x == 0) {
        int nz1 = 0, nz23 = 0;
        for (int i = 0; i < 4096; i += 4) {
            if (v[i+1]) nz1 = 1;
            if (v[i+2] | v[i+3]) nz23 = 1;
        }
        g_vmode = nz1 ? 0 : (nz23 ? 2 : 1);  // 0=uint8, 1=int32, 2=float32
    }
}

__global__ void conv_valid_kernel(const unsigned char* __restrict__ v) {
    int i = blockIdx.x * 256 + threadIdx.x;
    if (i >= NC) return;
    int mode = g_vmode;
    unsigned char r;
    if (mode == 0)      r = v[i] != 0;
    else if (mode == 1) r = ((const int*)v)[i] != 0;
    else                r = ((const unsigned int*)v)[i] != 0u;
    g_valid[i] = r;
}

// ---------------- all weight transposes in ONE launch (fp16 output) ---------
// ranges: w1at 131072 | w1bt 131072 | w2t 131072 | u1t 262144 | u2t 262144
__global__ void transpose_all_kernel(const float* __restrict__ w1,
                                     const float* __restrict__ w2,
                                     const float* __restrict__ u1,
                                     const float* __restrict__ u2) {
    int idx = blockIdx.x * 256 + threadIdx.x;
    if (idx < 131072) {
        int n = idx >> 8, k = idx & 255;                       // K=256,N=512
        g_w1at[idx] = __float2half(w1[(size_t)k * 512 + n]);
    } else if (idx < 262144) {
        int t = idx - 131072;
        int n = t >> 8, k = t & 255;
        g_w1bt[t] = __float2half(w1[(size_t)(k + 256) * 512 + n]);
    } else if (idx < 393216) {
        int t = idx - 262144;
        int n = t >> 9, k = t & 511;                           // K=512,N=256
        g_w2t[t] = __float2half(w2[(size_t)k * 256 + n]);
    } else if (idx < 655360) {
        int t = idx - 393216;
        int n = t >> 8, k = t & 255;                           // K=256,N=1024
        g_u1t[t] = __float2half(u1[(size_t)k * 1024 + n]);
    } else if (idx < 917504) {
        int t = idx - 655360;
        int n = t >> 10, k = t & 1023;                         // K=1024,N=256
        g_u2t[t] = __float2half(u2[(size_t)k * 256 + n]);
    }
}

// ---------------- LayerNorm (fp16 output; feeds MMA only) -------------------
__global__ void ln_kernel(const float* __restrict__ x,
                          const float* __restrict__ w,
                          const float* __restrict__ b,
                          __half* __restrict__ y,
                          int zero_agg) {
    int row = blockIdx.x;
    int t = threadIdx.x;
    float v = x[(size_t)row*Hdim + t];

    __shared__ float red[8];
    __shared__ float stat[2];

    float s = v;
    #pragma unroll
    for (int o = 16; o > 0; o >>= 1) s += __shfl_xor_sync(0xffffffffu, s, o);
    if ((t & 31) == 0) red[t >> 5] = s;
    __syncthreads();
    if (t == 0) {
        float m = 0.f;
        #pragma unroll
        for (int i = 0; i < 8; i++) m += red[i];
        stat[0] = m * (1.0f / Hdim);
    }
    __syncthreads();
    float mu = stat[0];
    float d = v - mu;
    s = d * d;
    #pragma unroll
    for (int o = 16; o > 0; o >>= 1) s += __shfl_xor_sync(0xffffffffu, s, o);
    if ((t & 31) == 0) red[t >> 5] = s;
    __syncthreads();
    if (t == 0) {
        float q = 0.f;
        #pragma unroll
        for (int i = 0; i < 8; i++) q += red[i];
        stat[1] = rsqrtf(q * (1.0f / Hdim) + 1e-5f);
    }
    __syncthreads();
    y[(size_t)row*Hdim + t] = __float2half(d * stat[1] * w[t] + b[t]);
    if (zero_agg) g_agg[(size_t)row*Hdim + t] = 0.f;
}

// ---------------- fused fwd+rev edge pre-activation + GELU (fp16 IO) --------
__global__ void edge_pre2_kernel(const float* __restrict__ xyz,
                                 const float* __restrict__ w1,
                                 const float* __restrict__ b1,
                                 int off, int Ce) {
    int m = blockIdx.x;
    int nidx = m / Ce;
    int c = m - nidx * Ce;
    int i = nidx * Cdim + c;
    int j = i + off;

    __shared__ float ef[4];
    if (threadIdx.x == 0) {
        float dx = xyz[3*j+0] - xyz[3*i+0];
        float dy = xyz[3*j+1] - xyz[3*i+1];
        float dz = xyz[3*j+2] - xyz[3*i+2];
        float d = fmaxf(sqrtf(dx*dx + dy*dy + dz*dz), 1e-6f);
        float inv = 1.0f / d;
        ef[0] = dx * inv; ef[1] = dy * inv; ef[2] = dz * inv; ef[3] = d;
    }
    __syncthreads();

    int f = threadIdx.x * 4;
    float pi[4], qi[4], pj[4], qj[4];
    ld4h(g_P + (size_t)i*H2 + f, pi);
    ld4h(g_Q + (size_t)i*H2 + f, qi);
    ld4h(g_P + (size_t)j*H2 + f, pj);
    ld4h(g_Q + (size_t)j*H2 + f, qj);
    float4 bb = *(const float4*)(b1 + f);
    float4 w0 = *(const float4*)(w1 + (size_t)(2*Hdim + 0)*H2 + f);
    float4 w1r= *(const float4*)(w1 + (size_t)(2*Hdim + 1)*H2 + f);
    float4 w2r= *(const float4*)(w1 + (size_t)(2*Hdim + 2)*H2 + f);
    float4 w3r= *(const float4*)(w1 + (size_t)(2*Hdim + 3)*H2 + f);
    float e0 = ef[0], e1 = ef[1], e2 = ef[2], e3 = ef[3];

    float eu[4], ed[4];
    eu[0] = e0*w0.x + e1*w1r.x + e2*w2r.x;  ed[0] = e3*w3r.x + bb.x;
    eu[1] = e0*w0.y + e1*w1r.y + e2*w2r.y;  ed[1] = e3*w3r.y + bb.y;
    eu[2] = e0*w0.z + e1*w1r.z + e2*w2r.z;  ed[2] = e3*w3r.z + bb.z;
    eu[3] = e0*w0.w + e1*w1r.w + e2*w2r.w;  ed[3] = e3*w3r.w + bb.w;

    float rf[4], rr[4];
    #pragma unroll
    for (int q = 0; q < 4; q++) {
        rf[q] = gelu_exact(pi[q] + qj[q] + eu[q] + ed[q]);
        rr[q] = gelu_exact(pj[q] + qi[q] - eu[q] + ed[q]);
    }
    st4h(g_G  + (size_t)m*H2 + f, rf);
    st4h(g_T1 + (size_t)m*H2 + f, rr);
}

// ---------------- h2 = h + agg*valid -----------------------------------------
__global__ void h2_kernel(const float* __restrict__ h) {
    int row = blockIdx.x;
    int t = threadIdx.x;
    size_t idx = (size_t)row*Hdim + t;
    float vf = g_valid[row] ? 1.0f : 0.0f;
    g_h2[idx] = h[idx] + g_agg[idx] * vf;
}

// ============================================================================
// tcgen05 f16 GEMM: C[M,N] = A[M,K] @ Bt[N,K]^T, fp16 inputs, fp32 accum.
// Tile 128x256, BK=64 (4 MMA dispatches of K=16), double-buffered.
// ============================================================================
__device__ __forceinline__ uint32_t smem_u32(const void* p) {
    uint32_t a;
    asm("{ .reg .u64 t; cvta.to.shared.u64 t, %1; cvt.u32.u64 %0, t; }" : "=r"(a) : "l"(p));
    return a;
}
__device__ __forceinline__ void mbar_wait(uint32_t mbar, uint32_t parity) {
    asm volatile(
        "{\n\t.reg .pred P1;\n\t"
        "W_%=:\n\t"
        "mbarrier.try_wait.parity.acquire.cta.shared::cta.b64 P1, [%0], %1, 0x989680;\n\t"
        "@P1 bra.uni D_%=;\n\t"
        "bra.uni W_%=;\n\t"
        "D_%=:\n\t}"
        :: "r"(mbar), "r"(parity) : "memory");
}

#if HAS_TC
__device__ __forceinline__ void mma_f16_ss(uint32_t d_tmem, uint64_t a_desc,
                                           uint64_t b_desc, uint32_t idesc, bool acc) {
    uint32_t en = acc ? 1u : 0u;
    asm volatile(
        "{\n\t.reg .pred p;\n\t"
        "setp.ne.u32 p, %5, 0;\n\t"
        "tcgen05.mma.cta_group::1.kind::f16 [%0], %1, %2, %3, {%4, %4, %4, %4}, p;\n\t"
        "}"
        :: "r"(d_tmem), "l"(a_desc), "l"(b_desc), "r"(idesc), "r"(0u), "r"(en)
        : "memory");
}
#define LDTM_X32(r, addr) \
    asm volatile( \
        "tcgen05.ld.sync.aligned.32x32b.x32.b32 " \
        "{%0, %1, %2, %3, %4, %5, %6, %7, " \
        " %8, %9, %10, %11, %12, %13, %14, %15, " \
        " %16, %17, %18, %19, %20, %21, %22, %23, " \
        " %24, %25, %26, %27, %28, %29, %30, %31}, [%32];" \
        : "=r"((r)[0]),  "=r"((r)[1]),  "=r"((r)[2]),  "=r"((r)[3]), \
          "=r"((r)[4]),  "=r"((r)[5]),  "=r"((r)[6]),  "=r"((r)[7]), \
          "=r"((r)[8]),  "=r"((r)[9]),  "=r"((r)[10]), "=r"((r)[11]), \
          "=r"((r)[12]), "=r"((r)[13]), "=r"((r)[14]), "=r"((r)[15]), \
          "=r"((r)[16]), "=r"((r)[17]), "=r"((r)[18]), "=r"((r)[19]), \
          "=r"((r)[20]), "=r"((r)[21]), "=r"((r)[22]), "=r"((r)[23]), \
          "=r"((r)[24]), "=r"((r)[25]), "=r"((r)[26]), "=r"((r)[27]), \
          "=r"((r)[28]), "=r"((r)[29]), "=r"((r)[30]), "=r"((r)[31]) \
        : "r"(addr))
#endif

static constexpr unsigned long long DESC_BASE =
    (2ull << 61) | (1ull << 46) | (64ull << 32) | (1ull << 16);  // SW128 K-major
// idesc kind::f16 fp16: dtype=F32(1)<<4, atype=F16(0)<<7, btype=F16(0)<<10,
// N=256 -> 32<<17, M=128 -> 8<<24
#define MMA_IDESC ((1u<<4) | (32u<<17) | (8u<<24))
// smem: pad(1024) + A0(16K) A1(16K) B0(32K) B1(32K) + ctrl(64)
#define SMEM_DYN  (1024 + 98304 + 64)

// EPI 0: plain half store; 1: half(gelu(acc+bias)); 2: agg[target] += (acc+bias) if valid;
// EPI 3: out = (aux + acc + bias) * valid  (float)
template<int EPI>
__global__ void __launch_bounds__(256)
mma_gemm(const __half* __restrict__ A, int lda,
         const __half* __restrict__ Bt,   // [N, K] row-major fp16
         const float* __restrict__ bias,
         void* __restrict__ CoutV, int ldc,
         const float* __restrict__ aux,
         int K, int off, int dir, int Ce) {
    extern __shared__ char dyn[];
    int tid = threadIdx.x;
    int m0 = blockIdx.y * 128;
    int n0 = blockIdx.x * 256;

#if HAS_TC
    uint32_t u0 = smem_u32(dyn);
    uint32_t pad = (1024u - (u0 & 1023u)) & 1023u;
    char* base = dyn + pad;
    uint32_t ub = u0 + pad;

    uint32_t ctrl  = ub + 98304;
    uint32_t mbar0 = ctrl + 8;

    int wid = tid >> 5;
    int lane = tid & 31;

    if (tid == 0) {
        asm volatile("mbarrier.init.shared.b64 [%0], 1;" :: "r"(mbar0)     : "memory");
        asm volatile("mbarrier.init.shared.b64 [%0], 1;" :: "r"(mbar0 + 8) : "memory");
    }
    if (wid == 0) {
        asm volatile("tcgen05.alloc.cta_group::1.sync.aligned.shared::cta.b32 [%0], %1;"
                     :: "r"(ctrl), "r"(256u) : "memory");
        asm volatile("tcgen05.relinquish_alloc_permit.cta_group::1.sync.aligned;");
    }
    __syncthreads();
    uint32_t tmem;
    asm volatile("ld.shared.b32 %0, [%1];" : "=r"(tmem) : "r"(ctrl));

    const int NCH = K >> 6;                    // BK = 64 halves = 128 bytes/row
    for (int c = 0; c < NCH; c++) {
        int buf = c & 1;
        if (c >= 2) mbar_wait(mbar0 + 8u * buf, (uint32_t)(((c - 2) >> 1) & 1));
        char* sA = base + buf * 16384;
        char* sB = base + 32768 + buf * 32768;
        int k0 = c << 6;

        // A tile: 128 rows x 64 halves (8 uint4/row; 4 uint4/thread)
        #pragma unroll
        for (int i = 0; i < 4; i++) {
            int idx = tid + i * 256;
            int r = idx >> 3, f4 = idx & 7;
            uint4 av = *(const uint4*)(A + (size_t)(m0 + r) * lda + k0 + f4 * 8);
            uint32_t so = (uint32_t)(r * 128 + f4 * 16);
            so ^= (so >> 3) & 0x70u;
            *(uint4*)(sA + so) = av;
        }
        // B tile: 256 rows x 64 halves (8 uint4/thread)
        #pragma unroll
        for (int i = 0; i < 8; i++) {
            int idx = tid + i * 256;
            int r = idx >> 3, f4 = idx & 7;
            uint4 bv = *(const uint4*)(Bt + (size_t)(n0 + r) * K + k0 + f4 * 8);
            uint32_t so = (uint32_t)(r * 128 + f4 * 16);
            so ^= (so >> 3) & 0x70u;
            *(uint4*)(sB + so) = bv;
        }
        asm volatile("fence.proxy.async.shared::cta;" ::: "memory");
        __syncthreads();

        if (tid == 0) {
            uint32_t aaddr = ub + (uint32_t)(buf * 16384);
            uint32_t baddr = ub + (uint32_t)(32768 + buf * 32768);
            uint64_t adesc = DESC_BASE | (uint64_t)((aaddr >> 4) & 0x3FFFu);
            uint64_t bdesc = DESC_BASE | (uint64_t)((baddr >> 4) & 0x3FFFu);
            #pragma unroll
            for (int s = 0; s < 4; s++) {     // 4 steps of K=16 (32B = 2 units)
                mma_f16_ss(tmem, adesc + 2u * s, bdesc + 2u * s, MMA_IDESC,
                           !(c == 0 && s == 0));
            }
            asm volatile(
                "tcgen05.commit.cta_group::1.mbarrier::arrive::one.shared::cluster.b64 [%0];"
                :: "r"(mbar0 + 8u * buf) : "memory");
        }
    }
    mbar_wait(mbar0 + 8u * ((NCH - 2) & 1), (uint32_t)(((NCH - 2) >> 1) & 1));
    mbar_wait(mbar0 + 8u * ((NCH - 1) & 1), (uint32_t)(((NCH - 1) >> 1) & 1));
    asm volatile("tcgen05.fence::after_thread_sync;" ::: "memory");

    // ---------------- epilogue: warps 0-3 read TMEM D (256 cols) ----------------
    if (wid < 4) {
        int trow = wid * 32 + lane;
        int m = m0 + trow;
        int tgt = 0; bool do_write = true;
        if (EPI == 2) {
            int nidx = m / Ce;
            int cc2 = m - nidx * Ce;
            int ii = nidx * Cdim + cc2;
            int jj = ii + off;
            do_write = (g_valid[ii] && g_valid[jj]);
            tgt = dir ? jj : ii;
        }
        float vf = 1.0f;
        if (EPI == 3) vf = g_valid[m] ? 1.0f : 0.0f;

        #pragma unroll
        for (int cc = 0; cc < 256; cc += 32) {
            uint32_t r[32];
            LDTM_X32(r, tmem + (uint32_t)cc);
            asm volatile("tcgen05.wait::ld.sync.aligned;" ::: "memory");
            int col0 = n0 + cc;
            if (EPI == 0) {
                __half* Cout = (__half*)CoutV;
                #pragma unroll
                for (int j = 0; j < 32; j += 4) {
                    float o[4] = {__uint_as_float(r[j]), __uint_as_float(r[j+1]),
                                  __uint_as_float(r[j+2]), __uint_as_float(r[j+3])};
                    st4h(Cout + (size_t)m * ldc + col0 + j, o);
                }
            } else if (EPI == 1) {
                __half* Cout = (__half*)CoutV;
                #pragma unroll
                for (int j = 0; j < 32; j += 4) {
                    float o[4];
                    o[0] = gelu_exact(__uint_as_float(r[j])   + __ldg(&bias[col0+j]));
                    o[1] = gelu_exact(__uint_as_float(r[j+1]) + __ldg(&bias[col0+j+1]));
                    o[2] = gelu_exact(__uint_as_float(r[j+2]) + __ldg(&bias[col0+j+2]));
                    o[3] = gelu_exact(__uint_as_float(r[j+3]) + __ldg(&bias[col0+j+3]));
                    st4h(Cout + (size_t)m * ldc + col0 + j, o);
                }
            } else if (EPI == 2) {
                if (do_write) {
                    float* d = g_agg + (size_t)tgt * Hdim + col0;
                    #pragma unroll
                    for (int j = 0; j < 32; j += 4) {
                        float4 old = *(float4*)(d + j);
                        old.x += __uint_as_float(r[j])   + __ldg(&bias[col0+j]);
                        old.y += __uint_as_float(r[j+1]) + __ldg(&bias[col0+j+1]);
                        old.z += __uint_as_float(r[j+2]) + __ldg(&bias[col0+j+2]);
                        old.w += __uint_as_float(r[j+3]) + __ldg(&bias[col0+j+3]);
                        *(float4*)(d + j) = old;
                    }
                }
            } else { // EPI == 3
                float* Cout = (float*)CoutV;
                const float* a2 = aux + (size_t)m * Hdim + col0;
                #pragma unroll
                for (int j = 0; j < 32; j += 4) {
                    float4 av = *(const float4*)(a2 + j);
                    float4 o;
                    o.x = (av.x + __uint_as_float(r[j])   + __ldg(&bias[col0+j]))   * vf;
                    o.y = (av.y + __uint_as_float(r[j+1]) + __ldg(&bias[col0+j+1])) * vf;
                    o.z = (av.z + __uint_as_float(r[j+2]) + __ldg(&bias[col0+j+2])) * vf;
                    o.w = (av.w + __uint_as_float(r[j+3]) + __ldg(&bias[col0+j+3])) * vf;
                    *(float4*)(Cout + (size_t)m * ldc + col0 + j) = o;
                }
            }
        }
    }
    __syncthreads();
    if (wid == 0) {
        asm volatile("tcgen05.dealloc.cta_group::1.sync.aligned.b32 %0, %1;"
                     :: "r"(tmem), "r"(256u));
    }

#else  // ---------------- SIMT fallback (compute_103 PTX pass) ----------------
    float* As = (float*)dyn;            // [16][128]
    float* Bs = (float*)(dyn + 8192);   // [16][128]

    int tr = tid >> 4, tc = tid & 15;
    int lrow = tid >> 1;
    int lk   = (tid & 1) * 8;

    for (int half = 0; half < 2; half++) {
        int n0h = n0 + half * 128;
        float acc[8][8] = {};
        for (int k0 = 0; k0 < K; k0 += 16) {
            #pragma unroll
            for (int e = 0; e < 8; e++) {
                As[(lk+e)*128 + lrow] = __half2float(A[(size_t)(m0 + lrow) * lda + k0 + lk + e]);
                Bs[(lk+e)*128 + lrow] = __half2float(Bt[(size_t)(n0h + lrow) * K + k0 + lk + e]);
            }
            __syncthreads();
            #pragma unroll
            for (int k = 0; k < 16; k++) {
                float a[8], b[8];
                #pragma unroll
                for (int i = 0; i < 8; i++) a[i] = As[k*128 + tr*8 + i];
                #pragma unroll
                for (int j = 0; j < 8; j++) b[j] = Bs[k*128 + tc*8 + j];
                #pragma unroll
                for (int i = 0; i < 8; i++)
                    #pragma unroll
                    for (int j = 0; j < 8; j++)
                        acc[i][j] += a[i] * b[j];
            }
            __syncthreads();
        }

        int col0 = n0h + tc * 8;
        #pragma unroll
        for (int i = 0; i < 8; i++) {
            int m = m0 + tr * 8 + i;
            if (EPI == 0) {
                __half* Cout = (__half*)CoutV;
                #pragma unroll
                for (int j = 0; j < 8; j++)
                    Cout[(size_t)m * ldc + col0 + j] = __float2half(acc[i][j]);
            } else if (EPI == 1) {
                __half* Cout = (__half*)CoutV;
                #pragma unroll
                for (int j = 0; j < 8; j++)
                    Cout[(size_t)m * ldc + col0 + j] =
                        __float2half(gelu_exact(acc[i][j] + bias[col0 + j]));
            } else if (EPI == 2) {
                int nidx = m / Ce;
                int cc2 = m - nidx * Ce;
                int ii = nidx * Cdim + cc2;
                int jj = ii + off;
                if (g_valid[ii] && g_valid[jj]) {
                    int tgt = dir ? jj : ii;
                    float* d = g_agg + (size_t)tgt * Hdim + col0;
                    #pragma unroll
                    for (int j = 0; j < 8; j++)
                        d[j] += acc[i][j] + bias[col0 + j];
                }
            } else {
                float* Cout = (float*)CoutV;
                float vf = g_valid[m] ? 1.0f : 0.0f;
                const float* a2 = aux + (size_t)m * Hdim + col0;
                #pragma unroll
                for (int j = 0; j < 8; j++)
                    Cout[(size_t)m * ldc + col0 + j] =
                        (a2[j] + acc[i][j] + bias[col0 + j]) * vf;
            }
        }
        __syncthreads();
    }
#endif
}

// ---------------- launch -----------------------------------------------------
extern "C" void kernel_launch(void* const* d_in, const int* in_sizes, int n_in,
                              void* d_out, int out_size) {
    const float*         h      = (const float*)d_in[0];
    const float*         xyz    = (const float*)d_in[1];
    const unsigned char* validb = (const unsigned char*)d_in[2];
    const float*         ln_n_w = (const float*)d_in[3];
    const float*         ln_n_b = (const float*)d_in[4];
    const float*         w1     = (const float*)d_in[5];
    const float*         b1     = (const float*)d_in[6];
    const float*         w2     = (const float*)d_in[7];
    const float*         b2     = (const float*)d_in[8];
    const float*         ln_u_w = (const float*)d_in[9];
    const float*         ln_u_b = (const float*)d_in[10];
    const float*         u1     = (const float*)d_in[11];
    const float*         bu1    = (const float*)d_in[12];
    const float*         u2     = (const float*)d_in[13];
    const float*         bu2    = (const float*)d_in[14];
    float* out = (float*)d_out;

    __half *pHin, *pP, *pQ, *pG, *pHu, *pT1;
    __half *pW1at, *pW1bt, *pW2t, *pU1t, *pU2t;
    float *pH2;
    cudaGetSymbolAddress((void**)&pHin, g_hin);
    cudaGetSymbolAddress((void**)&pP,   g_P);
    cudaGetSymbolAddress((void**)&pQ,   g_Q);
    cudaGetSymbolAddress((void**)&pG,   g_G);
    cudaGetSymbolAddress((void**)&pH2,  g_h2);
    cudaGetSymbolAddress((void**)&pHu,  g_hu);
    cudaGetSymbolAddress((void**)&pT1,  g_T1);
    cudaGetSymbolAddress((void**)&pW1at, g_w1at);
    cudaGetSymbolAddress((void**)&pW1bt, g_w1bt);
    cudaGetSymbolAddress((void**)&pW2t,  g_w2t);
    cudaGetSymbolAddress((void**)&pU1t,  g_u1t);
    cudaGetSymbolAddress((void**)&pU2t,  g_u2t);

    cudaFuncSetAttribute(mma_gemm<0>, cudaFuncAttributeMaxDynamicSharedMemorySize, SMEM_DYN);
    cudaFuncSetAttribute(mma_gemm<1>, cudaFuncAttributeMaxDynamicSharedMemorySize, SMEM_DYN);
    cudaFuncSetAttribute(mma_gemm<2>, cudaFuncAttributeMaxDynamicSharedMemorySize, SMEM_DYN);
    cudaFuncSetAttribute(mma_gemm<3>, cudaFuncAttributeMaxDynamicSharedMemorySize, SMEM_DYN);

    // 0. normalize valid; transpose all weights (one launch, fp16)
    detect_vmode_kernel<<<1, 32>>>(validb);
    conv_valid_kernel<<<(NC + 255) / 256, 256>>>(validb);
    transpose_all_kernel<<<917504/256, 256>>>(w1, w2, u1, u2);

    // 1. h_in = LN(h) (fp16), zero agg
    ln_kernel<<<NC, 256>>>(h, ln_n_w, ln_n_b, pHin, 1);

    // 2. P = h_in @ W1a, Q = h_in @ W1b   (M=NC, K=256, N=512)
    mma_gemm<0><<<dim3(H2/256, NC/128), 256, SMEM_DYN>>>(pHin, Hdim, pW1at,
                                                         nullptr, pP, H2, nullptr,
                                                         Hdim, 0, 0, 0);
    mma_gemm<0><<<dim3(H2/256, NC/128), 256, SMEM_DYN>>>(pHin, Hdim, pW1bt,
                                                         nullptr, pQ, H2, nullptr,
                                                         Hdim, 0, 0, 0);

    // 3. edge messages: fused fwd+rev pre, then two GEMMs with agg-RMW epilogue
    const int offs[4] = {1, 2, 4, 8};
    for (int oi = 0; oi < 4; oi++) {
        int off = offs[oi];
        int Ce = Cdim - off;
        int Me = Ndim * Ce;   // multiple of 128
        edge_pre2_kernel<<<Me, 128>>>(xyz, w1, b1, off, Ce);
        mma_gemm<2><<<dim3(Hdim/256, Me/128), 256, SMEM_DYN>>>(pG, H2, pW2t,
                                                               b2, nullptr, Hdim, nullptr,
                                                               H2, off, 0, Ce);
        mma_gemm<2><<<dim3(Hdim/256, Me/128), 256, SMEM_DYN>>>(pT1, H2, pW2t,
                                                               b2, nullptr, Hdim, nullptr,
                                                               H2, off, 1, Ce);
    }

    // 4. h2 = h + agg * valid
    h2_kernel<<<NC, 256>>>(h);

    // 5. update MLP
    ln_kernel<<<NC, 256>>>(pH2, ln_u_w, ln_u_b, pHu, 0);
    mma_gemm<1><<<dim3(HU/256, NC/128), 256, SMEM_DYN>>>(pHu, Hdim, pU1t,
                                                         bu1, pT1, HU, nullptr,
                                                         Hdim, 0, 0, 0);
    mma_gemm<3><<<dim3(Hdim/256, NC/128), 256, SMEM_DYN>>>(pT1, HU, pU2t,
                                                           bu2, out, Hdim, pH2,
                                                           HU, 0, 0, 0);
    (void)in_sizes; (void)n_in; (void)out_size;
}

// round 7
// speedup vs baseline: 6.2549x; 2.3472x over previous
#include <cuda_runtime.h>
#include <cuda_fp16.h>
#include <math.h>
#include <stdint.h>

#define Ndim 256
#define Cdim 512
#define Hdim 256
#define NC   (Ndim*Cdim)   // 131072
#define H2   512
#define HU   1024
#define MAXE 520448        // total directed-edge slots over offsets {1,2,4,8}
#define NB   2033          // MAXE / 256

#if defined(__CUDA_ARCH_FEAT_SM103_ALL) || defined(__CUDA_ARCH_FEAT_SM100_ALL) || \
    (defined(__CUDA_ARCH_SPECIFIC__) && (__CUDA_ARCH_SPECIFIC__ >= 1000))
#define HAS_TC 1
#else
#define HAS_TC 0
#endif

// ---------------- scratch ----------------------------------------------------
__device__ __half g_hin[(size_t)NC*Hdim];
__device__ __half g_PQ [(size_t)NC*HU];        // cols 0-511 = P, 512-1023 = Q
__device__ __half g_Gf [(size_t)MAXE*H2];      // fwd edge activations (compacted)
__device__ __half g_Gr [(size_t)MAXE*H2];      // rev edge activations (compacted)
__device__ float  g_agg[(size_t)NC*Hdim];
__device__ float  g_h2 [(size_t)NC*Hdim];
__device__ __half g_hu [(size_t)NC*Hdim];
__device__ __half g_T1 [(size_t)NC*HU];
__device__ __half g_wabt[(size_t)HU*Hdim];     // [1024,256] concat(W1a^T, W1b^T)
__device__ __half g_w2t [(size_t)Hdim*H2];
__device__ __half g_u1t [(size_t)HU*Hdim];
__device__ __half g_u2t [(size_t)Hdim*HU];
__device__ unsigned char g_valid[NC];
__device__ int g_vmode;
__device__ int g_ei[MAXE];
__device__ int g_ej[MAXE];
__device__ int g_bcount[2048];
__device__ int g_boffs[2048];
__device__ int g_E;
__device__ int g_Estart[5];                    // per-offset compacted ranges

__device__ __forceinline__ float gelu_exact(float x) {
    return 0.5f * x * (1.0f + erff(x * 0.70710678118654752f));
}
__device__ __forceinline__ void ld4h(const __half* p, float* f) {
    uint2 u = *(const uint2*)p;
    float2 fa = __half22float2(*(__half2*)&u.x);
    float2 fb = __half22float2(*(__half2*)&u.y);
    f[0] = fa.x; f[1] = fa.y; f[2] = fb.x; f[3] = fb.y;
}
__device__ __forceinline__ void st4h(__half* p, const float* f) {
    uint2 u;
    *(__half2*)&u.x = __float22half2_rn(make_float2(f[0], f[1]));
    *(__half2*)&u.y = __float22half2_rn(make_float2(f[2], f[3]));
    *(uint2*)p = u;
}

// edge id -> (i, j) decode; ids grouped by offset; group sizes are
// 256-divisible so count-block boundaries align with offset boundaries.
__device__ __forceinline__ void decode_edge(int g, int& i, int& j) {
    int off, Ce, t;
    if (g < 130816)      { off = 1; Ce = 511; t = g; }
    else if (g < 261376) { off = 2; Ce = 510; t = g - 130816; }
    else if (g < 391424) { off = 4; Ce = 508; t = g - 261376; }
    else                 { off = 8; Ce = 504; t = g - 391424; }
    int n = t / Ce, c = t - n * Ce;
    i = (n << 9) + c; j = i + off;
}

// ---------------- valid dtype detection + normalization ---------------------
__global__ void detect_vmode_kernel(const unsigned char* __restrict__ v) {
    if (threadIdx.x == 0) {
        int nz1 = 0, nz23 = 0;
        for (int i = 0; i < 4096; i += 4) {
            if (v[i+1]) nz1 = 1;
            if (v[i+2] | v[i+3]) nz23 = 1;
        }
        g_vmode = nz1 ? 0 : (nz23 ? 2 : 1);
    }
}
__global__ void conv_valid_kernel(const unsigned char* __restrict__ v) {
    int i = blockIdx.x * 256 + threadIdx.x;
    if (i >= NC) return;
    int mode = g_vmode;
    unsigned char r;
    if (mode == 0)      r = v[i] != 0;
    else if (mode == 1) r = ((const int*)v)[i] != 0;
    else                r = ((const unsigned int*)v)[i] != 0u;
    g_valid[i] = r;
}

// ---------------- weight transposes (fp16), one launch -----------------------
__global__ void transpose_all_kernel(const float* __restrict__ w1,
                                     const float* __restrict__ w2,
                                     const float* __restrict__ u1,
                                     const float* __restrict__ u2) {
    int idx = blockIdx.x * 256 + threadIdx.x;
    if (idx < 262144) {                         // g_wabt [1024,256]
        int n = idx >> 8, k = idx & 255;
        float s = (n < 512) ? w1[(size_t)k * 512 + n]
                            : w1[(size_t)(k + 256) * 512 + (n - 512)];
        g_wabt[idx] = __float2half(s);
    } else if (idx < 393216) {                  // g_w2t [256,512]
        int t = idx - 262144;
        int n = t >> 9, k = t & 511;
        g_w2t[t] = __float2half(w2[(size_t)k * 256 + n]);
    } else if (idx < 655360) {                  // g_u1t [1024,256]
        int t = idx - 393216;
        int n = t >> 8, k = t & 255;
        g_u1t[t] = __float2half(u1[(size_t)k * 1024 + n]);
    } else if (idx < 917504) {                  // g_u2t [256,1024]
        int t = idx - 655360;
        int n = t >> 10, k = t & 1023;
        g_u2t[t] = __float2half(u2[(size_t)k * 256 + n]);
    }
}

// ---------------- LayerNorm: one row per warp --------------------------------
__global__ void ln_kernel(const float* __restrict__ x,
                          const float* __restrict__ w,
                          const float* __restrict__ b,
                          __half* __restrict__ y,
                          int zero_agg) {
    int warp = threadIdx.x >> 5, lane = threadIdx.x & 31;
    int row = blockIdx.x * 8 + warp;
    const float* xr = x + (size_t)row * Hdim + lane * 8;
    float4 a = *(const float4*)xr;
    float4 c = *(const float4*)(xr + 4);
    float s = a.x + a.y + a.z + a.w + c.x + c.y + c.z + c.w;
    #pragma unroll
    for (int o = 16; o > 0; o >>= 1) s += __shfl_xor_sync(0xffffffffu, s, o);
    float mu = s * (1.0f / Hdim);
    float v[8] = {a.x-mu, a.y-mu, a.z-mu, a.w-mu, c.x-mu, c.y-mu, c.z-mu, c.w-mu};
    float q = 0.f;
    #pragma unroll
    for (int k = 0; k < 8; k++) q += v[k] * v[k];
    #pragma unroll
    for (int o = 16; o > 0; o >>= 1) q += __shfl_xor_sync(0xffffffffu, q, o);
    float inv = rsqrtf(q * (1.0f / Hdim) + 1e-5f);
    const float* wp = w + lane * 8;
    const float* bp = b + lane * 8;
    float o0[4], o1[4];
    #pragma unroll
    for (int k = 0; k < 4; k++) o0[k] = v[k]   * inv * wp[k]   + bp[k];
    #pragma unroll
    for (int k = 0; k < 4; k++) o1[k] = v[4+k] * inv * wp[4+k] + bp[4+k];
    __half* yr = y + (size_t)row * Hdim + lane * 8;
    st4h(yr, o0); st4h(yr + 4, o1);
    if (zero_agg) {
        float4 z = {0.f, 0.f, 0.f, 0.f};
        float* ar = g_agg + (size_t)row * Hdim + lane * 8;
        *(float4*)ar = z; *(float4*)(ar + 4) = z;
    }
}

// ---------------- compaction: count / scan / scatter -------------------------
__global__ void count_kernel() {
    int g = blockIdx.x * 256 + threadIdx.x;
    int i, j; decode_edge(g, i, j);
    int pred = g_valid[i] & g_valid[j];
    unsigned bal = __ballot_sync(0xffffffffu, pred);
    __shared__ int wcnt[8];
    if ((threadIdx.x & 31) == 0) wcnt[threadIdx.x >> 5] = __popc(bal);
    __syncthreads();
    if (threadIdx.x == 0) {
        int s = 0;
        #pragma unroll
        for (int k = 0; k < 8; k++) s += wcnt[k];
        g_bcount[blockIdx.x] = s;
    }
}

__global__ void scan_kernel() {
    __shared__ int part[256];
    int t = threadIdx.x;
    int base = t * 8;
    int loc[8];
    int s = 0;
    #pragma unroll
    for (int k = 0; k < 8; k++) {
        int idx = base + k;
        int v = (idx < NB) ? g_bcount[idx] : 0;
        loc[k] = s; s += v;
    }
    part[t] = s;
    __syncthreads();
    for (int o = 1; o < 256; o <<= 1) {
        int v = part[t];
        int add = (t >= o) ? part[t - o] : 0;
        __syncthreads();
        part[t] = v + add;
        __syncthreads();
    }
    int excl = part[t] - s;   // exclusive prefix for this thread's chunk
    #pragma unroll
    for (int k = 0; k < 8; k++) {
        int idx = base + k;
        if (idx < 2048) g_boffs[idx] = excl + loc[k];
    }
    __syncthreads();
    if (t == 0) {
        int total = part[255];
        g_E = total;
        g_Estart[0] = 0;
        g_Estart[1] = g_boffs[511];    // 130816/256
        g_Estart[2] = g_boffs[1021];   // 261376/256
        g_Estart[3] = g_boffs[1529];   // 391424/256
        g_Estart[4] = total;
    }
}

__global__ void scatter_kernel() {
    int g = blockIdx.x * 256 + threadIdx.x;
    int lane = threadIdx.x & 31, warp = threadIdx.x >> 5;
    int i, j; decode_edge(g, i, j);
    int pred = g_valid[i] & g_valid[j];
    unsigned bal = __ballot_sync(0xffffffffu, pred);
    __shared__ int wcnt[8], wbase[8];
    if (lane == 0) wcnt[warp] = __popc(bal);
    __syncthreads();
    if (threadIdx.x == 0) {
        int s = 0;
        #pragma unroll
        for (int k = 0; k < 8; k++) { wbase[k] = s; s += wcnt[k]; }
    }
    __syncthreads();
    if (pred) {
        int pos = g_boffs[blockIdx.x] + wbase[warp]
                + __popc(bal & ((1u << lane) - 1u));
        g_ei[pos] = i; g_ej[pos] = j;
    }
}

// ---------------- edge pre-activation + GELU over compacted edges -----------
__global__ void edge_pre_kernel(const float* __restrict__ xyz,
                                const float* __restrict__ w1,
                                const float* __restrict__ b1) {
    int E = g_E;
    int f = threadIdx.x * 4;
    float4 bb = *(const float4*)(b1 + f);
    float4 w0 = *(const float4*)(w1 + (size_t)(2*Hdim + 0)*H2 + f);
    float4 w1r= *(const float4*)(w1 + (size_t)(2*Hdim + 1)*H2 + f);
    float4 w2r= *(const float4*)(w1 + (size_t)(2*Hdim + 2)*H2 + f);
    float4 w3r= *(const float4*)(w1 + (size_t)(2*Hdim + 3)*H2 + f);

    for (int m = blockIdx.x; m < E; m += gridDim.x) {
        int i = g_ei[m], j = g_ej[m];
        float dx = xyz[3*j+0] - xyz[3*i+0];
        float dy = xyz[3*j+1] - xyz[3*i+1];
        float dz = xyz[3*j+2] - xyz[3*i+2];
        float d = fmaxf(sqrtf(dx*dx + dy*dy + dz*dz), 1e-6f);
        float inv = 1.0f / d;
        float e0 = dx*inv, e1 = dy*inv, e2 = dz*inv, e3 = d;

        float pi[4], qi[4], pj[4], qj[4];
        ld4h(g_PQ + (size_t)i*HU + f,       pi);
        ld4h(g_PQ + (size_t)i*HU + 512 + f, qi);
        ld4h(g_PQ + (size_t)j*HU + f,       pj);
        ld4h(g_PQ + (size_t)j*HU + 512 + f, qj);

        float eu[4], ed[4];
        eu[0] = e0*w0.x + e1*w1r.x + e2*w2r.x;  ed[0] = e3*w3r.x + bb.x;
        eu[1] = e0*w0.y + e1*w1r.y + e2*w2r.y;  ed[1] = e3*w3r.y + bb.y;
        eu[2] = e0*w0.z + e1*w1r.z + e2*w2r.z;  ed[2] = e3*w3r.z + bb.z;
        eu[3] = e0*w0.w + e1*w1r.w + e2*w2r.w;  ed[3] = e3*w3r.w + bb.w;

        float rf[4], rr[4];
        #pragma unroll
        for (int q = 0; q < 4; q++) {
            rf[q] = gelu_exact(pi[q] + qj[q] + eu[q] + ed[q]);
            rr[q] = gelu_exact(pj[q] + qi[q] - eu[q] + ed[q]);
        }
        st4h(g_Gf + (size_t)m*H2 + f, rf);
        st4h(g_Gr + (size_t)m*H2 + f, rr);
    }
}

// ---------------- h2 = h + agg*valid (vectorized) ----------------------------
__global__ void h2_kernel(const float* __restrict__ h) {
    int gid = blockIdx.x * 256 + threadIdx.x;     // one float4 each
    int row = gid >> 6;
    float vf = g_valid[row] ? 1.0f : 0.0f;
    float4 hv = ((const float4*)h)[gid];
    float4 av = ((const float4*)g_agg)[gid];
    float4 o = {hv.x + av.x*vf, hv.y + av.y*vf, hv.z + av.z*vf, hv.w + av.w*vf};
    ((float4*)g_h2)[gid] = o;
}

// ============================================================================
// tcgen05 f16 GEMM: C[M,N] = A[M,K] @ Bt[N,K]^T, fp16 in, fp32 accum.
// Tile 128x256, BK=64, double-buffered.
// ============================================================================
__device__ __forceinline__ uint32_t smem_u32(const void* p) {
    uint32_t a;
    asm("{ .reg .u64 t; cvta.to.shared.u64 t, %1; cvt.u32.u64 %0, t; }" : "=r"(a) : "l"(p));
    return a;
}
__device__ __forceinline__ void mbar_wait(uint32_t mbar, uint32_t parity) {
    asm volatile(
        "{\n\t.reg .pred P1;\n\t"
        "W_%=:\n\t"
        "mbarrier.try_wait.parity.acquire.cta.shared::cta.b64 P1, [%0], %1, 0x989680;\n\t"
        "@P1 bra.uni D_%=;\n\t"
        "bra.uni W_%=;\n\t"
        "D_%=:\n\t}"
        :: "r"(mbar), "r"(parity) : "memory");
}

#if HAS_TC
__device__ __forceinline__ void mma_f16_ss(uint32_t d_tmem, uint64_t a_desc,
                                           uint64_t b_desc, uint32_t idesc, bool acc) {
    uint32_t en = acc ? 1u : 0u;
    asm volatile(
        "{\n\t.reg .pred p;\n\t"
        "setp.ne.u32 p, %5, 0;\n\t"
        "tcgen05.mma.cta_group::1.kind::f16 [%0], %1, %2, %3, {%4, %4, %4, %4}, p;\n\t"
        "}"
        :: "r"(d_tmem), "l"(a_desc), "l"(b_desc), "r"(idesc), "r"(0u), "r"(en)
        : "memory");
}
#define LDTM_X32(r, addr) \
    asm volatile( \
        "tcgen05.ld.sync.aligned.32x32b.x32.b32 " \
        "{%0, %1, %2, %3, %4, %5, %6, %7, " \
        " %8, %9, %10, %11, %12, %13, %14, %15, " \
        " %16, %17, %18, %19, %20, %21, %22, %23, " \
        " %24, %25, %26, %27, %28, %29, %30, %31}, [%32];" \
        : "=r"((r)[0]),  "=r"((r)[1]),  "=r"((r)[2]),  "=r"((r)[3]), \
          "=r"((r)[4]),  "=r"((r)[5]),  "=r"((r)[6]),  "=r"((r)[7]), \
          "=r"((r)[8]),  "=r"((r)[9]),  "=r"((r)[10]), "=r"((r)[11]), \
          "=r"((r)[12]), "=r"((r)[13]), "=r"((r)[14]), "=r"((r)[15]), \
          "=r"((r)[16]), "=r"((r)[17]), "=r"((r)[18]), "=r"((r)[19]), \
          "=r"((r)[20]), "=r"((r)[21]), "=r"((r)[22]), "=r"((r)[23]), \
          "=r"((r)[24]), "=r"((r)[25]), "=r"((r)[26]), "=r"((r)[27]), \
          "=r"((r)[28]), "=r"((r)[29]), "=r"((r)[30]), "=r"((r)[31]) \
        : "r"(addr))
#endif

static constexpr unsigned long long DESC_BASE =
    (2ull << 61) | (1ull << 46) | (64ull << 32) | (1ull << 16);  // SW128 K-major
#define MMA_IDESC ((1u<<4) | (32u<<17) | (8u<<24))   // f16, F32 acc, N=256, M=128
#define SMEM_DYN  (1024 + 98304 + 64)

// EPI 0: half store; 1: half(gelu(acc+bias)); 2: agg[eidx[m]] += acc+bias (compacted);
// EPI 3: out = (aux + acc + bias) * valid (float)
template<int EPI>
__global__ void __launch_bounds__(256)
mma_gemm(const __half* __restrict__ A, int lda,
         const __half* __restrict__ Bt,
         const float* __restrict__ bias,
         void* __restrict__ CoutV, int ldc,
         const float* __restrict__ aux,
         const int* __restrict__ eidx,
         int K, int oi) {
    extern __shared__ char dyn[];
    int tid = threadIdx.x;
    int n0 = blockIdx.x * 256;

    int m0, mEnd = 0x7fffffff;
    if (EPI == 2) {
        int start = g_Estart[oi];
        mEnd = g_Estart[oi + 1];
        m0 = start + blockIdx.y * 128;
        if (m0 >= mEnd) return;
    } else {
        m0 = blockIdx.y * 128;
    }

#if HAS_TC
    uint32_t u0 = smem_u32(dyn);
    uint32_t pad = (1024u - (u0 & 1023u)) & 1023u;
    char* base = dyn + pad;
    uint32_t ub = u0 + pad;

    uint32_t ctrl  = ub + 98304;
    uint32_t mbar0 = ctrl + 8;

    int wid = tid >> 5;
    int lane = tid & 31;

    if (tid == 0) {
        asm volatile("mbarrier.init.shared.b64 [%0], 1;" :: "r"(mbar0)     : "memory");
        asm volatile("mbarrier.init.shared.b64 [%0], 1;" :: "r"(mbar0 + 8) : "memory");
    }
    if (wid == 0) {
        asm volatile("tcgen05.alloc.cta_group::1.sync.aligned.shared::cta.b32 [%0], %1;"
                     :: "r"(ctrl), "r"(256u) : "memory");
        asm volatile("tcgen05.relinquish_alloc_permit.cta_group::1.sync.aligned;");
    }
    __syncthreads();
    uint32_t tmem;
    asm volatile("ld.shared.b32 %0, [%1];" : "=r"(tmem) : "r"(ctrl));

    const int NCH = K >> 6;
    for (int c = 0; c < NCH; c++) {
        int buf = c & 1;
        if (c >= 2) mbar_wait(mbar0 + 8u * buf, (uint32_t)(((c - 2) >> 1) & 1));
        char* sA = base + buf * 16384;
        char* sB = base + 32768 + buf * 32768;
        int k0 = c << 6;

        #pragma unroll
        for (int i = 0; i < 4; i++) {
            int idx = tid + i * 256;
            int r = idx >> 3, f4 = idx & 7;
            uint4 av = *(const uint4*)(A + (size_t)(m0 + r) * lda + k0 + f4 * 8);
            uint32_t so = (uint32_t)(r * 128 + f4 * 16);
            so ^= (so >> 3) & 0x70u;
            *(uint4*)(sA + so) = av;
        }
        #pragma unroll
        for (int i = 0; i < 8; i++) {
            int idx = tid + i * 256;
            int r = idx >> 3, f4 = idx & 7;
            uint4 bv = *(const uint4*)(Bt + (size_t)(n0 + r) * K + k0 + f4 * 8);
            uint32_t so = (uint32_t)(r * 128 + f4 * 16);
            so ^= (so >> 3) & 0x70u;
            *(uint4*)(sB + so) = bv;
        }
        asm volatile("fence.proxy.async.shared::cta;" ::: "memory");
        __syncthreads();

        if (tid == 0) {
            uint32_t aaddr = ub + (uint32_t)(buf * 16384);
            uint32_t baddr = ub + (uint32_t)(32768 + buf * 32768);
            uint64_t adesc = DESC_BASE | (uint64_t)((aaddr >> 4) & 0x3FFFu);
            uint64_t bdesc = DESC_BASE | (uint64_t)((baddr >> 4) & 0x3FFFu);
            #pragma unroll
            for (int s = 0; s < 4; s++) {
                mma_f16_ss(tmem, adesc + 2u * s, bdesc + 2u * s, MMA_IDESC,
                           !(c == 0 && s == 0));
            }
            asm volatile(
                "tcgen05.commit.cta_group::1.mbarrier::arrive::one.shared::cluster.b64 [%0];"
                :: "r"(mbar0 + 8u * buf) : "memory");
        }
    }
    mbar_wait(mbar0 + 8u * ((NCH - 2) & 1), (uint32_t)(((NCH - 2) >> 1) & 1));
    mbar_wait(mbar0 + 8u * ((NCH - 1) & 1), (uint32_t)(((NCH - 1) >> 1) & 1));
    asm volatile("tcgen05.fence::after_thread_sync;" ::: "memory");

    if (wid < 4) {
        int trow = wid * 32 + lane;
        int m = m0 + trow;
        int tgt = 0; bool do_write = true;
        if (EPI == 2) {
            do_write = (m < mEnd);
            if (do_write) tgt = eidx[m];
        }
        float vf = 1.0f;
        if (EPI == 3) vf = g_valid[m] ? 1.0f : 0.0f;

        #pragma unroll
        for (int cc = 0; cc < 256; cc += 32) {
            uint32_t r[32];
            LDTM_X32(r, tmem + (uint32_t)cc);
            asm volatile("tcgen05.wait::ld.sync.aligned;" ::: "memory");
            int col0 = n0 + cc;
            if (EPI == 0) {
                __half* Cout = (__half*)CoutV;
                #pragma unroll
                for (int j = 0; j < 32; j += 4) {
                    float o[4] = {__uint_as_float(r[j]), __uint_as_float(r[j+1]),
                                  __uint_as_float(r[j+2]), __uint_as_float(r[j+3])};
                    st4h(Cout + (size_t)m * ldc + col0 + j, o);
                }
            } else if (EPI == 1) {
                __half* Cout = (__half*)CoutV;
                #pragma unroll
                for (int j = 0; j < 32; j += 4) {
                    float o[4];
                    o[0] = gelu_exact(__uint_as_float(r[j])   + __ldg(&bias[col0+j]));
                    o[1] = gelu_exact(__uint_as_float(r[j+1]) + __ldg(&bias[col0+j+1]));
                    o[2] = gelu_exact(__uint_as_float(r[j+2]) + __ldg(&bias[col0+j+2]));
                    o[3] = gelu_exact(__uint_as_float(r[j+3]) + __ldg(&bias[col0+j+3]));
                    st4h(Cout + (size_t)m * ldc + col0 + j, o);
                }
            } else if (EPI == 2) {
                if (do_write) {
                    float* d = g_agg + (size_t)tgt * Hdim + col0;
                    #pragma unroll
                    for (int j = 0; j < 32; j += 4) {
                        float4 old = *(float4*)(d + j);
                        old.x += __uint_as_float(r[j])   + __ldg(&bias[col0+j]);
                        old.y += __uint_as_float(r[j+1]) + __ldg(&bias[col0+j+1]);
                        old.z += __uint_as_float(r[j+2]) + __ldg(&bias[col0+j+2]);
                        old.w += __uint_as_float(r[j+3]) + __ldg(&bias[col0+j+3]);
                        *(float4*)(d + j) = old;
                    }
                }
            } else {
                float* Cout = (float*)CoutV;
                const float* a2 = aux + (size_t)m * Hdim + col0;
                #pragma unroll
                for (int j = 0; j < 32; j += 4) {
                    float4 av = *(const float4*)(a2 + j);
                    float4 o;
                    o.x = (av.x + __uint_as_float(r[j])   + __ldg(&bias[col0+j]))   * vf;
                    o.y = (av.y + __uint_as_float(r[j+1]) + __ldg(&bias[col0+j+1])) * vf;
                    o.z = (av.z + __uint_as_float(r[j+2]) + __ldg(&bias[col0+j+2])) * vf;
                    o.w = (av.w + __uint_as_float(r[j+3]) + __ldg(&bias[col0+j+3])) * vf;
                    *(float4*)(Cout + (size_t)m * ldc + col0 + j) = o;
                }
            }
        }
    }
    __syncthreads();
    if (wid == 0) {
        asm volatile("tcgen05.dealloc.cta_group::1.sync.aligned.b32 %0, %1;"
                     :: "r"(tmem), "r"(256u));
    }

#else  // ---------------- SIMT fallback (compute_103 PTX pass) ----------------
    float* As = (float*)dyn;
    float* Bs = (float*)(dyn + 8192);

    int tr = tid >> 4, tc = tid & 15;
    int lrow = tid >> 1;
    int lk   = (tid & 1) * 8;

    for (int half = 0; half < 2; half++) {
        int n0h = n0 + half * 128;
        float acc[8][8] = {};
        for (int k0 = 0; k0 < K; k0 += 16) {
            #pragma unroll
            for (int e = 0; e < 8; e++) {
                As[(lk+e)*128 + lrow] = __half2float(A[(size_t)(m0 + lrow) * lda + k0 + lk + e]);
                Bs[(lk+e)*128 + lrow] = __half2float(Bt[(size_t)(n0h + lrow) * K + k0 + lk + e]);
            }
            __syncthreads();
            #pragma unroll
            for (int k = 0; k < 16; k++) {
                float a[8], b[8];
                #pragma unroll
                for (int i = 0; i < 8; i++) a[i] = As[k*128 + tr*8 + i];
                #pragma unroll
                for (int j = 0; j < 8; j++) b[j] = Bs[k*128 + tc*8 + j];
                #pragma unroll
                for (int i = 0; i < 8; i++)
                    #pragma unroll
                    for (int j = 0; j < 8; j++)
                        acc[i][j] += a[i] * b[j];
            }
            __syncthreads();
        }

        int col0 = n0h + tc * 8;
        #pragma unroll
        for (int i = 0; i < 8; i++) {
            int m = m0 + tr * 8 + i;
            if (EPI == 0) {
                __half* Cout = (__half*)CoutV;
                for (int j = 0; j < 8; j++)
                    Cout[(size_t)m * ldc + col0 + j] = __float2half(acc[i][j]);
            } else if (EPI == 1) {
                __half* Cout = (__half*)CoutV;
                for (int j = 0; j < 8; j++)
                    Cout[(size_t)m * ldc + col0 + j] =
                        __float2half(gelu_exact(acc[i][j] + bias[col0 + j]));
            } else if (EPI == 2) {
                if (m < mEnd) {
                    int tgt = eidx[m];
                    float* d = g_agg + (size_t)tgt * Hdim + col0;
                    for (int j = 0; j < 8; j++)
                        d[j] += acc[i][j] + bias[col0 + j];
                }
            } else {
                float* Cout = (float*)CoutV;
                float vf = g_valid[m] ? 1.0f : 0.0f;
                const float* a2 = aux + (size_t)m * Hdim + col0;
                for (int j = 0; j < 8; j++)
                    Cout[(size_t)m * ldc + col0 + j] =
                        (a2[j] + acc[i][j] + bias[col0 + j]) * vf;
            }
        }
        __syncthreads();
    }
#endif
}

// ---------------- launch -----------------------------------------------------
extern "C" void kernel_launch(void* const* d_in, const int* in_sizes, int n_in,
                              void* d_out, int out_size) {
    const float*         h      = (const float*)d_in[0];
    const float*         xyz    = (const float*)d_in[1];
    const unsigned char* validb = (const unsigned char*)d_in[2];
    const float*         ln_n_w = (const float*)d_in[3];
    const float*         ln_n_b = (const float*)d_in[4];
    const float*         w1     = (const float*)d_in[5];
    const float*         b1     = (const float*)d_in[6];
    const float*         w2     = (const float*)d_in[7];
    const float*         b2     = (const float*)d_in[8];
    const float*         ln_u_w = (const float*)d_in[9];
    const float*         ln_u_b = (const float*)d_in[10];
    const float*         u1     = (const float*)d_in[11];
    const float*         bu1    = (const float*)d_in[12];
    const float*         u2     = (const float*)d_in[13];
    const float*         bu2    = (const float*)d_in[14];
    float* out = (float*)d_out;

    __half *pHin, *pPQ, *pGf, *pGr, *pHu, *pT1;
    __half *pWabt, *pW2t, *pU1t, *pU2t;
    float *pH2;
    int *pEi, *pEj;
    cudaGetSymbolAddress((void**)&pHin, g_hin);
    cudaGetSymbolAddress((void**)&pPQ,  g_PQ);
    cudaGetSymbolAddress((void**)&pGf,  g_Gf);
    cudaGetSymbolAddress((void**)&pGr,  g_Gr);
    cudaGetSymbolAddress((void**)&pH2,  g_h2);
    cudaGetSymbolAddress((void**)&pHu,  g_hu);
    cudaGetSymbolAddress((void**)&pT1,  g_T1);
    cudaGetSymbolAddress((void**)&pWabt, g_wabt);
    cudaGetSymbolAddress((void**)&pW2t,  g_w2t);
    cudaGetSymbolAddress((void**)&pU1t,  g_u1t);
    cudaGetSymbolAddress((void**)&pU2t,  g_u2t);
    cudaGetSymbolAddress((void**)&pEi,   g_ei);
    cudaGetSymbolAddress((void**)&pEj,   g_ej);

    cudaFuncSetAttribute(mma_gemm<0>, cudaFuncAttributeMaxDynamicSharedMemorySize, SMEM_DYN);
    cudaFuncSetAttribute(mma_gemm<1>, cudaFuncAttributeMaxDynamicSharedMemorySize, SMEM_DYN);
    cudaFuncSetAttribute(mma_gemm<2>, cudaFuncAttributeMaxDynamicSharedMemorySize, SMEM_DYN);
    cudaFuncSetAttribute(mma_gemm<3>, cudaFuncAttributeMaxDynamicSharedMemorySize, SMEM_DYN);

    // 0: detect(0), conv(1), transpose(2), ln(3), count(4), PQ GEMM(5: ncu slot)
    detect_vmode_kernel<<<1, 32>>>(validb);
    conv_valid_kernel<<<(NC + 255) / 256, 256>>>(validb);
    transpose_all_kernel<<<917504/256, 256>>>(w1, w2, u1, u2);
    ln_kernel<<<NC/8, 256>>>(h, ln_n_w, ln_n_b, pHin, 1);
    count_kernel<<<NB, 256>>>();
    // PQ = h_in @ [W1a | W1b]  (M=NC, K=256, N=1024)
    mma_gemm<0><<<dim3(4, NC/128), 256, SMEM_DYN>>>(pHin, Hdim, pWabt,
                                                    nullptr, pPQ, HU, nullptr, nullptr,
                                                    Hdim, 0);
    scan_kernel<<<1, 256>>>();
    scatter_kernel<<<NB, 256>>>();
    edge_pre_kernel<<<4096, 128>>>(xyz, w1, b1);

    // edge GEMMs: per offset x dir (unique agg targets within each launch)
    for (int oi = 0; oi < 4; oi++) {
        mma_gemm<2><<<dim3(1, 1022), 256, SMEM_DYN>>>(pGf, H2, pW2t,
                                                      b2, nullptr, Hdim, nullptr, pEi,
                                                      H2, oi);
        mma_gemm<2><<<dim3(1, 1022), 256, SMEM_DYN>>>(pGr, H2, pW2t,
                                                      b2, nullptr, Hdim, nullptr, pEj,
                                                      H2, oi);
    }

    h2_kernel<<<NC*Hdim/4/256, 256>>>(h);
    ln_kernel<<<NC/8, 256>>>(pH2, ln_u_w, ln_u_b, pHu, 0);
    mma_gemm<1><<<dim3(4, NC/128), 256, SMEM_DYN>>>(pHu, Hdim, pU1t,
                                                    bu1, pT1, HU, nullptr, nullptr,
                                                    Hdim, 0);
    mma_gemm<3><<<dim3(1, NC/128), 256, SMEM_DYN>>>(pT1, HU, pU2t,
                                                    bu2, out, Hdim, pH2, nullptr,
                                                    HU, 0);
    (void)in_sizes; (void)n_in; (void)out_size;
}

// round 8
// speedup vs baseline: 9.0164x; 1.4415x over previous
#include <cuda_runtime.h>
#include <cuda_fp16.h>
#include <math.h>
#include <stdint.h>

#define Ndim 256
#define Cdim 512
#define Hdim 256
#define NC   (Ndim*Cdim)   // 131072
#define H2   512
#define HU   1024
#define MAXE 520448
#define NB   2033          // MAXE / 256

#if defined(__CUDA_ARCH_FEAT_SM103_ALL) || defined(__CUDA_ARCH_FEAT_SM100_ALL) || \
    (defined(__CUDA_ARCH_SPECIFIC__) && (__CUDA_ARCH_SPECIFIC__ >= 1000))
#define HAS_TC 1
#else
#define HAS_TC 0
#endif

// ---------------- scratch ----------------------------------------------------
__device__ __half g_hin[(size_t)NC*Hdim];
__device__ __half g_PQ [(size_t)NC*HU];
__device__ __half g_Gf [(size_t)MAXE*H2];
__device__ __half g_Gr [(size_t)MAXE*H2];
__device__ float  g_agg[(size_t)NC*Hdim];
__device__ float  g_h2 [(size_t)NC*Hdim];
__device__ __half g_hu [(size_t)NC*Hdim];
__device__ __half g_T1 [(size_t)NC*HU];
__device__ __half g_wabt[(size_t)HU*Hdim];
__device__ __half g_w2t [(size_t)Hdim*H2];
__device__ __half g_u1t [(size_t)HU*Hdim];
__device__ __half g_u2t [(size_t)Hdim*HU];
__device__ unsigned char g_valid[NC];
__device__ int g_vmode;
__device__ int g_ei[MAXE];
__device__ int g_ej[MAXE];
__device__ int g_bcount[2048];
__device__ int g_boffs[2048];
__device__ int g_E;
__device__ int g_Estart[5];

__device__ __forceinline__ float gelu_exact(float x) {
    return 0.5f * x * (1.0f + erff(x * 0.70710678118654752f));
}
__device__ __forceinline__ void ld4h(const __half* p, float* f) {
    uint2 u = *(const uint2*)p;
    float2 fa = __half22float2(*(__half2*)&u.x);
    float2 fb = __half22float2(*(__half2*)&u.y);
    f[0] = fa.x; f[1] = fa.y; f[2] = fb.x; f[3] = fb.y;
}
__device__ __forceinline__ void st4h(__half* p, const float* f) {
    uint2 u;
    *(__half2*)&u.x = __float22half2_rn(make_float2(f[0], f[1]));
    *(__half2*)&u.y = __float22half2_rn(make_float2(f[2], f[3]));
    *(uint2*)p = u;
}

__device__ __forceinline__ void decode_edge(int g, int& i, int& j) {
    int off, Ce, t;
    if (g < 130816)      { off = 1; Ce = 511; t = g; }
    else if (g < 261376) { off = 2; Ce = 510; t = g - 130816; }
    else if (g < 391424) { off = 4; Ce = 508; t = g - 261376; }
    else                 { off = 8; Ce = 504; t = g - 391424; }
    int n = t / Ce, c = t - n * Ce;
    i = (n << 9) + c; j = i + off;
}

// ---------------- valid dtype detection + normalization ---------------------
__global__ void detect_vmode_kernel(const unsigned char* __restrict__ v) {
    int t = threadIdx.x;           // 256 threads x 16 bytes
    int nz1 = 0, nz23 = 0;
    #pragma unroll
    for (int k = 0; k < 16; k += 4) {
        int i = t * 16 + k;
        if (v[i+1]) nz1 = 1;
        if (v[i+2] | v[i+3]) nz23 = 1;
    }
    int a1 = __syncthreads_or(nz1);
    int a23 = __syncthreads_or(nz23);
    if (t == 0) g_vmode = a1 ? 0 : (a23 ? 2 : 1);
}
__global__ void conv_valid_kernel(const unsigned char* __restrict__ v) {
    int i = blockIdx.x * 256 + threadIdx.x;
    if (i >= NC) return;
    int mode = g_vmode;
    unsigned char r;
    if (mode == 0)      r = v[i] != 0;
    else if (mode == 1) r = ((const int*)v)[i] != 0;
    else                r = ((const unsigned int*)v)[i] != 0u;
    g_valid[i] = r;
}

// ---------------- weight transposes (fp16), one launch -----------------------
__global__ void transpose_all_kernel(const float* __restrict__ w1,
                                     const float* __restrict__ w2,
                                     const float* __restrict__ u1,
                                     const float* __restrict__ u2) {
    int idx = blockIdx.x * 256 + threadIdx.x;
    if (idx < 262144) {
        int n = idx >> 8, k = idx & 255;
        float s = (n < 512) ? w1[(size_t)k * 512 + n]
                            : w1[(size_t)(k + 256) * 512 + (n - 512)];
        g_wabt[idx] = __float2half(s);
    } else if (idx < 393216) {
        int t = idx - 262144;
        int n = t >> 9, k = t & 511;
        g_w2t[t] = __float2half(w2[(size_t)k * 256 + n]);
    } else if (idx < 655360) {
        int t = idx - 393216;
        int n = t >> 8, k = t & 255;
        g_u1t[t] = __float2half(u1[(size_t)k * 1024 + n]);
    } else if (idx < 917504) {
        int t = idx - 655360;
        int n = t >> 10, k = t & 1023;
        g_u2t[t] = __float2half(u2[(size_t)k * 256 + n]);
    }
}

// ---------------- LN1 (one-pass stats), warp per row -------------------------
__global__ void ln_kernel(const float* __restrict__ x,
                          const float* __restrict__ w,
                          const float* __restrict__ b,
                          __half* __restrict__ y) {
    int warp = threadIdx.x >> 5, lane = threadIdx.x & 31;
    int row = blockIdx.x * 8 + warp;
    const float* xr = x + (size_t)row * Hdim + lane * 8;
    float4 a = *(const float4*)xr;
    float4 c = *(const float4*)(xr + 4);
    float v[8] = {a.x, a.y, a.z, a.w, c.x, c.y, c.z, c.w};
    float s1 = 0.f, s2 = 0.f;
    #pragma unroll
    for (int k = 0; k < 8; k++) { s1 += v[k]; s2 += v[k]*v[k]; }
    #pragma unroll
    for (int o = 16; o > 0; o >>= 1) {
        s1 += __shfl_xor_sync(0xffffffffu, s1, o);
        s2 += __shfl_xor_sync(0xffffffffu, s2, o);
    }
    float mu = s1 * (1.0f / Hdim);
    float inv = rsqrtf(fmaxf(s2 * (1.0f / Hdim) - mu * mu, 0.f) + 1e-5f);
    const float* wp = w + lane * 8;
    const float* bp = b + lane * 8;
    float o0[4], o1[4];
    #pragma unroll
    for (int k = 0; k < 4; k++) o0[k] = (v[k]   - mu) * inv * wp[k]   + bp[k];
    #pragma unroll
    for (int k = 0; k < 4; k++) o1[k] = (v[4+k] - mu) * inv * wp[4+k] + bp[4+k];
    __half* yr = y + (size_t)row * Hdim + lane * 8;
    st4h(yr, o0); st4h(yr + 4, o1);
    float4 z = {0.f, 0.f, 0.f, 0.f};
    float* ar = g_agg + (size_t)row * Hdim + lane * 8;
    *(float4*)ar = z; *(float4*)(ar + 4) = z;
}

// ---------------- fused h2 = h + agg*valid, then LN -> hu --------------------
__global__ void h2ln_kernel(const float* __restrict__ h,
                            const float* __restrict__ w,
                            const float* __restrict__ b) {
    int warp = threadIdx.x >> 5, lane = threadIdx.x & 31;
    int row = blockIdx.x * 8 + warp;
    float vf = g_valid[row] ? 1.0f : 0.0f;
    const float* hr = h + (size_t)row * Hdim + lane * 8;
    const float* ar = g_agg + (size_t)row * Hdim + lane * 8;
    float4 ha = *(const float4*)hr;
    float4 hc = *(const float4*)(hr + 4);
    float4 aa = *(const float4*)ar;
    float4 ac = *(const float4*)(ar + 4);
    float v[8] = {ha.x + aa.x*vf, ha.y + aa.y*vf, ha.z + aa.z*vf, ha.w + aa.w*vf,
                  hc.x + ac.x*vf, hc.y + ac.y*vf, hc.z + ac.z*vf, hc.w + ac.w*vf};
    float* h2r = g_h2 + (size_t)row * Hdim + lane * 8;
    float4 o;
    o.x = v[0]; o.y = v[1]; o.z = v[2]; o.w = v[3];
    *(float4*)h2r = o;
    o.x = v[4]; o.y = v[5]; o.z = v[6]; o.w = v[7];
    *(float4*)(h2r + 4) = o;

    float s1 = 0.f, s2 = 0.f;
    #pragma unroll
    for (int k = 0; k < 8; k++) { s1 += v[k]; s2 += v[k]*v[k]; }
    #pragma unroll
    for (int ofs = 16; ofs > 0; ofs >>= 1) {
        s1 += __shfl_xor_sync(0xffffffffu, s1, ofs);
        s2 += __shfl_xor_sync(0xffffffffu, s2, ofs);
    }
    float mu = s1 * (1.0f / Hdim);
    float inv = rsqrtf(fmaxf(s2 * (1.0f / Hdim) - mu * mu, 0.f) + 1e-5f);
    const float* wp = w + lane * 8;
    const float* bp = b + lane * 8;
    float o0[4], o1[4];
    #pragma unroll
    for (int k = 0; k < 4; k++) o0[k] = (v[k]   - mu) * inv * wp[k]   + bp[k];
    #pragma unroll
    for (int k = 0; k < 4; k++) o1[k] = (v[4+k] - mu) * inv * wp[4+k] + bp[4+k];
    __half* yr = g_hu + (size_t)row * Hdim + lane * 8;
    st4h(yr, o0); st4h(yr + 4, o1);
}

// ---------------- compaction: count / scan / scatter -------------------------
__global__ void count_kernel() {
    int g = blockIdx.x * 256 + threadIdx.x;
    int i, j; decode_edge(g, i, j);
    int pred = g_valid[i] & g_valid[j];
    unsigned bal = __ballot_sync(0xffffffffu, pred);
    __shared__ int wcnt[8];
    if ((threadIdx.x & 31) == 0) wcnt[threadIdx.x >> 5] = __popc(bal);
    __syncthreads();
    if (threadIdx.x == 0) {
        int s = 0;
        #pragma unroll
        for (int k = 0; k < 8; k++) s += wcnt[k];
        g_bcount[blockIdx.x] = s;
    }
}

__global__ void scan_kernel() {
    __shared__ int part[256];
    int t = threadIdx.x;
    int base = t * 8;
    int loc[8];
    int s = 0;
    #pragma unroll
    for (int k = 0; k < 8; k++) {
        int idx = base + k;
        int v = (idx < NB) ? g_bcount[idx] : 0;
        loc[k] = s; s += v;
    }
    part[t] = s;
    __syncthreads();
    for (int o = 1; o < 256; o <<= 1) {
        int v = part[t];
        int add = (t >= o) ? part[t - o] : 0;
        __syncthreads();
        part[t] = v + add;
        __syncthreads();
    }
    int excl = part[t] - s;
    #pragma unroll
    for (int k = 0; k < 8; k++) {
        int idx = base + k;
        if (idx < 2048) g_boffs[idx] = excl + loc[k];
    }
    __syncthreads();
    if (t == 0) {
        int total = part[255];
        g_E = total;
        g_Estart[0] = 0;
        g_Estart[1] = g_boffs[511];
        g_Estart[2] = g_boffs[1021];
        g_Estart[3] = g_boffs[1529];
        g_Estart[4] = total;
    }
}

__global__ void scatter_kernel() {
    int g = blockIdx.x * 256 + threadIdx.x;
    int lane = threadIdx.x & 31, warp = threadIdx.x >> 5;
    int i, j; decode_edge(g, i, j);
    int pred = g_valid[i] & g_valid[j];
    unsigned bal = __ballot_sync(0xffffffffu, pred);
    __shared__ int wcnt[8], wbase[8];
    if (lane == 0) wcnt[warp] = __popc(bal);
    __syncthreads();
    if (threadIdx.x == 0) {
        int s = 0;
        #pragma unroll
        for (int k = 0; k < 8; k++) { wbase[k] = s; s += wcnt[k]; }
    }
    __syncthreads();
    if (pred) {
        int pos = g_boffs[blockIdx.x] + wbase[warp]
                + __popc(bal & ((1u << lane) - 1u));
        g_ei[pos] = i; g_ej[pos] = j;
    }
}

// ---------------- edge pre-activation + GELU over compacted edges -----------
__global__ void edge_pre_kernel(const float* __restrict__ xyz,
                                const float* __restrict__ w1,
                                const float* __restrict__ b1) {
    int E = g_E;
    int f = threadIdx.x * 4;
    float4 bb = *(const float4*)(b1 + f);
    float4 w0 = *(const float4*)(w1 + (size_t)(2*Hdim + 0)*H2 + f);
    float4 w1r= *(const float4*)(w1 + (size_t)(2*Hdim + 1)*H2 + f);
    float4 w2r= *(const float4*)(w1 + (size_t)(2*Hdim + 2)*H2 + f);
    float4 w3r= *(const float4*)(w1 + (size_t)(2*Hdim + 3)*H2 + f);

    for (int m = blockIdx.x; m < E; m += gridDim.x) {
        int i = g_ei[m], j = g_ej[m];
        float dx = xyz[3*j+0] - xyz[3*i+0];
        float dy = xyz[3*j+1] - xyz[3*i+1];
        float dz = xyz[3*j+2] - xyz[3*i+2];
        float d = fmaxf(sqrtf(dx*dx + dy*dy + dz*dz), 1e-6f);
        float inv = 1.0f / d;
        float e0 = dx*inv, e1 = dy*inv, e2 = dz*inv, e3 = d;

        float pi[4], qi[4], pj[4], qj[4];
        ld4h(g_PQ + (size_t)i*HU + f,       pi);
        ld4h(g_PQ + (size_t)i*HU + 512 + f, qi);
        ld4h(g_PQ + (size_t)j*HU + f,       pj);
        ld4h(g_PQ + (size_t)j*HU + 512 + f, qj);

        float eu[4], ed[4];
        eu[0] = e0*w0.x + e1*w1r.x + e2*w2r.x;  ed[0] = e3*w3r.x + bb.x;
        eu[1] = e0*w0.y + e1*w1r.y + e2*w2r.y;  ed[1] = e3*w3r.y + bb.y;
        eu[2] = e0*w0.z + e1*w1r.z + e2*w2r.z;  ed[2] = e3*w3r.z + bb.z;
        eu[3] = e0*w0.w + e1*w1r.w + e2*w2r.w;  ed[3] = e3*w3r.w + bb.w;

        float rf[4], rr[4];
        #pragma unroll
        for (int q = 0; q < 4; q++) {
            rf[q] = gelu_exact(pi[q] + qj[q] + eu[q] + ed[q]);
            rr[q] = gelu_exact(pj[q] + qi[q] - eu[q] + ed[q]);
        }
        st4h(g_Gf + (size_t)m*H2 + f, rf);
        st4h(g_Gr + (size_t)m*H2 + f, rr);
    }
}

// ============================================================================
// tcgen05 f16 GEMM, register-prefetched double-buffered pipeline.
// Tile 128x256, BK=64.
// ============================================================================
__device__ __forceinline__ uint32_t smem_u32(const void* p) {
    uint32_t a;
    asm("{ .reg .u64 t; cvta.to.shared.u64 t, %1; cvt.u32.u64 %0, t; }" : "=r"(a) : "l"(p));
    return a;
}
__device__ __forceinline__ void mbar_wait(uint32_t mbar, uint32_t parity) {
    asm volatile(
        "{\n\t.reg .pred P1;\n\t"
        "W_%=:\n\t"
        "mbarrier.try_wait.parity.acquire.cta.shared::cta.b64 P1, [%0], %1, 0x989680;\n\t"
        "@P1 bra.uni D_%=;\n\t"
        "bra.uni W_%=;\n\t"
        "D_%=:\n\t}"
        :: "r"(mbar), "r"(parity) : "memory");
}

#if HAS_TC
__device__ __forceinline__ void mma_f16_ss(uint32_t d_tmem, uint64_t a_desc,
                                           uint64_t b_desc, uint32_t idesc, bool acc) {
    uint32_t en = acc ? 1u : 0u;
    asm volatile(
        "{\n\t.reg .pred p;\n\t"
        "setp.ne.u32 p, %5, 0;\n\t"
        "tcgen05.mma.cta_group::1.kind::f16 [%0], %1, %2, %3, {%4, %4, %4, %4}, p;\n\t"
        "}"
        :: "r"(d_tmem), "l"(a_desc), "l"(b_desc), "r"(idesc), "r"(0u), "r"(en)
        : "memory");
}
#define LDTM_X32(r, addr) \
    asm volatile( \
        "tcgen05.ld.sync.aligned.32x32b.x32.b32 " \
        "{%0, %1, %2, %3, %4, %5, %6, %7, " \
        " %8, %9, %10, %11, %12, %13, %14, %15, " \
        " %16, %17, %18, %19, %20, %21, %22, %23, " \
        " %24, %25, %26, %27, %28, %29, %30, %31}, [%32];" \
        : "=r"((r)[0]),  "=r"((r)[1]),  "=r"((r)[2]),  "=r"((r)[3]), \
          "=r"((r)[4]),  "=r"((r)[5]),  "=r"((r)[6]),  "=r"((r)[7]), \
          "=r"((r)[8]),  "=r"((r)[9]),  "=r"((r)[10]), "=r"((r)[11]), \
          "=r"((r)[12]), "=r"((r)[13]), "=r"((r)[14]), "=r"((r)[15]), \
          "=r"((r)[16]), "=r"((r)[17]), "=r"((r)[18]), "=r"((r)[19]), \
          "=r"((r)[20]), "=r"((r)[21]), "=r"((r)[22]), "=r"((r)[23]), \
          "=r"((r)[24]), "=r"((r)[25]), "=r"((r)[26]), "=r"((r)[27]), \
          "=r"((r)[28]), "=r"((r)[29]), "=r"((r)[30]), "=r"((r)[31]) \
        : "r"(addr))
#endif

static constexpr unsigned long long DESC_BASE =
    (2ull << 61) | (1ull << 46) | (64ull << 32) | (1ull << 16);
#define MMA_IDESC ((1u<<4) | (32u<<17) | (8u<<24))
#define SMEM_DYN  (1024 + 98304 + 64)

template<int EPI>
__global__ void __launch_bounds__(256, 2)
mma_gemm(const __half* __restrict__ A, int lda,
         const __half* __restrict__ Bt,
         const float* __restrict__ bias,
         void* __restrict__ CoutV, int ldc,
         const float* __restrict__ aux,
         const int* __restrict__ eidx,
         int K, int oi) {
    extern __shared__ char dyn[];
    int tid = threadIdx.x;
    int n0 = blockIdx.x * 256;

    int m0, mEnd = 0x7fffffff;
    if (EPI == 2) {
        int start = g_Estart[oi];
        mEnd = g_Estart[oi + 1];
        m0 = start + blockIdx.y * 128;
        if (m0 >= mEnd) return;
    } else {
        m0 = blockIdx.y * 128;
    }

#if HAS_TC
    uint32_t u0 = smem_u32(dyn);
    uint32_t pad = (1024u - (u0 & 1023u)) & 1023u;
    char* base = dyn + pad;
    uint32_t ub = u0 + pad;

    uint32_t ctrl  = ub + 98304;
    uint32_t mbar0 = ctrl + 8;

    int wid = tid >> 5;
    int lane = tid & 31;

    if (tid == 0) {
        asm volatile("mbarrier.init.shared.b64 [%0], 1;" :: "r"(mbar0)     : "memory");
        asm volatile("mbarrier.init.shared.b64 [%0], 1;" :: "r"(mbar0 + 8) : "memory");
    }
    if (wid == 0) {
        asm volatile("tcgen05.alloc.cta_group::1.sync.aligned.shared::cta.b32 [%0], %1;"
                     :: "r"(ctrl), "r"(256u) : "memory");
        asm volatile("tcgen05.relinquish_alloc_permit.cta_group::1.sync.aligned;");
    }
    __syncthreads();
    uint32_t tmem;
    asm volatile("ld.shared.b32 %0, [%1];" : "=r"(tmem) : "r"(ctrl));

    // per-thread fill geometry (row r, 16B column chunk f4)
    int rA = tid >> 3, f4 = tid & 7;
    uint32_t soA = (uint32_t)(rA * 128 + f4 * 16);
    soA ^= (soA >> 3) & 0x70u;                 // same swizzle every 32 rows
    const __half* Abase = A + (size_t)(m0 + rA) * lda + f4 * 8;
    const __half* Bbase = Bt + (size_t)(n0 + rA) * K + f4 * 8;
    size_t strideA = (size_t)32 * lda;         // 32 rows per fill step
    size_t strideB = (size_t)32 * K;

    uint4 ra[4], rb[8];
    const int NCH = K >> 6;

    // prefetch chunk 0
    #pragma unroll
    for (int i = 0; i < 4; i++) ra[i] = *(const uint4*)(Abase + i * strideA);
    #pragma unroll
    for (int i = 0; i < 8; i++) rb[i] = *(const uint4*)(Bbase + i * strideB);

    #pragma unroll 2
    for (int c = 0; c < NCH; c++) {
        int buf = c & 1;
        if (c >= 2) mbar_wait(mbar0 + 8u * buf, (uint32_t)(((c - 2) >> 1) & 1));
        char* sA = base + buf * 16384;
        char* sB = base + 32768 + buf * 32768;

        #pragma unroll
        for (int i = 0; i < 4; i++)
            *(uint4*)(sA + soA + (uint32_t)(i * 4096)) = ra[i];
        #pragma unroll
        for (int i = 0; i < 8; i++)
            *(uint4*)(sB + soA + (uint32_t)(i * 4096)) = rb[i];

        // prefetch next chunk while MMA(c) runs
        if (c + 1 < NCH) {
            const __half* An = Abase + (c + 1) * 64;
            const __half* Bn = Bbase + (c + 1) * 64;
            #pragma unroll
            for (int i = 0; i < 4; i++) ra[i] = *(const uint4*)(An + i * strideA);
            #pragma unroll
            for (int i = 0; i < 8; i++) rb[i] = *(const uint4*)(Bn + i * strideB);
        }

        asm volatile("fence.proxy.async.shared::cta;" ::: "memory");
        __syncthreads();

        if (tid == 0) {
            uint32_t aaddr = ub + (uint32_t)(buf * 16384);
            uint32_t baddr = ub + (uint32_t)(32768 + buf * 32768);
            uint64_t adesc = DESC_BASE | (uint64_t)((aaddr >> 4) & 0x3FFFu);
            uint64_t bdesc = DESC_BASE | (uint64_t)((baddr >> 4) & 0x3FFFu);
            #pragma unroll
            for (int s = 0; s < 4; s++) {
                mma_f16_ss(tmem, adesc + 2u * s, bdesc + 2u * s, MMA_IDESC,
                           !(c == 0 && s == 0));
            }
            asm volatile(
                "tcgen05.commit.cta_group::1.mbarrier::arrive::one.shared::cluster.b64 [%0];"
                :: "r"(mbar0 + 8u * buf) : "memory");
        }
    }
    mbar_wait(mbar0 + 8u * ((NCH - 2) & 1), (uint32_t)(((NCH - 2) >> 1) & 1));
    mbar_wait(mbar0 + 8u * ((NCH - 1) & 1), (uint32_t)(((NCH - 1) >> 1) & 1));
    asm volatile("tcgen05.fence::after_thread_sync;" ::: "memory");

    if (wid < 4) {
        int trow = wid * 32 + lane;
        int m = m0 + trow;
        int tgt = 0; bool do_write = true;
        if (EPI == 2) {
            do_write = (m < mEnd);
            if (do_write) tgt = eidx[m];
        }
        float vf = 1.0f;
        if (EPI == 3) vf = g_valid[m] ? 1.0f : 0.0f;

        #pragma unroll
        for (int cc = 0; cc < 256; cc += 32) {
            uint32_t r[32];
            LDTM_X32(r, tmem + (uint32_t)cc);
            asm volatile("tcgen05.wait::ld.sync.aligned;" ::: "memory");
            int col0 = n0 + cc;
            if (EPI == 0) {
                __half* Cout = (__half*)CoutV;
                #pragma unroll
                for (int j = 0; j < 32; j += 4) {
                    float o[4] = {__uint_as_float(r[j]), __uint_as_float(r[j+1]),
                                  __uint_as_float(r[j+2]), __uint_as_float(r[j+3])};
                    st4h(Cout + (size_t)m * ldc + col0 + j, o);
                }
            } else if (EPI == 1) {
                __half* Cout = (__half*)CoutV;
                #pragma unroll
                for (int j = 0; j < 32; j += 4) {
                    float o[4];
                    o[0] = gelu_exact(__uint_as_float(r[j])   + __ldg(&bias[col0+j]));
                    o[1] = gelu_exact(__uint_as_float(r[j+1]) + __ldg(&bias[col0+j+1]));
                    o[2] = gelu_exact(__uint_as_float(r[j+2]) + __ldg(&bias[col0+j+2]));
                    o[3] = gelu_exact(__uint_as_float(r[j+3]) + __ldg(&bias[col0+j+3]));
                    st4h(Cout + (size_t)m * ldc + col0 + j, o);
                }
            } else if (EPI == 2) {
                if (do_write) {
                    float* d = g_agg + (size_t)tgt * Hdim + col0;
                    #pragma unroll
                    for (int j = 0; j < 32; j += 4) {
                        float4 old = *(float4*)(d + j);
                        old.x += __uint_as_float(r[j])   + __ldg(&bias[col0+j]);
                        old.y += __uint_as_float(r[j+1]) + __ldg(&bias[col0+j+1]);
                        old.z += __uint_as_float(r[j+2]) + __ldg(&bias[col0+j+2]);
                        old.w += __uint_as_float(r[j+3]) + __ldg(&bias[col0+j+3]);
                        *(float4*)(d + j) = old;
                    }
                }
            } else {
                float* Cout = (float*)CoutV;
                const float* a2 = aux + (size_t)m * Hdim + col0;
                #pragma unroll
                for (int j = 0; j < 32; j += 4) {
                    float4 av = *(const float4*)(a2 + j);
                    float4 o;
                    o.x = (av.x + __uint_as_float(r[j])   + __ldg(&bias[col0+j]))   * vf;
                    o.y = (av.y + __uint_as_float(r[j+1]) + __ldg(&bias[col0+j+1])) * vf;
                    o.z = (av.z + __uint_as_float(r[j+2]) + __ldg(&bias[col0+j+2])) * vf;
                    o.w = (av.w + __uint_as_float(r[j+3]) + __ldg(&bias[col0+j+3])) * vf;
                    *(float4*)(Cout + (size_t)m * ldc + col0 + j) = o;
                }
            }
        }
    }
    __syncthreads();
    if (wid == 0) {
        asm volatile("tcgen05.dealloc.cta_group::1.sync.aligned.b32 %0, %1;"
                     :: "r"(tmem), "r"(256u));
    }

#else  // ---------------- SIMT fallback (compute_103 PTX pass) ----------------
    float* As = (float*)dyn;
    float* Bs = (float*)(dyn + 8192);

    int tr = tid >> 4, tc = tid & 15;
    int lrow = tid >> 1;
    int lk   = (tid & 1) * 8;

    for (int half = 0; half < 2; half++) {
        int n0h = n0 + half * 128;
        float acc[8][8] = {};
        for (int k0 = 0; k0 < K; k0 += 16) {
            #pragma unroll
            for (int e = 0; e < 8; e++) {
                As[(lk+e)*128 + lrow] = __half2float(A[(size_t)(m0 + lrow) * lda + k0 + lk + e]);
                Bs[(lk+e)*128 + lrow] = __half2float(Bt[(size_t)(n0h + lrow) * K + k0 + lk + e]);
            }
            __syncthreads();
            #pragma unroll
            for (int k = 0; k < 16; k++) {
                float a[8], b[8];
                #pragma unroll
                for (int i = 0; i < 8; i++) a[i] = As[k*128 + tr*8 + i];
                #pragma unroll
                for (int j = 0; j < 8; j++) b[j] = Bs[k*128 + tc*8 + j];
                #pragma unroll
                for (int i = 0; i < 8; i++)
                    #pragma unroll
                    for (int j = 0; j < 8; j++)
                        acc[i][j] += a[i] * b[j];
            }
            __syncthreads();
        }

        int col0 = n0h + tc * 8;
        #pragma unroll
        for (int i = 0; i < 8; i++) {
            int m = m0 + tr * 8 + i;
            if (EPI == 0) {
                __half* Cout = (__half*)CoutV;
                for (int j = 0; j < 8; j++)
                    Cout[(size_t)m * ldc + col0 + j] = __float2half(acc[i][j]);
            } else if (EPI == 1) {
                __half* Cout = (__half*)CoutV;
                for (int j = 0; j < 8; j++)
                    Cout[(size_t)m * ldc + col0 + j] =
                        __float2half(gelu_exact(acc[i][j] + bias[col0 + j]));
            } else if (EPI == 2) {
                if (m < mEnd) {
                    int tgt = eidx[m];
                    float* d = g_agg + (size_t)tgt * Hdim + col0;
                    for (int j = 0; j < 8; j++)
                        d[j] += acc[i][j] + bias[col0 + j];
                }
            } else {
                float* Cout = (float*)CoutV;
                float vf = g_valid[m] ? 1.0f : 0.0f;
                const float* a2 = aux + (size_t)m * Hdim + col0;
                for (int j = 0; j < 8; j++)
                    Cout[(size_t)m * ldc + col0 + j] =
                        (a2[j] + acc[i][j] + bias[col0 + j]) * vf;
            }
        }
        __syncthreads();
    }
#endif
}

// ---------------- launch -----------------------------------------------------
extern "C" void kernel_launch(void* const* d_in, const int* in_sizes, int n_in,
                              void* d_out, int out_size) {
    const float*         h      = (const float*)d_in[0];
    const float*         xyz    = (const float*)d_in[1];
    const unsigned char* validb = (const unsigned char*)d_in[2];
    const float*         ln_n_w = (const float*)d_in[3];
    const float*         ln_n_b = (const float*)d_in[4];
    const float*         w1     = (const float*)d_in[5];
    const float*         b1     = (const float*)d_in[6];
    const float*         w2     = (const float*)d_in[7];
    const float*         b2     = (const float*)d_in[8];
    const float*         ln_u_w = (const float*)d_in[9];
    const float*         ln_u_b = (const float*)d_in[10];
    const float*         u1     = (const float*)d_in[11];
    const float*         bu1    = (const float*)d_in[12];
    const float*         u2     = (const float*)d_in[13];
    const float*         bu2    = (const float*)d_in[14];
    float* out = (float*)d_out;

    __half *pHin, *pPQ, *pGf, *pGr, *pHu, *pT1;
    __half *pWabt, *pW2t, *pU1t, *pU2t;
    float *pH2;
    int *pEi, *pEj;
    cudaGetSymbolAddress((void**)&pHin, g_hin);
    cudaGetSymbolAddress((void**)&pPQ,  g_PQ);
    cudaGetSymbolAddress((void**)&pGf,  g_Gf);
    cudaGetSymbolAddress((void**)&pGr,  g_Gr);
    cudaGetSymbolAddress((void**)&pH2,  g_h2);
    cudaGetSymbolAddress((void**)&pHu,  g_hu);
    cudaGetSymbolAddress((void**)&pT1,  g_T1);
    cudaGetSymbolAddress((void**)&pWabt, g_wabt);
    cudaGetSymbolAddress((void**)&pW2t,  g_w2t);
    cudaGetSymbolAddress((void**)&pU1t,  g_u1t);
    cudaGetSymbolAddress((void**)&pU2t,  g_u2t);
    cudaGetSymbolAddress((void**)&pEi,   g_ei);
    cudaGetSymbolAddress((void**)&pEj,   g_ej);

    cudaFuncSetAttribute(mma_gemm<0>, cudaFuncAttributeMaxDynamicSharedMemorySize, SMEM_DYN);
    cudaFuncSetAttribute(mma_gemm<1>, cudaFuncAttributeMaxDynamicSharedMemorySize, SMEM_DYN);
    cudaFuncSetAttribute(mma_gemm<2>, cudaFuncAttributeMaxDynamicSharedMemorySize, SMEM_DYN);
    cudaFuncSetAttribute(mma_gemm<3>, cudaFuncAttributeMaxDynamicSharedMemorySize, SMEM_DYN);

    detect_vmode_kernel<<<1, 256>>>(validb);
    conv_valid_kernel<<<(NC + 255) / 256, 256>>>(validb);
    transpose_all_kernel<<<917504/256, 256>>>(w1, w2, u1, u2);
    ln_kernel<<<NC/8, 256>>>(h, ln_n_w, ln_n_b, pHin);
    count_kernel<<<NB, 256>>>();
    // PQ = h_in @ [W1a | W1b]  (M=NC, K=256, N=1024)
    mma_gemm<0><<<dim3(4, NC/128), 256, SMEM_DYN>>>(pHin, Hdim, pWabt,
                                                    nullptr, pPQ, HU, nullptr, nullptr,
                                                    Hdim, 0);
    scan_kernel<<<1, 256>>>();
    scatter_kernel<<<NB, 256>>>();
    edge_pre_kernel<<<4096, 128>>>(xyz, w1, b1);

    for (int oi = 0; oi < 4; oi++) {
        mma_gemm<2><<<dim3(1, 1022), 256, SMEM_DYN>>>(pGf, H2, pW2t,
                                                      b2, nullptr, Hdim, nullptr, pEi,
                                                      H2, oi);
        mma_gemm<2><<<dim3(1, 1022), 256, SMEM_DYN>>>(pGr, H2, pW2t,
                                                      b2, nullptr, Hdim, nullptr, pEj,
                                                      H2, oi);
    }

    h2ln_kernel<<<NC/8, 256>>>(h, ln_u_w, ln_u_b);
    mma_gemm<1><<<dim3(4, NC/128), 256, SMEM_DYN>>>(pHu, Hdim, pU1t,
                                                    bu1, pT1, HU, nullptr, nullptr,
                                                    Hdim, 0);
    mma_gemm<3><<<dim3(1, NC/128), 256, SMEM_DYN>>>(pT1, HU, pU2t,
                                                    bu2, out, Hdim, pH2, nullptr,
                                                    HU, 0);
    (void)in_sizes; (void)n_in; (void)out_size;
}

// round 9
// speedup vs baseline: 9.9254x; 1.1008x over previous
#include <cuda_runtime.h>
#include <cuda_fp16.h>
#include <math.h>
#include <stdint.h>

#define Ndim 256
#define Cdim 512
#define Hdim 256
#define NC   (Ndim*Cdim)   // 131072
#define H2   512
#define HU   1024
#define MAXE 520448
#define NB   2033          // MAXE / 256

#if defined(__CUDA_ARCH_FEAT_SM103_ALL) || defined(__CUDA_ARCH_FEAT_SM100_ALL) || \
    (defined(__CUDA_ARCH_SPECIFIC__) && (__CUDA_ARCH_SPECIFIC__ >= 1000))
#define HAS_TC 1
#else
#define HAS_TC 0
#endif

// ---------------- scratch ----------------------------------------------------
__device__ __half g_hin[(size_t)NC*Hdim];
__device__ __half g_PQ [(size_t)NC*HU];
__device__ __half g_Gf [(size_t)MAXE*H2];
__device__ __half g_Gr [(size_t)MAXE*H2];
__device__ __half g_Mf [(size_t)MAXE*Hdim];   // per-edge fwd messages
__device__ __half g_Mr [(size_t)MAXE*Hdim];   // per-edge rev messages
__device__ float  g_h2 [(size_t)NC*Hdim];
__device__ __half g_hu [(size_t)NC*Hdim];
__device__ __half g_T1 [(size_t)NC*HU];
__device__ __half g_wabt[(size_t)HU*Hdim];
__device__ __half g_w2t [(size_t)Hdim*H2];
__device__ __half g_u1t [(size_t)HU*Hdim];
__device__ __half g_u2t [(size_t)Hdim*HU];
__device__ unsigned char g_valid[NC];
__device__ int g_vmode;
__device__ int g_ei[MAXE];
__device__ int g_ej[MAXE];
__device__ int g_posf[4*NC];                  // edge position by (offset, target i)
__device__ int g_posr[4*NC];                  // edge position by (offset, target j)
__device__ int g_bcount[2048];
__device__ int g_boffs[2048];
__device__ int g_E;

__device__ __forceinline__ float gelu_exact(float x) {
    return 0.5f * x * (1.0f + erff(x * 0.70710678118654752f));
}
__device__ __forceinline__ void ld4h(const __half* p, float* f) {
    uint2 u = *(const uint2*)p;
    float2 fa = __half22float2(*(__half2*)&u.x);
    float2 fb = __half22float2(*(__half2*)&u.y);
    f[0] = fa.x; f[1] = fa.y; f[2] = fb.x; f[3] = fb.y;
}
__device__ __forceinline__ void st4h(__half* p, const float* f) {
    uint2 u;
    *(__half2*)&u.x = __float22half2_rn(make_float2(f[0], f[1]));
    *(__half2*)&u.y = __float22half2_rn(make_float2(f[2], f[3]));
    *(uint2*)p = u;
}

__device__ __forceinline__ void decode_edge(int g, int& i, int& j, int& oi) {
    int off, Ce, t;
    if (g < 130816)      { off = 1; Ce = 511; t = g;          oi = 0; }
    else if (g < 261376) { off = 2; Ce = 510; t = g - 130816; oi = 1; }
    else if (g < 391424) { off = 4; Ce = 508; t = g - 261376; oi = 2; }
    else                 { off = 8; Ce = 504; t = g - 391424; oi = 3; }
    int n = t / Ce, c = t - n * Ce;
    i = (n << 9) + c; j = i + off;
}

// ---------------- valid dtype detection + normalization ---------------------
__global__ void detect_vmode_kernel(const unsigned char* __restrict__ v) {
    int t = threadIdx.x;
    int nz1 = 0, nz23 = 0;
    #pragma unroll
    for (int k = 0; k < 16; k += 4) {
        int i = t * 16 + k;
        if (v[i+1]) nz1 = 1;
        if (v[i+2] | v[i+3]) nz23 = 1;
    }
    int a1 = __syncthreads_or(nz1);
    int a23 = __syncthreads_or(nz23);
    if (t == 0) g_vmode = a1 ? 0 : (a23 ? 2 : 1);
}
__global__ void conv_valid_kernel(const unsigned char* __restrict__ v) {
    int i = blockIdx.x * 256 + threadIdx.x;
    if (i >= NC) return;
    int mode = g_vmode;
    unsigned char r;
    if (mode == 0)      r = v[i] != 0;
    else if (mode == 1) r = ((const int*)v)[i] != 0;
    else                r = ((const unsigned int*)v)[i] != 0u;
    g_valid[i] = r;
}

// ---------------- clear position tables --------------------------------------
__global__ void clear_pos_kernel() {
    int i = blockIdx.x * 256 + threadIdx.x;   // 4*NC entries each array
    g_posf[i] = -1;
    g_posr[i] = -1;
}

// ---------------- weight transposes (fp16), one launch -----------------------
__global__ void transpose_all_kernel(const float* __restrict__ w1,
                                     const float* __restrict__ w2,
                                     const float* __restrict__ u1,
                                     const float* __restrict__ u2) {
    int idx = blockIdx.x * 256 + threadIdx.x;
    if (idx < 262144) {
        int n = idx >> 8, k = idx & 255;
        float s = (n < 512) ? w1[(size_t)k * 512 + n]
                            : w1[(size_t)(k + 256) * 512 + (n - 512)];
        g_wabt[idx] = __float2half(s);
    } else if (idx < 393216) {
        int t = idx - 262144;
        int n = t >> 9, k = t & 511;
        g_w2t[t] = __float2half(w2[(size_t)k * 256 + n]);
    } else if (idx < 655360) {
        int t = idx - 393216;
        int n = t >> 8, k = t & 255;
        g_u1t[t] = __float2half(u1[(size_t)k * 1024 + n]);
    } else if (idx < 917504) {
        int t = idx - 655360;
        int n = t >> 10, k = t & 1023;
        g_u2t[t] = __float2half(u2[(size_t)k * 256 + n]);
    }
}

// ---------------- LN1 (one-pass stats), warp per row -------------------------
__global__ void ln_kernel(const float* __restrict__ x,
                          const float* __restrict__ w,
                          const float* __restrict__ b,
                          __half* __restrict__ y) {
    int warp = threadIdx.x >> 5, lane = threadIdx.x & 31;
    int row = blockIdx.x * 8 + warp;
    const float* xr = x + (size_t)row * Hdim + lane * 8;
    float4 a = *(const float4*)xr;
    float4 c = *(const float4*)(xr + 4);
    float v[8] = {a.x, a.y, a.z, a.w, c.x, c.y, c.z, c.w};
    float s1 = 0.f, s2 = 0.f;
    #pragma unroll
    for (int k = 0; k < 8; k++) { s1 += v[k]; s2 += v[k]*v[k]; }
    #pragma unroll
    for (int o = 16; o > 0; o >>= 1) {
        s1 += __shfl_xor_sync(0xffffffffu, s1, o);
        s2 += __shfl_xor_sync(0xffffffffu, s2, o);
    }
    float mu = s1 * (1.0f / Hdim);
    float inv = rsqrtf(fmaxf(s2 * (1.0f / Hdim) - mu * mu, 0.f) + 1e-5f);
    const float* wp = w + lane * 8;
    const float* bp = b + lane * 8;
    float o0[4], o1[4];
    #pragma unroll
    for (int k = 0; k < 4; k++) o0[k] = (v[k]   - mu) * inv * wp[k]   + bp[k];
    #pragma unroll
    for (int k = 0; k < 4; k++) o1[k] = (v[4+k] - mu) * inv * wp[4+k] + bp[4+k];
    __half* yr = y + (size_t)row * Hdim + lane * 8;
    st4h(yr, o0); st4h(yr + 4, o1);
}

// ---------------- compaction: count / scan / scatter -------------------------
__global__ void count_kernel() {
    int g = blockIdx.x * 256 + threadIdx.x;
    int i, j, oi; decode_edge(g, i, j, oi);
    int pred = g_valid[i] & g_valid[j];
    unsigned bal = __ballot_sync(0xffffffffu, pred);
    __shared__ int wcnt[8];
    if ((threadIdx.x & 31) == 0) wcnt[threadIdx.x >> 5] = __popc(bal);
    __syncthreads();
    if (threadIdx.x == 0) {
        int s = 0;
        #pragma unroll
        for (int k = 0; k < 8; k++) s += wcnt[k];
        g_bcount[blockIdx.x] = s;
    }
}

__global__ void scan_kernel() {
    __shared__ int part[256];
    int t = threadIdx.x;
    int base = t * 8;
    int loc[8];
    int s = 0;
    #pragma unroll
    for (int k = 0; k < 8; k++) {
        int idx = base + k;
        int v = (idx < NB) ? g_bcount[idx] : 0;
        loc[k] = s; s += v;
    }
    part[t] = s;
    __syncthreads();
    for (int o = 1; o < 256; o <<= 1) {
        int v = part[t];
        int add = (t >= o) ? part[t - o] : 0;
        __syncthreads();
        part[t] = v + add;
        __syncthreads();
    }
    int excl = part[t] - s;
    #pragma unroll
    for (int k = 0; k < 8; k++) {
        int idx = base + k;
        if (idx < 2048) g_boffs[idx] = excl + loc[k];
    }
    __syncthreads();
    if (t == 0) g_E = part[255];
}

__global__ void scatter_kernel() {
    int g = blockIdx.x * 256 + threadIdx.x;
    int lane = threadIdx.x & 31, warp = threadIdx.x >> 5;
    int i, j, oi; decode_edge(g, i, j, oi);
    int pred = g_valid[i] & g_valid[j];
    unsigned bal = __ballot_sync(0xffffffffu, pred);
    __shared__ int wcnt[8], wbase[8];
    if (lane == 0) wcnt[warp] = __popc(bal);
    __syncthreads();
    if (threadIdx.x == 0) {
        int s = 0;
        #pragma unroll
        for (int k = 0; k < 8; k++) { wbase[k] = s; s += wcnt[k]; }
    }
    __syncthreads();
    if (pred) {
        int pos = g_boffs[blockIdx.x] + wbase[warp]
                + __popc(bal & ((1u << lane) - 1u));
        g_ei[pos] = i; g_ej[pos] = j;
        g_posf[oi * NC + i] = pos;
        g_posr[oi * NC + j] = pos;
    }
}

// ---------------- edge pre-activation + GELU over compacted edges -----------
__global__ void edge_pre_kernel(const float* __restrict__ xyz,
                                const float* __restrict__ w1,
                                const float* __restrict__ b1) {
    int E = g_E;
    int f = threadIdx.x * 4;
    float4 bb = *(const float4*)(b1 + f);
    float4 w0 = *(const float4*)(w1 + (size_t)(2*Hdim + 0)*H2 + f);
    float4 w1r= *(const float4*)(w1 + (size_t)(2*Hdim + 1)*H2 + f);
    float4 w2r= *(const float4*)(w1 + (size_t)(2*Hdim + 2)*H2 + f);
    float4 w3r= *(const float4*)(w1 + (size_t)(2*Hdim + 3)*H2 + f);

    for (int m = blockIdx.x; m < E; m += gridDim.x) {
        int i = g_ei[m], j = g_ej[m];
        float dx = xyz[3*j+0] - xyz[3*i+0];
        float dy = xyz[3*j+1] - xyz[3*i+1];
        float dz = xyz[3*j+2] - xyz[3*i+2];
        float d = fmaxf(sqrtf(dx*dx + dy*dy + dz*dz), 1e-6f);
        float inv = 1.0f / d;
        float e0 = dx*inv, e1 = dy*inv, e2 = dz*inv, e3 = d;

        float pi[4], qi[4], pj[4], qj[4];
        ld4h(g_PQ + (size_t)i*HU + f,       pi);
        ld4h(g_PQ + (size_t)i*HU + 512 + f, qi);
        ld4h(g_PQ + (size_t)j*HU + f,       pj);
        ld4h(g_PQ + (size_t)j*HU + 512 + f, qj);

        float eu[4], ed[4];
        eu[0] = e0*w0.x + e1*w1r.x + e2*w2r.x;  ed[0] = e3*w3r.x + bb.x;
        eu[1] = e0*w0.y + e1*w1r.y + e2*w2r.y;  ed[1] = e3*w3r.y + bb.y;
        eu[2] = e0*w0.z + e1*w1r.z + e2*w2r.z;  ed[2] = e3*w3r.z + bb.z;
        eu[3] = e0*w0.w + e1*w1r.w + e2*w2r.w;  ed[3] = e3*w3r.w + bb.w;

        float rf[4], rr[4];
        #pragma unroll
        for (int q = 0; q < 4; q++) {
            rf[q] = gelu_exact(pi[q] + qj[q] + eu[q] + ed[q]);
            rr[q] = gelu_exact(pj[q] + qi[q] - eu[q] + ed[q]);
        }
        st4h(g_Gf + (size_t)m*H2 + f, rf);
        st4h(g_Gr + (size_t)m*H2 + f, rr);
    }
}

// ---------------- gather messages + h2 residual + LN -> hu -------------------
// warp per node: acc = sum of incident messages (<=8) + cnt*b2;
// h2 = h + acc; hu = LN(h2).
__global__ void gather_ln_kernel(const float* __restrict__ h,
                                 const float* __restrict__ b2,
                                 const float* __restrict__ w,
                                 const float* __restrict__ b) {
    int warp = threadIdx.x >> 5, lane = threadIdx.x & 31;
    int row = blockIdx.x * 8 + warp;

    int p = -1;
    if (lane < 4)      p = g_posf[lane * NC + row];
    else if (lane < 8) p = g_posr[(lane - 4) * NC + row];

    float acc[8] = {};
    int cnt = 0;
    #pragma unroll
    for (int s = 0; s < 8; s++) {
        int ps = __shfl_sync(0xffffffffu, p, s);
        if (ps >= 0) {
            cnt++;
            const __half* Mrow = (s < 4 ? g_Mf : g_Mr) + (size_t)ps * Hdim + lane * 8;
            uint4 u = *(const uint4*)Mrow;
            float2 f0 = __half22float2(*(__half2*)&u.x);
            float2 f1 = __half22float2(*(__half2*)&u.y);
            float2 f2 = __half22float2(*(__half2*)&u.z);
            float2 f3 = __half22float2(*(__half2*)&u.w);
            acc[0] += f0.x; acc[1] += f0.y; acc[2] += f1.x; acc[3] += f1.y;
            acc[4] += f2.x; acc[5] += f2.y; acc[6] += f3.x; acc[7] += f3.y;
        }
    }
    float cf = (float)cnt;
    const float* hr = h + (size_t)row * Hdim + lane * 8;
    const float* b2p = b2 + lane * 8;
    float4 ha = *(const float4*)hr;
    float4 hc = *(const float4*)(hr + 4);
    float hv[8] = {ha.x, ha.y, ha.z, ha.w, hc.x, hc.y, hc.z, hc.w};
    float v[8];
    #pragma unroll
    for (int k = 0; k < 8; k++) v[k] = hv[k] + acc[k] + cf * b2p[k];

    float* h2r = g_h2 + (size_t)row * Hdim + lane * 8;
    float4 o;
    o.x = v[0]; o.y = v[1]; o.z = v[2]; o.w = v[3];
    *(float4*)h2r = o;
    o.x = v[4]; o.y = v[5]; o.z = v[6]; o.w = v[7];
    *(float4*)(h2r + 4) = o;

    float s1 = 0.f, s2 = 0.f;
    #pragma unroll
    for (int k = 0; k < 8; k++) { s1 += v[k]; s2 += v[k]*v[k]; }
    #pragma unroll
    for (int ofs = 16; ofs > 0; ofs >>= 1) {
        s1 += __shfl_xor_sync(0xffffffffu, s1, ofs);
        s2 += __shfl_xor_sync(0xffffffffu, s2, ofs);
    }
    float mu = s1 * (1.0f / Hdim);
    float inv = rsqrtf(fmaxf(s2 * (1.0f / Hdim) - mu * mu, 0.f) + 1e-5f);
    const float* wp = w + lane * 8;
    const float* bp = b + lane * 8;
    float o0[4], o1[4];
    #pragma unroll
    for (int k = 0; k < 4; k++) o0[k] = (v[k]   - mu) * inv * wp[k]   + bp[k];
    #pragma unroll
    for (int k = 0; k < 4; k++) o1[k] = (v[4+k] - mu) * inv * wp[4+k] + bp[4+k];
    __half* yr = g_hu + (size_t)row * Hdim + lane * 8;
    st4h(yr, o0); st4h(yr + 4, o1);
}

// ============================================================================
// tcgen05 f16 GEMM, register-prefetched double-buffered pipeline.
// Tile 128x256, BK=64.
// EPI 0: half store; 1: half(gelu(acc+bias)); 3: (aux+acc+bias)*valid float;
// EPI 4: half store, row-bounded by g_E (edge message GEMM).
// ============================================================================
__device__ __forceinline__ uint32_t smem_u32(const void* p) {
    uint32_t a;
    asm("{ .reg .u64 t; cvta.to.shared.u64 t, %1; cvt.u32.u64 %0, t; }" : "=r"(a) : "l"(p));
    return a;
}
__device__ __forceinline__ void mbar_wait(uint32_t mbar, uint32_t parity) {
    asm volatile(
        "{\n\t.reg .pred P1;\n\t"
        "W_%=:\n\t"
        "mbarrier.try_wait.parity.acquire.cta.shared::cta.b64 P1, [%0], %1, 0x989680;\n\t"
        "@P1 bra.uni D_%=;\n\t"
        "bra.uni W_%=;\n\t"
        "D_%=:\n\t}"
        :: "r"(mbar), "r"(parity) : "memory");
}

#if HAS_TC
__device__ __forceinline__ void mma_f16_ss(uint32_t d_tmem, uint64_t a_desc,
                                           uint64_t b_desc, uint32_t idesc, bool acc) {
    uint32_t en = acc ? 1u : 0u;
    asm volatile(
        "{\n\t.reg .pred p;\n\t"
        "setp.ne.u32 p, %5, 0;\n\t"
        "tcgen05.mma.cta_group::1.kind::f16 [%0], %1, %2, %3, {%4, %4, %4, %4}, p;\n\t"
        "}"
        :: "r"(d_tmem), "l"(a_desc), "l"(b_desc), "r"(idesc), "r"(0u), "r"(en)
        : "memory");
}
#define LDTM_X32(r, addr) \
    asm volatile( \
        "tcgen05.ld.sync.aligned.32x32b.x32.b32 " \
        "{%0, %1, %2, %3, %4, %5, %6, %7, " \
        " %8, %9, %10, %11, %12, %13, %14, %15, " \
        " %16, %17, %18, %19, %20, %21, %22, %23, " \
        " %24, %25, %26, %27, %28, %29, %30, %31}, [%32];" \
        : "=r"((r)[0]),  "=r"((r)[1]),  "=r"((r)[2]),  "=r"((r)[3]), \
          "=r"((r)[4]),  "=r"((r)[5]),  "=r"((r)[6]),  "=r"((r)[7]), \
          "=r"((r)[8]),  "=r"((r)[9]),  "=r"((r)[10]), "=r"((r)[11]), \
          "=r"((r)[12]), "=r"((r)[13]), "=r"((r)[14]), "=r"((r)[15]), \
          "=r"((r)[16]), "=r"((r)[17]), "=r"((r)[18]), "=r"((r)[19]), \
          "=r"((r)[20]), "=r"((r)[21]), "=r"((r)[22]), "=r"((r)[23]), \
          "=r"((r)[24]), "=r"((r)[25]), "=r"((r)[26]), "=r"((r)[27]), \
          "=r"((r)[28]), "=r"((r)[29]), "=r"((r)[30]), "=r"((r)[31]) \
        : "r"(addr))
#endif

static constexpr unsigned long long DESC_BASE =
    (2ull << 61) | (1ull << 46) | (64ull << 32) | (1ull << 16);
#define MMA_IDESC ((1u<<4) | (32u<<17) | (8u<<24))
#define SMEM_DYN  (1024 + 98304 + 64)

template<int EPI>
__global__ void __launch_bounds__(256, 2)
mma_gemm(const __half* __restrict__ A, int lda,
         const __half* __restrict__ Bt,
         const float* __restrict__ bias,
         void* __restrict__ CoutV, int ldc,
         const float* __restrict__ aux,
         int K) {
    extern __shared__ char dyn[];
    int tid = threadIdx.x;
    int n0 = blockIdx.x * 256;
    int m0 = blockIdx.y * 128;
    if (EPI == 4 && m0 >= g_E) return;

#if HAS_TC
    uint32_t u0 = smem_u32(dyn);
    uint32_t pad = (1024u - (u0 & 1023u)) & 1023u;
    char* base = dyn + pad;
    uint32_t ub = u0 + pad;

    uint32_t ctrl  = ub + 98304;
    uint32_t mbar0 = ctrl + 8;

    int wid = tid >> 5;
    int lane = tid & 31;

    if (tid == 0) {
        asm volatile("mbarrier.init.shared.b64 [%0], 1;" :: "r"(mbar0)     : "memory");
        asm volatile("mbarrier.init.shared.b64 [%0], 1;" :: "r"(mbar0 + 8) : "memory");
    }
    if (wid == 0) {
        asm volatile("tcgen05.alloc.cta_group::1.sync.aligned.shared::cta.b32 [%0], %1;"
                     :: "r"(ctrl), "r"(256u) : "memory");
        asm volatile("tcgen05.relinquish_alloc_permit.cta_group::1.sync.aligned;");
    }
    __syncthreads();
    uint32_t tmem;
    asm volatile("ld.shared.b32 %0, [%1];" : "=r"(tmem) : "r"(ctrl));

    int rA = tid >> 3, f4 = tid & 7;
    uint32_t soA = (uint32_t)(rA * 128 + f4 * 16);
    soA ^= (soA >> 3) & 0x70u;
    const __half* Abase = A + (size_t)(m0 + rA) * lda + f4 * 8;
    const __half* Bbase = Bt + (size_t)(n0 + rA) * K + f4 * 8;
    size_t strideA = (size_t)32 * lda;
    size_t strideB = (size_t)32 * K;

    uint4 ra[4], rb[8];
    const int NCH = K >> 6;

    #pragma unroll
    for (int i = 0; i < 4; i++) ra[i] = *(const uint4*)(Abase + i * strideA);
    #pragma unroll
    for (int i = 0; i < 8; i++) rb[i] = *(const uint4*)(Bbase + i * strideB);

    #pragma unroll 2
    for (int c = 0; c < NCH; c++) {
        int buf = c & 1;
        if (c >= 2) mbar_wait(mbar0 + 8u * buf, (uint32_t)(((c - 2) >> 1) & 1));
        char* sA = base + buf * 16384;
        char* sB = base + 32768 + buf * 32768;

        #pragma unroll
        for (int i = 0; i < 4; i++)
            *(uint4*)(sA + soA + (uint32_t)(i * 4096)) = ra[i];
        #pragma unroll
        for (int i = 0; i < 8; i++)
            *(uint4*)(sB + soA + (uint32_t)(i * 4096)) = rb[i];

        if (c + 1 < NCH) {
            const __half* An = Abase + (c + 1) * 64;
            const __half* Bn = Bbase + (c + 1) * 64;
            #pragma unroll
            for (int i = 0; i < 4; i++) ra[i] = *(const uint4*)(An + i * strideA);
            #pragma unroll
            for (int i = 0; i < 8; i++) rb[i] = *(const uint4*)(Bn + i * strideB);
        }

        asm volatile("fence.proxy.async.shared::cta;" ::: "memory");
        __syncthreads();

        if (tid == 0) {
            uint32_t aaddr = ub + (uint32_t)(buf * 16384);
            uint32_t baddr = ub + (uint32_t)(32768 + buf * 32768);
            uint64_t adesc = DESC_BASE | (uint64_t)((aaddr >> 4) & 0x3FFFu);
            uint64_t bdesc = DESC_BASE | (uint64_t)((baddr >> 4) & 0x3FFFu);
            #pragma unroll
            for (int s = 0; s < 4; s++) {
                mma_f16_ss(tmem, adesc + 2u * s, bdesc + 2u * s, MMA_IDESC,
                           !(c == 0 && s == 0));
            }
            asm volatile(
                "tcgen05.commit.cta_group::1.mbarrier::arrive::one.shared::cluster.b64 [%0];"
                :: "r"(mbar0 + 8u * buf) : "memory");
        }
    }
    mbar_wait(mbar0 + 8u * ((NCH - 2) & 1), (uint32_t)(((NCH - 2) >> 1) & 1));
    mbar_wait(mbar0 + 8u * ((NCH - 1) & 1), (uint32_t)(((NCH - 1) >> 1) & 1));
    asm volatile("tcgen05.fence::after_thread_sync;" ::: "memory");

    if (wid < 4) {
        int trow = wid * 32 + lane;
        int m = m0 + trow;
        float vf = 1.0f;
        if (EPI == 3) vf = g_valid[m] ? 1.0f : 0.0f;

        #pragma unroll
        for (int cc = 0; cc < 256; cc += 32) {
            uint32_t r[32];
            LDTM_X32(r, tmem + (uint32_t)cc);
            asm volatile("tcgen05.wait::ld.sync.aligned;" ::: "memory");
            int col0 = n0 + cc;
            if (EPI == 0 || EPI == 4) {
                __half* Cout = (__half*)CoutV;
                #pragma unroll
                for (int j = 0; j < 32; j += 4) {
                    float o[4] = {__uint_as_float(r[j]), __uint_as_float(r[j+1]),
                                  __uint_as_float(r[j+2]), __uint_as_float(r[j+3])};
                    st4h(Cout + (size_t)m * ldc + col0 + j, o);
                }
            } else if (EPI == 1) {
                __half* Cout = (__half*)CoutV;
                #pragma unroll
                for (int j = 0; j < 32; j += 4) {
                    float o[4];
                    o[0] = gelu_exact(__uint_as_float(r[j])   + __ldg(&bias[col0+j]));
                    o[1] = gelu_exact(__uint_as_float(r[j+1]) + __ldg(&bias[col0+j+1]));
                    o[2] = gelu_exact(__uint_as_float(r[j+2]) + __ldg(&bias[col0+j+2]));
                    o[3] = gelu_exact(__uint_as_float(r[j+3]) + __ldg(&bias[col0+j+3]));
                    st4h(Cout + (size_t)m * ldc + col0 + j, o);
                }
            } else {
                float* Cout = (float*)CoutV;
                const float* a2 = aux + (size_t)m * Hdim + col0;
                #pragma unroll
                for (int j = 0; j < 32; j += 4) {
                    float4 av = *(const float4*)(a2 + j);
                    float4 o;
                    o.x = (av.x + __uint_as_float(r[j])   + __ldg(&bias[col0+j]))   * vf;
                    o.y = (av.y + __uint_as_float(r[j+1]) + __ldg(&bias[col0+j+1])) * vf;
                    o.z = (av.z + __uint_as_float(r[j+2]) + __ldg(&bias[col0+j+2])) * vf;
                    o.w = (av.w + __uint_as_float(r[j+3]) + __ldg(&bias[col0+j+3])) * vf;
                    *(float4*)(Cout + (size_t)m * ldc + col0 + j) = o;
                }
            }
        }
    }
    __syncthreads();
    if (wid == 0) {
        asm volatile("tcgen05.dealloc.cta_group::1.sync.aligned.b32 %0, %1;"
                     :: "r"(tmem), "r"(256u));
    }

#else  // ---------------- SIMT fallback (compute_103 PTX pass) ----------------
    float* As = (float*)dyn;
    float* Bs = (float*)(dyn + 8192);

    int tr = tid >> 4, tc = tid & 15;
    int lrow = tid >> 1;
    int lk   = (tid & 1) * 8;

    for (int half = 0; half < 2; half++) {
        int n0h = n0 + half * 128;
        float acc[8][8] = {};
        for (int k0 = 0; k0 < K; k0 += 16) {
            #pragma unroll
            for (int e = 0; e < 8; e++) {
                As[(lk+e)*128 + lrow] = __half2float(A[(size_t)(m0 + lrow) * lda + k0 + lk + e]);
                Bs[(lk+e)*128 + lrow] = __half2float(Bt[(size_t)(n0h + lrow) * K + k0 + lk + e]);
            }
            __syncthreads();
            #pragma unroll
            for (int k = 0; k < 16; k++) {
                float a[8], b[8];
                #pragma unroll
                for (int i = 0; i < 8; i++) a[i] = As[k*128 + tr*8 + i];
                #pragma unroll
                for (int j = 0; j < 8; j++) b[j] = Bs[k*128 + tc*8 + j];
                #pragma unroll
                for (int i = 0; i < 8; i++)
                    #pragma unroll
                    for (int j = 0; j < 8; j++)
                        acc[i][j] += a[i] * b[j];
            }
            __syncthreads();
        }

        int col0 = n0h + tc * 8;
        #pragma unroll
        for (int i = 0; i < 8; i++) {
            int m = m0 + tr * 8 + i;
            if (EPI == 0 || EPI == 4) {
                __half* Cout = (__half*)CoutV;
                for (int j = 0; j < 8; j++)
                    Cout[(size_t)m * ldc + col0 + j] = __float2half(acc[i][j]);
            } else if (EPI == 1) {
                __half* Cout = (__half*)CoutV;
                for (int j = 0; j < 8; j++)
                    Cout[(size_t)m * ldc + col0 + j] =
                        __float2half(gelu_exact(acc[i][j] + bias[col0 + j]));
            } else {
                float* Cout = (float*)CoutV;
                float vf = g_valid[m] ? 1.0f : 0.0f;
                const float* a2 = aux + (size_t)m * Hdim + col0;
                for (int j = 0; j < 8; j++)
                    Cout[(size_t)m * ldc + col0 + j] =
                        (a2[j] + acc[i][j] + bias[col0 + j]) * vf;
            }
        }
        __syncthreads();
    }
#endif
}

// ---------------- launch -----------------------------------------------------
extern "C" void kernel_launch(void* const* d_in, const int* in_sizes, int n_in,
                              void* d_out, int out_size) {
    const float*         h      = (const float*)d_in[0];
    const float*         xyz    = (const float*)d_in[1];
    const unsigned char* validb = (const unsigned char*)d_in[2];
    const float*         ln_n_w = (const float*)d_in[3];
    const float*         ln_n_b = (const float*)d_in[4];
    const float*         w1     = (const float*)d_in[5];
    const float*         b1     = (const float*)d_in[6];
    const float*         w2     = (const float*)d_in[7];
    const float*         b2     = (const float*)d_in[8];
    const float*         ln_u_w = (const float*)d_in[9];
    const float*         ln_u_b = (const float*)d_in[10];
    const float*         u1     = (const float*)d_in[11];
    const float*         bu1    = (const float*)d_in[12];
    const float*         u2     = (const float*)d_in[13];
    const float*         bu2    = (const float*)d_in[14];
    float* out = (float*)d_out;

    __half *pHin, *pPQ, *pGf, *pGr, *pMf, *pMr, *pHu, *pT1;
    __half *pWabt, *pW2t, *pU1t, *pU2t;
    float *pH2;
    cudaGetSymbolAddress((void**)&pHin, g_hin);
    cudaGetSymbolAddress((void**)&pPQ,  g_PQ);
    cudaGetSymbolAddress((void**)&pGf,  g_Gf);
    cudaGetSymbolAddress((void**)&pGr,  g_Gr);
    cudaGetSymbolAddress((void**)&pMf,  g_Mf);
    cudaGetSymbolAddress((void**)&pMr,  g_Mr);
    cudaGetSymbolAddress((void**)&pH2,  g_h2);
    cudaGetSymbolAddress((void**)&pHu,  g_hu);
    cudaGetSymbolAddress((void**)&pT1,  g_T1);
    cudaGetSymbolAddress((void**)&pWabt, g_wabt);
    cudaGetSymbolAddress((void**)&pW2t,  g_w2t);
    cudaGetSymbolAddress((void**)&pU1t,  g_u1t);
    cudaGetSymbolAddress((void**)&pU2t,  g_u2t);

    cudaFuncSetAttribute(mma_gemm<0>, cudaFuncAttributeMaxDynamicSharedMemorySize, SMEM_DYN);
    cudaFuncSetAttribute(mma_gemm<1>, cudaFuncAttributeMaxDynamicSharedMemorySize, SMEM_DYN);
    cudaFuncSetAttribute(mma_gemm<3>, cudaFuncAttributeMaxDynamicSharedMemorySize, SMEM_DYN);
    cudaFuncSetAttribute(mma_gemm<4>, cudaFuncAttributeMaxDynamicSharedMemorySize, SMEM_DYN);

    detect_vmode_kernel<<<1, 256>>>(validb);
    conv_valid_kernel<<<(NC + 255) / 256, 256>>>(validb);
    clear_pos_kernel<<<4*NC/256, 256>>>();
    transpose_all_kernel<<<917504/256, 256>>>(w1, w2, u1, u2);
    ln_kernel<<<NC/8, 256>>>(h, ln_n_w, ln_n_b, pHin);
    count_kernel<<<NB, 256>>>();
    // PQ = h_in @ [W1a | W1b]  (M=NC, K=256, N=1024)
    mma_gemm<0><<<dim3(4, NC/128), 256, SMEM_DYN>>>(pHin, Hdim, pWabt,
                                                    nullptr, pPQ, HU, nullptr, Hdim);
    scan_kernel<<<1, 256>>>();
    scatter_kernel<<<NB, 256>>>();
    edge_pre_kernel<<<4096, 128>>>(xyz, w1, b1);

    // edge message GEMMs: Mf = Gf @ w2, Mr = Gr @ w2 (rows bounded by g_E)
    mma_gemm<4><<<dim3(1, MAXE/128), 256, SMEM_DYN>>>(pGf, H2, pW2t,
                                                      nullptr, pMf, Hdim, nullptr, H2);
    mma_gemm<4><<<dim3(1, MAXE/128), 256, SMEM_DYN>>>(pGr, H2, pW2t,
                                                      nullptr, pMr, Hdim, nullptr, H2);

    // gather messages -> h2 -> LN -> hu
    gather_ln_kernel<<<NC/8, 256>>>(h, b2, ln_u_w, ln_u_b);

    mma_gemm<1><<<dim3(4, NC/128), 256, SMEM_DYN>>>(pHu, Hdim, pU1t,
                                                    bu1, pT1, HU, nullptr, Hdim);
    mma_gemm<3><<<dim3(1, NC/128), 256, SMEM_DYN>>>(pT1, HU, pU2t,
                                                    bu2, out, Hdim, pH2, HU);
    (void)in_sizes; (void)n_in; (void)out_size;
}

// round 10
// speedup vs baseline: 10.2844x; 1.0362x over previous
#include <cuda_runtime.h>
#include <cuda_fp16.h>
#include <math.h>
#include <stdint.h>

#define Ndim 256
#define Cdim 512
#define Hdim 256
#define NC   (Ndim*Cdim)   // 131072
#define H2   512
#define HU   1024
#define MAXE 520448
#define NB   2033          // MAXE / 256

#if defined(__CUDA_ARCH_FEAT_SM103_ALL) || defined(__CUDA_ARCH_FEAT_SM100_ALL) || \
    (defined(__CUDA_ARCH_SPECIFIC__) && (__CUDA_ARCH_SPECIFIC__ >= 1000))
#define HAS_TC 1
#else
#define HAS_TC 0
#endif

// ---------------- scratch ----------------------------------------------------
__device__ __half g_hin[(size_t)NC*Hdim];
__device__ __half g_PQ [(size_t)NC*HU];
__device__ __half g_Mf [(size_t)MAXE*Hdim];   // per-edge fwd messages
__device__ __half g_Mr [(size_t)MAXE*Hdim];   // per-edge rev messages
__device__ float  g_h2 [(size_t)NC*Hdim];
__device__ __half g_hu [(size_t)NC*Hdim];
__device__ __half g_T1 [(size_t)NC*HU];
__device__ __half g_wabt[(size_t)HU*Hdim];
__device__ __half g_w2t [(size_t)Hdim*H2];
__device__ __half g_u1t [(size_t)HU*Hdim];
__device__ __half g_u2t [(size_t)Hdim*HU];
__device__ unsigned char g_valid[NC];
__device__ int g_vmode;
__device__ int g_ei[MAXE];
__device__ int g_ej[MAXE];
__device__ int g_posf[4*NC];
__device__ int g_posr[4*NC];
__device__ int g_bcount[2048];
__device__ int g_boffs[2048];
__device__ int g_E;

__device__ __forceinline__ float gelu_exact(float x) {
    return 0.5f * x * (1.0f + erff(x * 0.70710678118654752f));
}
__device__ __forceinline__ void st4h(__half* p, const float* f) {
    uint2 u;
    *(__half2*)&u.x = __float22half2_rn(make_float2(f[0], f[1]));
    *(__half2*)&u.y = __float22half2_rn(make_float2(f[2], f[3]));
    *(uint2*)p = u;
}
__device__ __forceinline__ void ld8h(const __half* p, float* f) {
    uint4 u = *(const uint4*)p;
    float2 a = __half22float2(*(__half2*)&u.x);
    float2 b = __half22float2(*(__half2*)&u.y);
    float2 c = __half22float2(*(__half2*)&u.z);
    float2 d = __half22float2(*(__half2*)&u.w);
    f[0]=a.x; f[1]=a.y; f[2]=b.x; f[3]=b.y; f[4]=c.x; f[5]=c.y; f[6]=d.x; f[7]=d.y;
}
__device__ __forceinline__ uint4 pack8h(const float* f) {
    uint4 u;
    *(__half2*)&u.x = __float22half2_rn(make_float2(f[0], f[1]));
    *(__half2*)&u.y = __float22half2_rn(make_float2(f[2], f[3]));
    *(__half2*)&u.z = __float22half2_rn(make_float2(f[4], f[5]));
    *(__half2*)&u.w = __float22half2_rn(make_float2(f[6], f[7]));
    return u;
}

__device__ __forceinline__ void decode_edge(int g, int& i, int& j, int& oi) {
    int off, Ce, t;
    if (g < 130816)      { off = 1; Ce = 511; t = g;          oi = 0; }
    else if (g < 261376) { off = 2; Ce = 510; t = g - 130816; oi = 1; }
    else if (g < 391424) { off = 4; Ce = 508; t = g - 261376; oi = 2; }
    else                 { off = 8; Ce = 504; t = g - 391424; oi = 3; }
    int n = t / Ce, c = t - n * Ce;
    i = (n << 9) + c; j = i + off;
}

// ---------------- valid dtype detection + normalization ---------------------
__global__ void detect_vmode_kernel(const unsigned char* __restrict__ v) {
    int t = threadIdx.x;
    int nz1 = 0, nz23 = 0;
    #pragma unroll
    for (int k = 0; k < 16; k += 4) {
        int i = t * 16 + k;
        if (v[i+1]) nz1 = 1;
        if (v[i+2] | v[i+3]) nz23 = 1;
    }
    int a1 = __syncthreads_or(nz1);
    int a23 = __syncthreads_or(nz23);
    if (t == 0) g_vmode = a1 ? 0 : (a23 ? 2 : 1);
}
__global__ void conv_valid_kernel(const unsigned char* __restrict__ v) {
    int i = blockIdx.x * 256 + threadIdx.x;
    if (i >= NC) return;
    int mode = g_vmode;
    unsigned char r;
    if (mode == 0)      r = v[i] != 0;
    else if (mode == 1) r = ((const int*)v)[i] != 0;
    else                r = ((const unsigned int*)v)[i] != 0u;
    g_valid[i] = r;
}

__global__ void clear_pos_kernel() {
    int i = blockIdx.x * 256 + threadIdx.x;
    g_posf[i] = -1;
    g_posr[i] = -1;
}

// ---------------- weight transposes (fp16), one launch -----------------------
__global__ void transpose_all_kernel(const float* __restrict__ w1,
                                     const float* __restrict__ w2,
                                     const float* __restrict__ u1,
                                     const float* __restrict__ u2) {
    int idx = blockIdx.x * 256 + threadIdx.x;
    if (idx < 262144) {
        int n = idx >> 8, k = idx & 255;
        float s = (n < 512) ? w1[(size_t)k * 512 + n]
                            : w1[(size_t)(k + 256) * 512 + (n - 512)];
        g_wabt[idx] = __float2half(s);
    } else if (idx < 393216) {
        int t = idx - 262144;
        int n = t >> 9, k = t & 511;
        g_w2t[t] = __float2half(w2[(size_t)k * 256 + n]);
    } else if (idx < 655360) {
        int t = idx - 393216;
        int n = t >> 8, k = t & 255;
        g_u1t[t] = __float2half(u1[(size_t)k * 1024 + n]);
    } else if (idx < 917504) {
        int t = idx - 655360;
        int n = t >> 10, k = t & 1023;
        g_u2t[t] = __float2half(u2[(size_t)k * 256 + n]);
    }
}

// ---------------- LN1 (one-pass stats), warp per row -------------------------
__global__ void ln_kernel(const float* __restrict__ x,
                          const float* __restrict__ w,
                          const float* __restrict__ b,
                          __half* __restrict__ y) {
    int warp = threadIdx.x >> 5, lane = threadIdx.x & 31;
    int row = blockIdx.x * 8 + warp;
    const float* xr = x + (size_t)row * Hdim + lane * 8;
    float4 a = *(const float4*)xr;
    float4 c = *(const float4*)(xr + 4);
    float v[8] = {a.x, a.y, a.z, a.w, c.x, c.y, c.z, c.w};
    float s1 = 0.f, s2 = 0.f;
    #pragma unroll
    for (int k = 0; k < 8; k++) { s1 += v[k]; s2 += v[k]*v[k]; }
    #pragma unroll
    for (int o = 16; o > 0; o >>= 1) {
        s1 += __shfl_xor_sync(0xffffffffu, s1, o);
        s2 += __shfl_xor_sync(0xffffffffu, s2, o);
    }
    float mu = s1 * (1.0f / Hdim);
    float inv = rsqrtf(fmaxf(s2 * (1.0f / Hdim) - mu * mu, 0.f) + 1e-5f);
    const float* wp = w + lane * 8;
    const float* bp = b + lane * 8;
    float o0[4], o1[4];
    #pragma unroll
    for (int k = 0; k < 4; k++) o0[k] = (v[k]   - mu) * inv * wp[k]   + bp[k];
    #pragma unroll
    for (int k = 0; k < 4; k++) o1[k] = (v[4+k] - mu) * inv * wp[4+k] + bp[4+k];
    __half* yr = y + (size_t)row * Hdim + lane * 8;
    st4h(yr, o0); st4h(yr + 4, o1);
}

// ---------------- compaction: count / scan / scatter -------------------------
__global__ void count_kernel() {
    int g = blockIdx.x * 256 + threadIdx.x;
    int i, j, oi; decode_edge(g, i, j, oi);
    int pred = g_valid[i] & g_valid[j];
    unsigned bal = __ballot_sync(0xffffffffu, pred);
    __shared__ int wcnt[8];
    if ((threadIdx.x & 31) == 0) wcnt[threadIdx.x >> 5] = __popc(bal);
    __syncthreads();
    if (threadIdx.x == 0) {
        int s = 0;
        #pragma unroll
        for (int k = 0; k < 8; k++) s += wcnt[k];
        g_bcount[blockIdx.x] = s;
    }
}

__global__ void scan_kernel() {
    __shared__ int part[256];
    int t = threadIdx.x;
    int base = t * 8;
    int loc[8];
    int s = 0;
    #pragma unroll
    for (int k = 0; k < 8; k++) {
        int idx = base + k;
        int v = (idx < NB) ? g_bcount[idx] : 0;
        loc[k] = s; s += v;
    }
    part[t] = s;
    __syncthreads();
    for (int o = 1; o < 256; o <<= 1) {
        int v = part[t];
        int add = (t >= o) ? part[t - o] : 0;
        __syncthreads();
        part[t] = v + add;
        __syncthreads();
    }
    int excl = part[t] - s;
    #pragma unroll
    for (int k = 0; k < 8; k++) {
        int idx = base + k;
        if (idx < 2048) g_boffs[idx] = excl + loc[k];
    }
    __syncthreads();
    if (t == 0) g_E = part[255];
}

__global__ void scatter_kernel() {
    int g = blockIdx.x * 256 + threadIdx.x;
    int lane = threadIdx.x & 31, warp = threadIdx.x >> 5;
    int i, j, oi; decode_edge(g, i, j, oi);
    int pred = g_valid[i] & g_valid[j];
    unsigned bal = __ballot_sync(0xffffffffu, pred);
    __shared__ int wcnt[8], wbase[8];
    if (lane == 0) wcnt[warp] = __popc(bal);
    __syncthreads();
    if (threadIdx.x == 0) {
        int s = 0;
        #pragma unroll
        for (int k = 0; k < 8; k++) { wbase[k] = s; s += wcnt[k]; }
    }
    __syncthreads();
    if (pred) {
        int pos = g_boffs[blockIdx.x] + wbase[warp]
                + __popc(bal & ((1u << lane) - 1u));
        g_ei[pos] = i; g_ej[pos] = j;
        g_posf[oi * NC + i] = pos;
        g_posr[oi * NC + j] = pos;
    }
}

// ---------------- gather messages + h2 residual + LN -> hu -------------------
__global__ void gather_ln_kernel(const float* __restrict__ h,
                                 const float* __restrict__ b2,
                                 const float* __restrict__ w,
                                 const float* __restrict__ b) {
    int warp = threadIdx.x >> 5, lane = threadIdx.x & 31;
    int row = blockIdx.x * 8 + warp;

    int p = -1;
    if (lane < 4)      p = g_posf[lane * NC + row];
    else if (lane < 8) p = g_posr[(lane - 4) * NC + row];

    float acc[8] = {};
    int cnt = 0;
    #pragma unroll
    for (int s = 0; s < 8; s++) {
        int ps = __shfl_sync(0xffffffffu, p, s);
        if (ps >= 0) {
            cnt++;
            const __half* Mrow = (s < 4 ? g_Mf : g_Mr) + (size_t)ps * Hdim + lane * 8;
            float f[8];
            ld8h(Mrow, f);
            #pragma unroll
            for (int k = 0; k < 8; k++) acc[k] += f[k];
        }
    }
    float cf = (float)cnt;
    const float* hr = h + (size_t)row * Hdim + lane * 8;
    const float* b2p = b2 + lane * 8;
    float4 ha = *(const float4*)hr;
    float4 hc = *(const float4*)(hr + 4);
    float hv[8] = {ha.x, ha.y, ha.z, ha.w, hc.x, hc.y, hc.z, hc.w};
    float v[8];
    #pragma unroll
    for (int k = 0; k < 8; k++) v[k] = hv[k] + acc[k] + cf * b2p[k];

    float* h2r = g_h2 + (size_t)row * Hdim + lane * 8;
    float4 o;
    o.x = v[0]; o.y = v[1]; o.z = v[2]; o.w = v[3];
    *(float4*)h2r = o;
    o.x = v[4]; o.y = v[5]; o.z = v[6]; o.w = v[7];
    *(float4*)(h2r + 4) = o;

    float s1 = 0.f, s2 = 0.f;
    #pragma unroll
    for (int k = 0; k < 8; k++) { s1 += v[k]; s2 += v[k]*v[k]; }
    #pragma unroll
    for (int ofs = 16; ofs > 0; ofs >>= 1) {
        s1 += __shfl_xor_sync(0xffffffffu, s1, ofs);
        s2 += __shfl_xor_sync(0xffffffffu, s2, ofs);
    }
    float mu = s1 * (1.0f / Hdim);
    float inv = rsqrtf(fmaxf(s2 * (1.0f / Hdim) - mu * mu, 0.f) + 1e-5f);
    const float* wp = w + lane * 8;
    const float* bp = b + lane * 8;
    float o0[4], o1[4];
    #pragma unroll
    for (int k = 0; k < 4; k++) o0[k] = (v[k]   - mu) * inv * wp[k]   + bp[k];
    #pragma unroll
    for (int k = 0; k < 4; k++) o1[k] = (v[4+k] - mu) * inv * wp[4+k] + bp[4+k];
    __half* yr = g_hu + (size_t)row * Hdim + lane * 8;
    st4h(yr, o0); st4h(yr + 4, o1);
}

// ============================================================================
// common tcgen05 helpers
// ============================================================================
__device__ __forceinline__ uint32_t smem_u32(const void* p) {
    uint32_t a;
    asm("{ .reg .u64 t; cvta.to.shared.u64 t, %1; cvt.u32.u64 %0, t; }" : "=r"(a) : "l"(p));
    return a;
}
__device__ __forceinline__ void mbar_wait(uint32_t mbar, uint32_t parity) {
    asm volatile(
        "{\n\t.reg .pred P1;\n\t"
        "W_%=:\n\t"
        "mbarrier.try_wait.parity.acquire.cta.shared::cta.b64 P1, [%0], %1, 0x989680;\n\t"
        "@P1 bra.uni D_%=;\n\t"
        "bra.uni W_%=;\n\t"
        "D_%=:\n\t}"
        :: "r"(mbar), "r"(parity) : "memory");
}

#if HAS_TC
__device__ __forceinline__ void mma_f16_ss(uint32_t d_tmem, uint64_t a_desc,
                                           uint64_t b_desc, uint32_t idesc, bool acc) {
    uint32_t en = acc ? 1u : 0u;
    asm volatile(
        "{\n\t.reg .pred p;\n\t"
        "setp.ne.u32 p, %5, 0;\n\t"
        "tcgen05.mma.cta_group::1.kind::f16 [%0], %1, %2, %3, {%4, %4, %4, %4}, p;\n\t"
        "}"
        :: "r"(d_tmem), "l"(a_desc), "l"(b_desc), "r"(idesc), "r"(0u), "r"(en)
        : "memory");
}
#define LDTM_X32(r, addr) \
    asm volatile( \
        "tcgen05.ld.sync.aligned.32x32b.x32.b32 " \
        "{%0, %1, %2, %3, %4, %5, %6, %7, " \
        " %8, %9, %10, %11, %12, %13, %14, %15, " \
        " %16, %17, %18, %19, %20, %21, %22, %23, " \
        " %24, %25, %26, %27, %28, %29, %30, %31}, [%32];" \
        : "=r"((r)[0]),  "=r"((r)[1]),  "=r"((r)[2]),  "=r"((r)[3]), \
          "=r"((r)[4]),  "=r"((r)[5]),  "=r"((r)[6]),  "=r"((r)[7]), \
          "=r"((r)[8]),  "=r"((r)[9]),  "=r"((r)[10]), "=r"((r)[11]), \
          "=r"((r)[12]), "=r"((r)[13]), "=r"((r)[14]), "=r"((r)[15]), \
          "=r"((r)[16]), "=r"((r)[17]), "=r"((r)[18]), "=r"((r)[19]), \
          "=r"((r)[20]), "=r"((r)[21]), "=r"((r)[22]), "=r"((r)[23]), \
          "=r"((r)[24]), "=r"((r)[25]), "=r"((r)[26]), "=r"((r)[27]), \
          "=r"((r)[28]), "=r"((r)[29]), "=r"((r)[30]), "=r"((r)[31]) \
        : "r"(addr))
#endif

static constexpr unsigned long long DESC_BASE =
    (2ull << 61) | (1ull << 46) | (64ull << 32) | (1ull << 16);
#define MMA_IDESC ((1u<<4) | (32u<<17) | (8u<<24))
#define SMEM_DYN  (1024 + 98304 + 64)
#define SMEM_EDGE (1024 + 131072 + 128 + 2048)

// ============================================================================
// fused edge-message kernel: computes A = gelu(P/Q gather + edge feats) into
// SMEM per chunk, MMAs both directions against w2t, writes Mf/Mr.
// Tile: 128 edges x 256 out, K=512, BK=64, TMEM 0-255 fwd / 256-511 rev.
// ============================================================================
__global__ void __launch_bounds__(256, 1)
edge_msg_kernel(const float* __restrict__ xyz,
                const float* __restrict__ w1,
                const float* __restrict__ b1,
                const __half* __restrict__ w2t) {
    extern __shared__ char dyn[];
    int tid = threadIdx.x;
    int m0 = blockIdx.x * 128;
    if (m0 >= g_E) return;

#if HAS_TC
    uint32_t u0 = smem_u32(dyn);
    uint32_t pad = (1024u - (u0 & 1023u)) & 1023u;
    char* base = dyn + pad;
    uint32_t ub = u0 + pad;

    uint32_t ctrl  = ub + 131072;
    uint32_t mbar0 = ctrl + 8;
    float* ef = (float*)(base + 131072 + 128);   // 128 edges x 4 floats

    int wid = tid >> 5;
    int lane = tid & 31;

    if (tid == 0) {
        asm volatile("mbarrier.init.shared.b64 [%0], 1;" :: "r"(mbar0)     : "memory");
        asm volatile("mbarrier.init.shared.b64 [%0], 1;" :: "r"(mbar0 + 8) : "memory");
    }
    if (wid == 0) {
        asm volatile("tcgen05.alloc.cta_group::1.sync.aligned.shared::cta.b32 [%0], %1;"
                     :: "r"(ctrl), "r"(512u) : "memory");
        asm volatile("tcgen05.relinquish_alloc_permit.cta_group::1.sync.aligned;");
    }
    __syncthreads();
    uint32_t tmem;
    asm volatile("ld.shared.b32 %0, [%1];" : "=r"(tmem) : "r"(ctrl));

    // edge features (once per CTA)
    if (tid < 128) {
        int m = m0 + tid;
        int i = g_ei[m], j = g_ej[m];
        float dx = xyz[3*j+0] - xyz[3*i+0];
        float dy = xyz[3*j+1] - xyz[3*i+1];
        float dz = xyz[3*j+2] - xyz[3*i+2];
        float d = fmaxf(sqrtf(dx*dx + dy*dy + dz*dz), 1e-6f);
        float inv = 1.0f / d;
        ef[tid*4+0] = dx*inv; ef[tid*4+1] = dy*inv; ef[tid*4+2] = dz*inv; ef[tid*4+3] = d;
    }
    __syncthreads();

    int r0 = tid >> 3, oct = tid & 7;
    uint32_t so = (uint32_t)(r0 * 128 + oct * 16);
    so ^= (so >> 3) & 0x70u;

    const int NCH = 8;                 // K=512, BK=64
    for (int c = 0; c < NCH; c++) {
        int buf = c & 1;
        if (c >= 2) mbar_wait(mbar0 + 8u * buf, (uint32_t)(((c - 2) >> 1) & 1));
        char* sAf = base + buf * 65536;
        char* sAr = sAf + 16384;
        char* sB  = sAf + 32768;
        int k0 = c << 6;
        int col = k0 + oct * 8;

        // B tile: 256 rows x 64 halves
        #pragma unroll
        for (int i2 = 0; i2 < 8; i2++) {
            int idx = tid + i2 * 256;
            int rB = idx >> 3, fB = idx & 7;
            uint4 bv = *(const uint4*)(w2t + (size_t)rB * H2 + k0 + fB * 8);
            uint32_t sob = (uint32_t)(rB * 128 + fB * 16);
            sob ^= (sob >> 3) & 0x70u;
            *(uint4*)(sB + sob) = bv;
        }

        // weight slices for this octet (per chunk)
        float w0v[8], w1v[8], w2v[8], w3v[8], bbv[8];
        {
            const float* wr0 = w1 + (size_t)(2*Hdim + 0)*H2 + col;
            const float* wr1 = w1 + (size_t)(2*Hdim + 1)*H2 + col;
            const float* wr2 = w1 + (size_t)(2*Hdim + 2)*H2 + col;
            const float* wr3 = w1 + (size_t)(2*Hdim + 3)*H2 + col;
            const float* bbr = b1 + col;
            #pragma unroll
            for (int q = 0; q < 8; q += 4) {
                *(float4*)(w0v+q) = *(const float4*)(wr0+q);
                *(float4*)(w1v+q) = *(const float4*)(wr1+q);
                *(float4*)(w2v+q) = *(const float4*)(wr2+q);
                *(float4*)(w3v+q) = *(const float4*)(wr3+q);
                *(float4*)(bbv+q) = *(const float4*)(bbr+q);
            }
        }

        // A tiles (fwd + rev): 4 rows per thread
        #pragma unroll
        for (int it = 0; it < 4; it++) {
            int r = r0 + it * 32;
            int m = m0 + r;
            int i = g_ei[m], j = g_ej[m];
            float e0 = ef[r*4+0], e1 = ef[r*4+1], e2 = ef[r*4+2], e3 = ef[r*4+3];
            float pi[8], qi[8], pj[8], qj[8];
            ld8h(g_PQ + (size_t)i*HU + col,       pi);
            ld8h(g_PQ + (size_t)i*HU + 512 + col, qi);
            ld8h(g_PQ + (size_t)j*HU + col,       pj);
            ld8h(g_PQ + (size_t)j*HU + 512 + col, qj);
            float rf[8], rr[8];
            #pragma unroll
            for (int q = 0; q < 8; q++) {
                float eu = e0*w0v[q] + e1*w1v[q] + e2*w2v[q];
                float ed = e3*w3v[q] + bbv[q];
                rf[q] = gelu_exact(pi[q] + qj[q] + eu + ed);
                rr[q] = gelu_exact(pj[q] + qi[q] - eu + ed);
            }
            *(uint4*)(sAf + so + (uint32_t)(it * 4096)) = pack8h(rf);
            *(uint4*)(sAr + so + (uint32_t)(it * 4096)) = pack8h(rr);
        }

        asm volatile("fence.proxy.async.shared::cta;" ::: "memory");
        __syncthreads();

        if (tid == 0) {
            uint32_t afaddr = ub + (uint32_t)(buf * 65536);
            uint32_t araddr = afaddr + 16384u;
            uint32_t baddr  = afaddr + 32768u;
            uint64_t adescF = DESC_BASE | (uint64_t)((afaddr >> 4) & 0x3FFFu);
            uint64_t adescR = DESC_BASE | (uint64_t)((araddr >> 4) & 0x3FFFu);
            uint64_t bdesc  = DESC_BASE | (uint64_t)((baddr  >> 4) & 0x3FFFu);
            #pragma unroll
            for (int s = 0; s < 4; s++) {
                bool acc = !(c == 0 && s == 0);
                mma_f16_ss(tmem,        adescF + 2u*s, bdesc + 2u*s, MMA_IDESC, acc);
                mma_f16_ss(tmem + 256u, adescR + 2u*s, bdesc + 2u*s, MMA_IDESC, acc);
            }
            asm volatile(
                "tcgen05.commit.cta_group::1.mbarrier::arrive::one.shared::cluster.b64 [%0];"
                :: "r"(mbar0 + 8u * buf) : "memory");
        }
    }
    mbar_wait(mbar0 + 8u * ((NCH - 2) & 1), (uint32_t)(((NCH - 2) >> 1) & 1));
    mbar_wait(mbar0 + 8u * ((NCH - 1) & 1), (uint32_t)(((NCH - 1) >> 1) & 1));
    asm volatile("tcgen05.fence::after_thread_sync;" ::: "memory");

    // epilogue: warps 0-3 -> fwd, warps 4-7 -> rev (parallel)
    {
        int dir = wid >> 2;
        int wd  = wid & 3;
        int trow = wd * 32 + lane;
        int m = m0 + trow;
        __half* M = dir ? g_Mr : g_Mf;
        uint32_t dbase = tmem + (uint32_t)(dir * 256);
        #pragma unroll
        for (int cc = 0; cc < 256; cc += 32) {
            uint32_t r[32];
            LDTM_X32(r, dbase + (uint32_t)cc);
            asm volatile("tcgen05.wait::ld.sync.aligned;" ::: "memory");
            #pragma unroll
            for (int q = 0; q < 32; q += 4) {
                float o[4] = {__uint_as_float(r[q]),   __uint_as_float(r[q+1]),
                              __uint_as_float(r[q+2]), __uint_as_float(r[q+3])};
                st4h(M + (size_t)m * Hdim + cc + q, o);
            }
        }
    }
    __syncthreads();
    if (wid == 0) {
        asm volatile("tcgen05.dealloc.cta_group::1.sync.aligned.b32 %0, %1;"
                     :: "r"(tmem), "r"(512u));
    }

#else  // -------- SIMT fallback (compute_103 PTX pass; compile-only path) -----
    float* As = (float*)dyn;            // [16][128]
    float* Bs = (float*)(dyn + 8192);   // [16][128]
    float* ef = (float*)(dyn + 16384);  // 128 x 4

    int tid2 = tid;
    if (tid2 < 128) {
        int m = m0 + tid2;
        int i = g_ei[m], j = g_ej[m];
        float dx = xyz[3*j+0] - xyz[3*i+0];
        float dy = xyz[3*j+1] - xyz[3*i+1];
        float dz = xyz[3*j+2] - xyz[3*i+2];
        float d = fmaxf(sqrtf(dx*dx + dy*dy + dz*dz), 1e-6f);
        float inv = 1.0f / d;
        ef[tid2*4+0] = dx*inv; ef[tid2*4+1] = dy*inv; ef[tid2*4+2] = dz*inv; ef[tid2*4+3] = d;
    }
    __syncthreads();

    int tr = tid >> 4, tc = tid & 15;
    for (int dir = 0; dir < 2; dir++) {
        for (int half = 0; half < 2; half++) {
            int n0h = half * 128;
            float acc[8][8] = {};
            for (int k0 = 0; k0 < H2; k0 += 16) {
                // fill As (computed) and Bs
                #pragma unroll
                for (int e = 0; e < 8; e++) {
                    int idx = tid * 8 + e;
                    int kk = idx >> 7, rr2 = idx & 127;
                    int m = m0 + rr2;
                    int i = g_ei[m], j = g_ej[m];
                    int colk = k0 + kk;
                    float e0 = ef[rr2*4], e1 = ef[rr2*4+1], e2 = ef[rr2*4+2], e3 = ef[rr2*4+3];
                    float eu = e0*w1[(size_t)(2*Hdim+0)*H2+colk]
                             + e1*w1[(size_t)(2*Hdim+1)*H2+colk]
                             + e2*w1[(size_t)(2*Hdim+2)*H2+colk];
                    float ed = e3*w1[(size_t)(2*Hdim+3)*H2+colk] + b1[colk];
                    float pv, qv;
                    if (dir == 0) {
                        pv = __half2float(g_PQ[(size_t)i*HU + colk]);
                        qv = __half2float(g_PQ[(size_t)j*HU + 512 + colk]);
                        As[kk*128 + rr2] = gelu_exact(pv + qv + eu + ed);
                    } else {
                        pv = __half2float(g_PQ[(size_t)j*HU + colk]);
                        qv = __half2float(g_PQ[(size_t)i*HU + 512 + colk]);
                        As[kk*128 + rr2] = gelu_exact(pv + qv - eu + ed);
                    }
                    Bs[kk*128 + rr2] = __half2float(w2t[(size_t)(n0h + rr2) * H2 + colk]);
                }
                __syncthreads();
                #pragma unroll
                for (int k = 0; k < 16; k++) {
                    float a[8], b[8];
                    #pragma unroll
                    for (int i2 = 0; i2 < 8; i2++) a[i2] = As[k*128 + tr*8 + i2];
                    #pragma unroll
                    for (int j2 = 0; j2 < 8; j2++) b[j2] = Bs[k*128 + tc*8 + j2];
                    #pragma unroll
                    for (int i2 = 0; i2 < 8; i2++)
                        #pragma unroll
                        for (int j2 = 0; j2 < 8; j2++)
                            acc[i2][j2] += a[i2] * b[j2];
                }
                __syncthreads();
            }
            __half* M = dir ? g_Mr : g_Mf;
            int col0 = n0h + tc * 8;
            #pragma unroll
            for (int i2 = 0; i2 < 8; i2++) {
                int m = m0 + tr * 8 + i2;
                for (int j2 = 0; j2 < 8; j2++)
                    M[(size_t)m * Hdim + col0 + j2] = __float2half(acc[i2][j2]);
            }
            __syncthreads();
        }
    }
#endif
}

// ============================================================================
// tcgen05 f16 GEMM (dense), register-prefetched double-buffered pipeline.
// Tile 128x256, BK=64.  EPI 0: half store; 1: half(gelu(acc+bias));
// EPI 3: (aux + acc + bias) * valid (float)
// ============================================================================
template<int EPI>
__global__ void __launch_bounds__(256, 2)
mma_gemm(const __half* __restrict__ A, int lda,
         const __half* __restrict__ Bt,
         const float* __restrict__ bias,
         void* __restrict__ CoutV, int ldc,
         const float* __restrict__ aux,
         int K) {
    extern __shared__ char dyn[];
    int tid = threadIdx.x;
    int n0 = blockIdx.x * 256;
    int m0 = blockIdx.y * 128;

#if HAS_TC
    uint32_t u0 = smem_u32(dyn);
    uint32_t pad = (1024u - (u0 & 1023u)) & 1023u;
    char* base = dyn + pad;
    uint32_t ub = u0 + pad;

    uint32_t ctrl  = ub + 98304;
    uint32_t mbar0 = ctrl + 8;

    int wid = tid >> 5;
    int lane = tid & 31;

    if (tid == 0) {
        asm volatile("mbarrier.init.shared.b64 [%0], 1;" :: "r"(mbar0)     : "memory");
        asm volatile("mbarrier.init.shared.b64 [%0], 1;" :: "r"(mbar0 + 8) : "memory");
    }
    if (wid == 0) {
        asm volatile("tcgen05.alloc.cta_group::1.sync.aligned.shared::cta.b32 [%0], %1;"
                     :: "r"(ctrl), "r"(256u) : "memory");
        asm volatile("tcgen05.relinquish_alloc_permit.cta_group::1.sync.aligned;");
    }
    __syncthreads();
    uint32_t tmem;
    asm volatile("ld.shared.b32 %0, [%1];" : "=r"(tmem) : "r"(ctrl));

    int rA = tid >> 3, f4 = tid & 7;
    uint32_t soA = (uint32_t)(rA * 128 + f4 * 16);
    soA ^= (soA >> 3) & 0x70u;
    const __half* Abase = A + (size_t)(m0 + rA) * lda + f4 * 8;
    const __half* Bbase = Bt + (size_t)(n0 + rA) * K + f4 * 8;
    size_t strideA = (size_t)32 * lda;
    size_t strideB = (size_t)32 * K;

    uint4 ra[4], rb[8];
    const int NCH = K >> 6;

    #pragma unroll
    for (int i = 0; i < 4; i++) ra[i] = *(const uint4*)(Abase + i * strideA);
    #pragma unroll
    for (int i = 0; i < 8; i++) rb[i] = *(const uint4*)(Bbase + i * strideB);

    #pragma unroll 2
    for (int c = 0; c < NCH; c++) {
        int buf = c & 1;
        if (c >= 2) mbar_wait(mbar0 + 8u * buf, (uint32_t)(((c - 2) >> 1) & 1));
        char* sA = base + buf * 16384;
        char* sB = base + 32768 + buf * 32768;

        #pragma unroll
        for (int i = 0; i < 4; i++)
            *(uint4*)(sA + soA + (uint32_t)(i * 4096)) = ra[i];
        #pragma unroll
        for (int i = 0; i < 8; i++)
            *(uint4*)(sB + soA + (uint32_t)(i * 4096)) = rb[i];

        if (c + 1 < NCH) {
            const __half* An = Abase + (c + 1) * 64;
            const __half* Bn = Bbase + (c + 1) * 64;
            #pragma unroll
            for (int i = 0; i < 4; i++) ra[i] = *(const uint4*)(An + i * strideA);
            #pragma unroll
            for (int i = 0; i < 8; i++) rb[i] = *(const uint4*)(Bn + i * strideB);
        }

        asm volatile("fence.proxy.async.shared::cta;" ::: "memory");
        __syncthreads();

        if (tid == 0) {
            uint32_t aaddr = ub + (uint32_t)(buf * 16384);
            uint32_t baddr = ub + (uint32_t)(32768 + buf * 32768);
            uint64_t adesc = DESC_BASE | (uint64_t)((aaddr >> 4) & 0x3FFFu);
            uint64_t bdesc = DESC_BASE | (uint64_t)((baddr >> 4) & 0x3FFFu);
            #pragma unroll
            for (int s = 0; s < 4; s++) {
                mma_f16_ss(tmem, adesc + 2u * s, bdesc + 2u * s, MMA_IDESC,
                           !(c == 0 && s == 0));
            }
            asm volatile(
                "tcgen05.commit.cta_group::1.mbarrier::arrive::one.shared::cluster.b64 [%0];"
                :: "r"(mbar0 + 8u * buf) : "memory");
        }
    }
    mbar_wait(mbar0 + 8u * ((NCH - 2) & 1), (uint32_t)(((NCH - 2) >> 1) & 1));
    mbar_wait(mbar0 + 8u * ((NCH - 1) & 1), (uint32_t)(((NCH - 1) >> 1) & 1));
    asm volatile("tcgen05.fence::after_thread_sync;" ::: "memory");

    if (wid < 4) {
        int trow = wid * 32 + lane;
        int m = m0 + trow;
        float vf = 1.0f;
        if (EPI == 3) vf = g_valid[m] ? 1.0f : 0.0f;

        #pragma unroll
        for (int cc = 0; cc < 256; cc += 32) {
            uint32_t r[32];
            LDTM_X32(r, tmem + (uint32_t)cc);
            asm volatile("tcgen05.wait::ld.sync.aligned;" ::: "memory");
            int col0 = n0 + cc;
            if (EPI == 0) {
                __half* Cout = (__half*)CoutV;
                #pragma unroll
                for (int j = 0; j < 32; j += 4) {
                    float o[4] = {__uint_as_float(r[j]), __uint_as_float(r[j+1]),
                                  __uint_as_float(r[j+2]), __uint_as_float(r[j+3])};
                    st4h(Cout + (size_t)m * ldc + col0 + j, o);
                }
            } else if (EPI == 1) {
                __half* Cout = (__half*)CoutV;
                #pragma unroll
                for (int j = 0; j < 32; j += 4) {
                    float o[4];
                    o[0] = gelu_exact(__uint_as_float(r[j])   + __ldg(&bias[col0+j]));
                    o[1] = gelu_exact(__uint_as_float(r[j+1]) + __ldg(&bias[col0+j+1]));
                    o[2] = gelu_exact(__uint_as_float(r[j+2]) + __ldg(&bias[col0+j+2]));
                    o[3] = gelu_exact(__uint_as_float(r[j+3]) + __ldg(&bias[col0+j+3]));
                    st4h(Cout + (size_t)m * ldc + col0 + j, o);
                }
            } else {
                float* Cout = (float*)CoutV;
                const float* a2 = aux + (size_t)m * Hdim + col0;
                #pragma unroll
                for (int j = 0; j < 32; j += 4) {
                    float4 av = *(const float4*)(a2 + j);
                    float4 o;
                    o.x = (av.x + __uint_as_float(r[j])   + __ldg(&bias[col0+j]))   * vf;
                    o.y = (av.y + __uint_as_float(r[j+1]) + __ldg(&bias[col0+j+1])) * vf;
                    o.z = (av.z + __uint_as_float(r[j+2]) + __ldg(&bias[col0+j+2])) * vf;
                    o.w = (av.w + __uint_as_float(r[j+3]) + __ldg(&bias[col0+j+3])) * vf;
                    *(float4*)(Cout + (size_t)m * ldc + col0 + j) = o;
                }
            }
        }
    }
    __syncthreads();
    if (wid == 0) {
        asm volatile("tcgen05.dealloc.cta_group::1.sync.aligned.b32 %0, %1;"
                     :: "r"(tmem), "r"(256u));
    }

#else  // ---------------- SIMT fallback (compute_103 PTX pass) ----------------
    float* As = (float*)dyn;
    float* Bs = (float*)(dyn + 8192);

    int tr = tid >> 4, tc = tid & 15;
    int lrow = tid >> 1;
    int lk   = (tid & 1) * 8;

    for (int half = 0; half < 2; half++) {
        int n0h = n0 + half * 128;
        float acc[8][8] = {};
        for (int k0 = 0; k0 < K; k0 += 16) {
            #pragma unroll
            for (int e = 0; e < 8; e++) {
                As[(lk+e)*128 + lrow] = __half2float(A[(size_t)(m0 + lrow) * lda + k0 + lk + e]);
                Bs[(lk+e)*128 + lrow] = __half2float(Bt[(size_t)(n0h + lrow) * K + k0 + lk + e]);
            }
            __syncthreads();
            #pragma unroll
            for (int k = 0; k < 16; k++) {
                float a[8], b[8];
                #pragma unroll
                for (int i = 0; i < 8; i++) a[i] = As[k*128 + tr*8 + i];
                #pragma unroll
                for (int j = 0; j < 8; j++) b[j] = Bs[k*128 + tc*8 + j];
                #pragma unroll
                for (int i = 0; i < 8; i++)
                    #pragma unroll
                    for (int j = 0; j < 8; j++)
                        acc[i][j] += a[i] * b[j];
            }
            __syncthreads();
        }

        int col0 = n0h + tc * 8;
        #pragma unroll
        for (int i = 0; i < 8; i++) {
            int m = m0 + tr * 8 + i;
            if (EPI == 0) {
                __half* Cout = (__half*)CoutV;
                for (int j = 0; j < 8; j++)
                    Cout[(size_t)m * ldc + col0 + j] = __float2half(acc[i][j]);
            } else if (EPI == 1) {
                __half* Cout = (__half*)CoutV;
                for (int j = 0; j < 8; j++)
                    Cout[(size_t)m * ldc + col0 + j] =
                        __float2half(gelu_exact(acc[i][j] + bias[col0 + j]));
            } else {
                float* Cout = (float*)CoutV;
                float vf = g_valid[m] ? 1.0f : 0.0f;
                const float* a2 = aux + (size_t)m * Hdim + col0;
                for (int j = 0; j < 8; j++)
                    Cout[(size_t)m * ldc + col0 + j] =
                        (a2[j] + acc[i][j] + bias[col0 + j]) * vf;
            }
        }
        __syncthreads();
    }
#endif
}

// ---------------- launch -----------------------------------------------------
extern "C" void kernel_launch(void* const* d_in, const int* in_sizes, int n_in,
                              void* d_out, int out_size) {
    const float*         h      = (const float*)d_in[0];
    const float*         xyz    = (const float*)d_in[1];
    const unsigned char* validb = (const unsigned char*)d_in[2];
    const float*         ln_n_w = (const float*)d_in[3];
    const float*         ln_n_b = (const float*)d_in[4];
    const float*         w1     = (const float*)d_in[5];
    const float*         b1     = (const float*)d_in[6];
    const float*         w2     = (const float*)d_in[7];
    const float*         b2     = (const float*)d_in[8];
    const float*         ln_u_w = (const float*)d_in[9];
    const float*         ln_u_b = (const float*)d_in[10];
    const float*         u1     = (const float*)d_in[11];
    const float*         bu1    = (const float*)d_in[12];
    const float*         u2     = (const float*)d_in[13];
    const float*         bu2    = (const float*)d_in[14];
    float* out = (float*)d_out;

    __half *pHin, *pPQ, *pHu, *pT1;
    __half *pWabt, *pW2t, *pU1t, *pU2t;
    float *pH2;
    cudaGetSymbolAddress((void**)&pHin, g_hin);
    cudaGetSymbolAddress((void**)&pPQ,  g_PQ);
    cudaGetSymbolAddress((void**)&pH2,  g_h2);
    cudaGetSymbolAddress((void**)&pHu,  g_hu);
    cudaGetSymbolAddress((void**)&pT1,  g_T1);
    cudaGetSymbolAddress((void**)&pWabt, g_wabt);
    cudaGetSymbolAddress((void**)&pW2t,  g_w2t);
    cudaGetSymbolAddress((void**)&pU1t,  g_u1t);
    cudaGetSymbolAddress((void**)&pU2t,  g_u2t);

    cudaFuncSetAttribute(mma_gemm<0>, cudaFuncAttributeMaxDynamicSharedMemorySize, SMEM_DYN);
    cudaFuncSetAttribute(mma_gemm<1>, cudaFuncAttributeMaxDynamicSharedMemorySize, SMEM_DYN);
    cudaFuncSetAttribute(mma_gemm<3>, cudaFuncAttributeMaxDynamicSharedMemorySize, SMEM_DYN);
    cudaFuncSetAttribute(edge_msg_kernel, cudaFuncAttributeMaxDynamicSharedMemorySize, SMEM_EDGE);

    detect_vmode_kernel<<<1, 256>>>(validb);
    conv_valid_kernel<<<(NC + 255) / 256, 256>>>(validb);
    clear_pos_kernel<<<4*NC/256, 256>>>();
    transpose_all_kernel<<<917504/256, 256>>>(w1, w2, u1, u2);
    ln_kernel<<<NC/8, 256>>>(h, ln_n_w, ln_n_b, pHin);
    count_kernel<<<NB, 256>>>();
    // PQ = h_in @ [W1a | W1b]  (M=NC, K=256, N=1024)
    mma_gemm<0><<<dim3(4, NC/128), 256, SMEM_DYN>>>(pHin, Hdim, pWabt,
                                                    nullptr, pPQ, HU, nullptr, Hdim);
    scan_kernel<<<1, 256>>>();
    scatter_kernel<<<NB, 256>>>();

    // fused edge message kernel (edge features + gelu + both-direction GEMM)
    edge_msg_kernel<<<MAXE/128, 256, SMEM_EDGE>>>(xyz, w1, b1, pW2t);

    // gather messages -> h2 -> LN -> hu
    gather_ln_kernel<<<NC/8, 256>>>(h, b2, ln_u_w, ln_u_b);

    mma_gemm<1><<<dim3(4, NC/128), 256, SMEM_DYN>>>(pHu, Hdim, pU1t,
                                                    bu1, pT1, HU, nullptr, Hdim);
    mma_gemm<3><<<dim3(1, NC/128), 256, SMEM_DYN>>>(pT1, HU, pU2t,
                                                    bu2, out, Hdim, pH2, HU);
    (void)in_sizes; (void)n_in; (void)out_size;
}

// round 11
// speedup vs baseline: 11.5332x; 1.1214x over previous
#include <cuda_runtime.h>
#include <cuda_fp16.h>
#include <math.h>
#include <stdint.h>

#define Ndim 256
#define Cdim 512
#define Hdim 256
#define NC   (Ndim*Cdim)   // 131072
#define H2   512
#define HU   1024
#define MAXE 520448
#define NB   2033          // MAXE / 256

#if defined(__CUDA_ARCH_FEAT_SM103_ALL) || defined(__CUDA_ARCH_FEAT_SM100_ALL) || \
    (defined(__CUDA_ARCH_SPECIFIC__) && (__CUDA_ARCH_SPECIFIC__ >= 1000))
#define HAS_TC 1
#else
#define HAS_TC 0
#endif

// ---------------- scratch ----------------------------------------------------
__device__ __half g_hin[(size_t)NC*Hdim];
__device__ __half g_PQ [(size_t)NC*HU];
__device__ __half g_Mf [(size_t)MAXE*Hdim];
__device__ __half g_Mr [(size_t)MAXE*Hdim];
__device__ float  g_h2 [(size_t)NC*Hdim];
__device__ __half g_hu [(size_t)NC*Hdim];
__device__ __half g_T1 [(size_t)NC*HU];      // fallback staging only
__device__ __half g_wabt[(size_t)HU*Hdim];
__device__ __half g_w2t [(size_t)Hdim*H2];
__device__ __half g_u1t [(size_t)HU*Hdim];
__device__ __half g_u2t [(size_t)Hdim*HU];
__device__ unsigned char g_valid[NC];
__device__ int g_vmode;
__device__ int g_ei[MAXE];
__device__ int g_ej[MAXE];
__device__ int g_posf[4*NC];
__device__ int g_posr[4*NC];
__device__ int g_bcount[2048];
__device__ int g_boffs[2048];
__device__ int g_E;

__device__ __forceinline__ float gelu_exact(float x) {
    return 0.5f * x * (1.0f + erff(x * 0.70710678118654752f));
}
__device__ __forceinline__ void st4h(__half* p, const float* f) {
    uint2 u;
    *(__half2*)&u.x = __float22half2_rn(make_float2(f[0], f[1]));
    *(__half2*)&u.y = __float22half2_rn(make_float2(f[2], f[3]));
    *(uint2*)p = u;
}
__device__ __forceinline__ void ld8h(const __half* p, float* f) {
    uint4 u = *(const uint4*)p;
    float2 a = __half22float2(*(__half2*)&u.x);
    float2 b = __half22float2(*(__half2*)&u.y);
    float2 c = __half22float2(*(__half2*)&u.z);
    float2 d = __half22float2(*(__half2*)&u.w);
    f[0]=a.x; f[1]=a.y; f[2]=b.x; f[3]=b.y; f[4]=c.x; f[5]=c.y; f[6]=d.x; f[7]=d.y;
}
__device__ __forceinline__ void cvt8h(const uint4& u, float* f) {
    float2 a = __half22float2(*(__half2*)&u.x);
    float2 b = __half22float2(*(__half2*)&u.y);
    float2 c = __half22float2(*(__half2*)&u.z);
    float2 d = __half22float2(*(__half2*)&u.w);
    f[0]=a.x; f[1]=a.y; f[2]=b.x; f[3]=b.y; f[4]=c.x; f[5]=c.y; f[6]=d.x; f[7]=d.y;
}
__device__ __forceinline__ uint4 pack8h(const float* f) {
    uint4 u;
    *(__half2*)&u.x = __float22half2_rn(make_float2(f[0], f[1]));
    *(__half2*)&u.y = __float22half2_rn(make_float2(f[2], f[3]));
    *(__half2*)&u.z = __float22half2_rn(make_float2(f[4], f[5]));
    *(__half2*)&u.w = __float22half2_rn(make_float2(f[6], f[7]));
    return u;
}

__device__ __forceinline__ void decode_edge(int g, int& i, int& j, int& oi) {
    int off, Ce, t;
    if (g < 130816)      { off = 1; Ce = 511; t = g;          oi = 0; }
    else if (g < 261376) { off = 2; Ce = 510; t = g - 130816; oi = 1; }
    else if (g < 391424) { off = 4; Ce = 508; t = g - 261376; oi = 2; }
    else                 { off = 8; Ce = 504; t = g - 391424; oi = 3; }
    int n = t / Ce, c = t - n * Ce;
    i = (n << 9) + c; j = i + off;
}

// ---------------- valid dtype detection + normalization ---------------------
__global__ void detect_vmode_kernel(const unsigned char* __restrict__ v) {
    int t = threadIdx.x;
    int nz1 = 0, nz23 = 0;
    #pragma unroll
    for (int k = 0; k < 16; k += 4) {
        int i = t * 16 + k;
        if (v[i+1]) nz1 = 1;
        if (v[i+2] | v[i+3]) nz23 = 1;
    }
    int a1 = __syncthreads_or(nz1);
    int a23 = __syncthreads_or(nz23);
    if (t == 0) g_vmode = a1 ? 0 : (a23 ? 2 : 1);
}
__global__ void conv_valid_kernel(const unsigned char* __restrict__ v) {
    int i = blockIdx.x * 256 + threadIdx.x;
    if (i >= NC) return;
    int mode = g_vmode;
    unsigned char r;
    if (mode == 0)      r = v[i] != 0;
    else if (mode == 1) r = ((const int*)v)[i] != 0;
    else                r = ((const unsigned int*)v)[i] != 0u;
    g_valid[i] = r;
}

__global__ void clear_pos_kernel() {
    int i = blockIdx.x * 256 + threadIdx.x;
    g_posf[i] = -1;
    g_posr[i] = -1;
}

// ---------------- weight transposes (fp16), one launch -----------------------
__global__ void transpose_all_kernel(const float* __restrict__ w1,
                                     const float* __restrict__ w2,
                                     const float* __restrict__ u1,
                                     const float* __restrict__ u2) {
    int idx = blockIdx.x * 256 + threadIdx.x;
    if (idx < 262144) {
        int n = idx >> 8, k = idx & 255;
        float s = (n < 512) ? w1[(size_t)k * 512 + n]
                            : w1[(size_t)(k + 256) * 512 + (n - 512)];
        g_wabt[idx] = __float2half(s);
    } else if (idx < 393216) {
        int t = idx - 262144;
        int n = t >> 9, k = t & 511;
        g_w2t[t] = __float2half(w2[(size_t)k * 256 + n]);
    } else if (idx < 655360) {
        int t = idx - 393216;
        int n = t >> 8, k = t & 255;
        g_u1t[t] = __float2half(u1[(size_t)k * 1024 + n]);
    } else if (idx < 917504) {
        int t = idx - 655360;
        int n = t >> 10, k = t & 1023;
        g_u2t[t] = __float2half(u2[(size_t)k * 256 + n]);
    }
}

// ---------------- LN1 (one-pass stats), warp per row -------------------------
__global__ void ln_kernel(const float* __restrict__ x,
                          const float* __restrict__ w,
                          const float* __restrict__ b,
                          __half* __restrict__ y) {
    int warp = threadIdx.x >> 5, lane = threadIdx.x & 31;
    int row = blockIdx.x * 8 + warp;
    const float* xr = x + (size_t)row * Hdim + lane * 8;
    float4 a = *(const float4*)xr;
    float4 c = *(const float4*)(xr + 4);
    float v[8] = {a.x, a.y, a.z, a.w, c.x, c.y, c.z, c.w};
    float s1 = 0.f, s2 = 0.f;
    #pragma unroll
    for (int k = 0; k < 8; k++) { s1 += v[k]; s2 += v[k]*v[k]; }
    #pragma unroll
    for (int o = 16; o > 0; o >>= 1) {
        s1 += __shfl_xor_sync(0xffffffffu, s1, o);
        s2 += __shfl_xor_sync(0xffffffffu, s2, o);
    }
    float mu = s1 * (1.0f / Hdim);
    float inv = rsqrtf(fmaxf(s2 * (1.0f / Hdim) - mu * mu, 0.f) + 1e-5f);
    const float* wp = w + lane * 8;
    const float* bp = b + lane * 8;
    float o0[4], o1[4];
    #pragma unroll
    for (int k = 0; k < 4; k++) o0[k] = (v[k]   - mu) * inv * wp[k]   + bp[k];
    #pragma unroll
    for (int k = 0; k < 4; k++) o1[k] = (v[4+k] - mu) * inv * wp[4+k] + bp[4+k];
    __half* yr = y + (size_t)row * Hdim + lane * 8;
    st4h(yr, o0); st4h(yr + 4, o1);
}

// ---------------- compaction: count / scan / scatter -------------------------
__global__ void count_kernel() {
    int g = blockIdx.x * 256 + threadIdx.x;
    int i, j, oi; decode_edge(g, i, j, oi);
    int pred = g_valid[i] & g_valid[j];
    unsigned bal = __ballot_sync(0xffffffffu, pred);
    __shared__ int wcnt[8];
    if ((threadIdx.x & 31) == 0) wcnt[threadIdx.x >> 5] = __popc(bal);
    __syncthreads();
    if (threadIdx.x == 0) {
        int s = 0;
        #pragma unroll
        for (int k = 0; k < 8; k++) s += wcnt[k];
        g_bcount[blockIdx.x] = s;
    }
}

__global__ void scan_kernel() {
    __shared__ int part[256];
    int t = threadIdx.x;
    int base = t * 8;
    int loc[8];
    int s = 0;
    #pragma unroll
    for (int k = 0; k < 8; k++) {
        int idx = base + k;
        int v = (idx < NB) ? g_bcount[idx] : 0;
        loc[k] = s; s += v;
    }
    part[t] = s;
    __syncthreads();
    for (int o = 1; o < 256; o <<= 1) {
        int v = part[t];
        int add = (t >= o) ? part[t - o] : 0;
        __syncthreads();
        part[t] = v + add;
        __syncthreads();
    }
    int excl = part[t] - s;
    #pragma unroll
    for (int k = 0; k < 8; k++) {
        int idx = base + k;
        if (idx < 2048) g_boffs[idx] = excl + loc[k];
    }
    __syncthreads();
    if (t == 0) g_E = part[255];
}

__global__ void scatter_kernel() {
    int g = blockIdx.x * 256 + threadIdx.x;
    int lane = threadIdx.x & 31, warp = threadIdx.x >> 5;
    int i, j, oi; decode_edge(g, i, j, oi);
    int pred = g_valid[i] & g_valid[j];
    unsigned bal = __ballot_sync(0xffffffffu, pred);
    __shared__ int wcnt[8], wbase[8];
    if (lane == 0) wcnt[warp] = __popc(bal);
    __syncthreads();
    if (threadIdx.x == 0) {
        int s = 0;
        #pragma unroll
        for (int k = 0; k < 8; k++) { wbase[k] = s; s += wcnt[k]; }
    }
    __syncthreads();
    if (pred) {
        int pos = g_boffs[blockIdx.x] + wbase[warp]
                + __popc(bal & ((1u << lane) - 1u));
        g_ei[pos] = i; g_ej[pos] = j;
        g_posf[oi * NC + i] = pos;
        g_posr[oi * NC + j] = pos;
    }
}

// ---------------- gather messages + h2 residual + LN -> hu -------------------
__global__ void gather_ln_kernel(const float* __restrict__ h,
                                 const float* __restrict__ b2,
                                 const float* __restrict__ w,
                                 const float* __restrict__ b) {
    int warp = threadIdx.x >> 5, lane = threadIdx.x & 31;
    int row = blockIdx.x * 8 + warp;

    int p = -1;
    if (lane < 4)      p = g_posf[lane * NC + row];
    else if (lane < 8) p = g_posr[(lane - 4) * NC + row];

    float acc[8] = {};
    int cnt = 0;
    #pragma unroll
    for (int s = 0; s < 8; s++) {
        int ps = __shfl_sync(0xffffffffu, p, s);
        if (ps >= 0) {
            cnt++;
            const __half* Mrow = (s < 4 ? g_Mf : g_Mr) + (size_t)ps * Hdim + lane * 8;
            float f[8];
            ld8h(Mrow, f);
            #pragma unroll
            for (int k = 0; k < 8; k++) acc[k] += f[k];
        }
    }
    float cf = (float)cnt;
    const float* hr = h + (size_t)row * Hdim + lane * 8;
    const float* b2p = b2 + lane * 8;
    float4 ha = *(const float4*)hr;
    float4 hc = *(const float4*)(hr + 4);
    float hv[8] = {ha.x, ha.y, ha.z, ha.w, hc.x, hc.y, hc.z, hc.w};
    float v[8];
    #pragma unroll
    for (int k = 0; k < 8; k++) v[k] = hv[k] + acc[k] + cf * b2p[k];

    float* h2r = g_h2 + (size_t)row * Hdim + lane * 8;
    float4 o;
    o.x = v[0]; o.y = v[1]; o.z = v[2]; o.w = v[3];
    *(float4*)h2r = o;
    o.x = v[4]; o.y = v[5]; o.z = v[6]; o.w = v[7];
    *(float4*)(h2r + 4) = o;

    float s1 = 0.f, s2 = 0.f;
    #pragma unroll
    for (int k = 0; k < 8; k++) { s1 += v[k]; s2 += v[k]*v[k]; }
    #pragma unroll
    for (int ofs = 16; ofs > 0; ofs >>= 1) {
        s1 += __shfl_xor_sync(0xffffffffu, s1, ofs);
        s2 += __shfl_xor_sync(0xffffffffu, s2, ofs);
    }
    float mu = s1 * (1.0f / Hdim);
    float inv = rsqrtf(fmaxf(s2 * (1.0f / Hdim) - mu * mu, 0.f) + 1e-5f);
    const float* wp = w + lane * 8;
    const float* bp = b + lane * 8;
    float o0[4], o1[4];
    #pragma unroll
    for (int k = 0; k < 4; k++) o0[k] = (v[k]   - mu) * inv * wp[k]   + bp[k];
    #pragma unroll
    for (int k = 0; k < 4; k++) o1[k] = (v[4+k] - mu) * inv * wp[4+k] + bp[4+k];
    __half* yr = g_hu + (size_t)row * Hdim + lane * 8;
    st4h(yr, o0); st4h(yr + 4, o1);
}

// ============================================================================
// common tcgen05 helpers
// ============================================================================
__device__ __forceinline__ uint32_t smem_u32(const void* p) {
    uint32_t a;
    asm("{ .reg .u64 t; cvta.to.shared.u64 t, %1; cvt.u32.u64 %0, t; }" : "=r"(a) : "l"(p));
    return a;
}
__device__ __forceinline__ void mbar_wait(uint32_t mbar, uint32_t parity) {
    asm volatile(
        "{\n\t.reg .pred P1;\n\t"
        "W_%=:\n\t"
        "mbarrier.try_wait.parity.acquire.cta.shared::cta.b64 P1, [%0], %1, 0x989680;\n\t"
        "@P1 bra.uni D_%=;\n\t"
        "bra.uni W_%=;\n\t"
        "D_%=:\n\t}"
        :: "r"(mbar), "r"(parity) : "memory");
}

#if HAS_TC
__device__ __forceinline__ void mma_f16_ss(uint32_t d_tmem, uint64_t a_desc,
                                           uint64_t b_desc, uint32_t idesc, bool acc) {
    uint32_t en = acc ? 1u : 0u;
    asm volatile(
        "{\n\t.reg .pred p;\n\t"
        "setp.ne.u32 p, %5, 0;\n\t"
        "tcgen05.mma.cta_group::1.kind::f16 [%0], %1, %2, %3, {%4, %4, %4, %4}, p;\n\t"
        "}"
        :: "r"(d_tmem), "l"(a_desc), "l"(b_desc), "r"(idesc), "r"(0u), "r"(en)
        : "memory");
}
#define LDTM_X32(r, addr) \
    asm volatile( \
        "tcgen05.ld.sync.aligned.32x32b.x32.b32 " \
        "{%0, %1, %2, %3, %4, %5, %6, %7, " \
        " %8, %9, %10, %11, %12, %13, %14, %15, " \
        " %16, %17, %18, %19, %20, %21, %22, %23, " \
        " %24, %25, %26, %27, %28, %29, %30, %31}, [%32];" \
        : "=r"((r)[0]),  "=r"((r)[1]),  "=r"((r)[2]),  "=r"((r)[3]), \
          "=r"((r)[4]),  "=r"((r)[5]),  "=r"((r)[6]),  "=r"((r)[7]), \
          "=r"((r)[8]),  "=r"((r)[9]),  "=r"((r)[10]), "=r"((r)[11]), \
          "=r"((r)[12]), "=r"((r)[13]), "=r"((r)[14]), "=r"((r)[15]), \
          "=r"((r)[16]), "=r"((r)[17]), "=r"((r)[18]), "=r"((r)[19]), \
          "=r"((r)[20]), "=r"((r)[21]), "=r"((r)[22]), "=r"((r)[23]), \
          "=r"((r)[24]), "=r"((r)[25]), "=r"((r)[26]), "=r"((r)[27]), \
          "=r"((r)[28]), "=r"((r)[29]), "=r"((r)[30]), "=r"((r)[31]) \
        : "r"(addr))
#endif

static constexpr unsigned long long DESC_BASE =
    (2ull << 61) | (1ull << 46) | (64ull << 32) | (1ull << 16);
#define MMA_IDESC ((1u<<4) | (32u<<17) | (8u<<24))
#define SMEM_DYN  (1024 + 98304 + 64)
#define SMEM_EDGE (1024 + 131072 + 128 + 2048)
#define SMEM_MLP  (1024 + 196608 + 64)

// ============================================================================
// fused edge-message kernel (register-prefetched gathers)
// ============================================================================
__global__ void __launch_bounds__(256, 1)
edge_msg_kernel(const float* __restrict__ xyz,
                const float* __restrict__ w1,
                const float* __restrict__ b1,
                const __half* __restrict__ w2t) {
    extern __shared__ char dyn[];
    int tid = threadIdx.x;
    int m0 = blockIdx.x * 128;
    if (m0 >= g_E) return;

#if HAS_TC
    uint32_t u0 = smem_u32(dyn);
    uint32_t pad = (1024u - (u0 & 1023u)) & 1023u;
    char* base = dyn + pad;
    uint32_t ub = u0 + pad;

    uint32_t ctrl  = ub + 131072;
    uint32_t mbar0 = ctrl + 8;
    float* ef = (float*)(base + 131072 + 128);

    int wid = tid >> 5;
    int lane = tid & 31;

    if (tid == 0) {
        asm volatile("mbarrier.init.shared.b64 [%0], 1;" :: "r"(mbar0)     : "memory");
        asm volatile("mbarrier.init.shared.b64 [%0], 1;" :: "r"(mbar0 + 8) : "memory");
    }
    if (wid == 0) {
        asm volatile("tcgen05.alloc.cta_group::1.sync.aligned.shared::cta.b32 [%0], %1;"
                     :: "r"(ctrl), "r"(512u) : "memory");
        asm volatile("tcgen05.relinquish_alloc_permit.cta_group::1.sync.aligned;");
    }
    __syncthreads();
    uint32_t tmem;
    asm volatile("ld.shared.b32 %0, [%1];" : "=r"(tmem) : "r"(ctrl));

    if (tid < 128) {
        int m = m0 + tid;
        int i = g_ei[m], j = g_ej[m];
        float dx = xyz[3*j+0] - xyz[3*i+0];
        float dy = xyz[3*j+1] - xyz[3*i+1];
        float dz = xyz[3*j+2] - xyz[3*i+2];
        float d = fmaxf(sqrtf(dx*dx + dy*dy + dz*dz), 1e-6f);
        float inv = 1.0f / d;
        ef[tid*4+0] = dx*inv; ef[tid*4+1] = dy*inv; ef[tid*4+2] = dz*inv; ef[tid*4+3] = d;
    }
    __syncthreads();

    int r0 = tid >> 3, oct = tid & 7;
    uint32_t so = (uint32_t)(r0 * 128 + oct * 16);
    so ^= (so >> 3) & 0x70u;

    // hoist edge indices + edge feats for this thread's 4 rows
    int ei4[4], ej4[4];
    float efr[4][4];
    #pragma unroll
    for (int it = 0; it < 4; it++) {
        int r = r0 + it * 32;
        ei4[it] = g_ei[m0 + r];
        ej4[it] = g_ej[m0 + r];
        efr[it][0] = ef[r*4+0]; efr[it][1] = ef[r*4+1];
        efr[it][2] = ef[r*4+2]; efr[it][3] = ef[r*4+3];
    }

    uint4 gp[16];   // pi,qi,pj,qj per 4 row-iters
    uint4 rbB[8];
    const int NCH = 8;

    // prefetch chunk 0
    {
        int col = oct * 8;
        #pragma unroll
        for (int it = 0; it < 4; it++) {
            gp[it*4+0] = *(const uint4*)(g_PQ + (size_t)ei4[it]*HU + col);
            gp[it*4+1] = *(const uint4*)(g_PQ + (size_t)ei4[it]*HU + 512 + col);
            gp[it*4+2] = *(const uint4*)(g_PQ + (size_t)ej4[it]*HU + col);
            gp[it*4+3] = *(const uint4*)(g_PQ + (size_t)ej4[it]*HU + 512 + col);
        }
        #pragma unroll
        for (int i2 = 0; i2 < 8; i2++) {
            int idx = tid + i2 * 256;
            int rB = idx >> 3, fB = idx & 7;
            rbB[i2] = *(const uint4*)(w2t + (size_t)rB * H2 + fB * 8);
        }
    }

    for (int c = 0; c < NCH; c++) {
        int buf = c & 1;
        if (c >= 2) mbar_wait(mbar0 + 8u * buf, (uint32_t)(((c - 2) >> 1) & 1));
        char* sAf = base + buf * 65536;
        char* sAr = sAf + 16384;
        char* sB  = sAf + 32768;
        int k0 = c << 6;
        int col = k0 + oct * 8;

        // store prefetched B
        #pragma unroll
        for (int i2 = 0; i2 < 8; i2++) {
            int idx = tid + i2 * 256;
            int rB = idx >> 3, fB = idx & 7;
            uint32_t sob = (uint32_t)(rB * 128 + fB * 16);
            sob ^= (sob >> 3) & 0x70u;
            *(uint4*)(sB + sob) = rbB[i2];
        }

        // weight slices for this chunk
        float w0v[8], w1v[8], w2v[8], w3v[8], bbv[8];
        {
            const float* wr0 = w1 + (size_t)(2*Hdim + 0)*H2 + col;
            const float* wr1 = w1 + (size_t)(2*Hdim + 1)*H2 + col;
            const float* wr2 = w1 + (size_t)(2*Hdim + 2)*H2 + col;
            const float* wr3 = w1 + (size_t)(2*Hdim + 3)*H2 + col;
            const float* bbr = b1 + col;
            #pragma unroll
            for (int q = 0; q < 8; q += 4) {
                *(float4*)(w0v+q) = *(const float4*)(wr0+q);
                *(float4*)(w1v+q) = *(const float4*)(wr1+q);
                *(float4*)(w2v+q) = *(const float4*)(wr2+q);
                *(float4*)(w3v+q) = *(const float4*)(wr3+q);
                *(float4*)(bbv+q) = *(const float4*)(bbr+q);
            }
        }

        // compute A tiles from prefetched gathers
        #pragma unroll
        for (int it = 0; it < 4; it++) {
            float pi[8], qi[8], pj[8], qj[8];
            cvt8h(gp[it*4+0], pi);
            cvt8h(gp[it*4+1], qi);
            cvt8h(gp[it*4+2], pj);
            cvt8h(gp[it*4+3], qj);
            float e0 = efr[it][0], e1 = efr[it][1], e2 = efr[it][2], e3 = efr[it][3];
            float rf[8], rr[8];
            #pragma unroll
            for (int q = 0; q < 8; q++) {
                float eu = e0*w0v[q] + e1*w1v[q] + e2*w2v[q];
                float ed = e3*w3v[q] + bbv[q];
                rf[q] = gelu_exact(pi[q] + qj[q] + eu + ed);
                rr[q] = gelu_exact(pj[q] + qi[q] - eu + ed);
            }
            *(uint4*)(sAf + so + (uint32_t)(it * 4096)) = pack8h(rf);
            *(uint4*)(sAr + so + (uint32_t)(it * 4096)) = pack8h(rr);
        }

        // prefetch chunk c+1
        if (c + 1 < NCH) {
            int coln = ((c + 1) << 6) + oct * 8;
            #pragma unroll
            for (int it = 0; it < 4; it++) {
                gp[it*4+0] = *(const uint4*)(g_PQ + (size_t)ei4[it]*HU + coln);
                gp[it*4+1] = *(const uint4*)(g_PQ + (size_t)ei4[it]*HU + 512 + coln);
                gp[it*4+2] = *(const uint4*)(g_PQ + (size_t)ej4[it]*HU + coln);
                gp[it*4+3] = *(const uint4*)(g_PQ + (size_t)ej4[it]*HU + 512 + coln);
            }
            int k0n = (c + 1) << 6;
            #pragma unroll
            for (int i2 = 0; i2 < 8; i2++) {
                int idx = tid + i2 * 256;
                int rB = idx >> 3, fB = idx & 7;
                rbB[i2] = *(const uint4*)(w2t + (size_t)rB * H2 + k0n + fB * 8);
            }
        }

        asm volatile("fence.proxy.async.shared::cta;" ::: "memory");
        __syncthreads();

        if (tid == 0) {
            uint32_t afaddr = ub + (uint32_t)(buf * 65536);
            uint32_t araddr = afaddr + 16384u;
            uint32_t baddr  = afaddr + 32768u;
            uint64_t adescF = DESC_BASE | (uint64_t)((afaddr >> 4) & 0x3FFFu);
            uint64_t adescR = DESC_BASE | (uint64_t)((araddr >> 4) & 0x3FFFu);
            uint64_t bdesc  = DESC_BASE | (uint64_t)((baddr  >> 4) & 0x3FFFu);
            #pragma unroll
            for (int s = 0; s < 4; s++) {
                bool acc = !(c == 0 && s == 0);
                mma_f16_ss(tmem,        adescF + 2u*s, bdesc + 2u*s, MMA_IDESC, acc);
                mma_f16_ss(tmem + 256u, adescR + 2u*s, bdesc + 2u*s, MMA_IDESC, acc);
            }
            asm volatile(
                "tcgen05.commit.cta_group::1.mbarrier::arrive::one.shared::cluster.b64 [%0];"
                :: "r"(mbar0 + 8u * buf) : "memory");
        }
    }
    mbar_wait(mbar0 + 8u * ((NCH - 2) & 1), (uint32_t)(((NCH - 2) >> 1) & 1));
    mbar_wait(mbar0 + 8u * ((NCH - 1) & 1), (uint32_t)(((NCH - 1) >> 1) & 1));
    asm volatile("tcgen05.fence::after_thread_sync;" ::: "memory");

    {
        int dir = wid >> 2;
        int wd  = wid & 3;
        int trow = wd * 32 + lane;
        int m = m0 + trow;
        __half* M = dir ? g_Mr : g_Mf;
        uint32_t dbase = tmem + (uint32_t)(dir * 256);
        #pragma unroll
        for (int cc = 0; cc < 256; cc += 32) {
            uint32_t r[32];
            LDTM_X32(r, dbase + (uint32_t)cc);
            asm volatile("tcgen05.wait::ld.sync.aligned;" ::: "memory");
            #pragma unroll
            for (int q = 0; q < 32; q += 4) {
                float o[4] = {__uint_as_float(r[q]),   __uint_as_float(r[q+1]),
                              __uint_as_float(r[q+2]), __uint_as_float(r[q+3])};
                st4h(M + (size_t)m * Hdim + cc + q, o);
            }
        }
    }
    __syncthreads();
    if (wid == 0) {
        asm volatile("tcgen05.dealloc.cta_group::1.sync.aligned.b32 %0, %1;"
                     :: "r"(tmem), "r"(512u));
    }

#else  // -------- SIMT fallback (compute_103 PTX pass; compile-only path) -----
    float* As = (float*)dyn;
    float* Bs = (float*)(dyn + 8192);
    float* ef = (float*)(dyn + 16384);

    if (tid < 128) {
        int m = m0 + tid;
        int i = g_ei[m], j = g_ej[m];
        float dx = xyz[3*j+0] - xyz[3*i+0];
        float dy = xyz[3*j+1] - xyz[3*i+1];
        float dz = xyz[3*j+2] - xyz[3*i+2];
        float d = fmaxf(sqrtf(dx*dx + dy*dy + dz*dz), 1e-6f);
        float inv = 1.0f / d;
        ef[tid*4+0] = dx*inv; ef[tid*4+1] = dy*inv; ef[tid*4+2] = dz*inv; ef[tid*4+3] = d;
    }
    __syncthreads();

    int tr = tid >> 4, tc = tid & 15;
    for (int dir = 0; dir < 2; dir++) {
        for (int half = 0; half < 2; half++) {
            int n0h = half * 128;
            float acc[8][8] = {};
            for (int k0 = 0; k0 < H2; k0 += 16) {
                #pragma unroll
                for (int e = 0; e < 8; e++) {
                    int idx = tid * 8 + e;
                    int kk = idx >> 7, rr2 = idx & 127;
                    int m = m0 + rr2;
                    int i = g_ei[m], j = g_ej[m];
                    int colk = k0 + kk;
                    float e0 = ef[rr2*4], e1 = ef[rr2*4+1], e2 = ef[rr2*4+2], e3 = ef[rr2*4+3];
                    float eu = e0*w1[(size_t)(2*Hdim+0)*H2+colk]
                             + e1*w1[(size_t)(2*Hdim+1)*H2+colk]
                             + e2*w1[(size_t)(2*Hdim+2)*H2+colk];
                    float ed = e3*w1[(size_t)(2*Hdim+3)*H2+colk] + b1[colk];
                    float pv, qv;
                    if (dir == 0) {
                        pv = __half2float(g_PQ[(size_t)i*HU + colk]);
                        qv = __half2float(g_PQ[(size_t)j*HU + 512 + colk]);
                        As[kk*128 + rr2] = gelu_exact(pv + qv + eu + ed);
                    } else {
                        pv = __half2float(g_PQ[(size_t)j*HU + colk]);
                        qv = __half2float(g_PQ[(size_t)i*HU + 512 + colk]);
                        As[kk*128 + rr2] = gelu_exact(pv + qv - eu + ed);
                    }
                    Bs[kk*128 + rr2] = __half2float(w2t[(size_t)(n0h + rr2) * H2 + colk]);
                }
                __syncthreads();
                #pragma unroll
                for (int k = 0; k < 16; k++) {
                    float a[8], b[8];
                    #pragma unroll
                    for (int i2 = 0; i2 < 8; i2++) a[i2] = As[k*128 + tr*8 + i2];
                    #pragma unroll
                    for (int j2 = 0; j2 < 8; j2++) b[j2] = Bs[k*128 + tc*8 + j2];
                    #pragma unroll
                    for (int i2 = 0; i2 < 8; i2++)
                        #pragma unroll
                        for (int j2 = 0; j2 < 8; j2++)
                            acc[i2][j2] += a[i2] * b[j2];
                }
                __syncthreads();
            }
            __half* M = dir ? g_Mr : g_Mf;
            int col0 = n0h + tc * 8;
            #pragma unroll
            for (int i2 = 0; i2 < 8; i2++) {
                int m = m0 + tr * 8 + i2;
                for (int j2 = 0; j2 < 8; j2++)
                    M[(size_t)m * Hdim + col0 + j2] = __float2half(acc[i2][j2]);
            }
            __syncthreads();
        }
    }
#endif
}

// ============================================================================
// fused update-MLP kernel:
//   out = (h2 + gelu(hu@u1 + bu1) @ u2 + bu2) * valid
// Tile: 128 rows. hu tile resident in SMEM. 4 phases over T1's 1024 cols:
//   D1 (TMEM 256-511) = hu @ u1t[p]; epilogue gelu+bu1 -> sA2; D2 (TMEM 0-255) += sA2 @ u2t[p].
// ============================================================================
__global__ void __launch_bounds__(256, 1)
fused_mlp_kernel(const __half* __restrict__ u1t,   // [1024,256]
                 const __half* __restrict__ u2t,   // [256,1024]
                 const float* __restrict__ bu1,
                 const float* __restrict__ bu2,
                 float* __restrict__ out) {
    extern __shared__ char dyn[];
    int tid = threadIdx.x;
    int m0 = blockIdx.x * 128;

#if HAS_TC
    uint32_t u0 = smem_u32(dyn);
    uint32_t pad = (1024u - (u0 & 1023u)) & 1023u;
    char* base = dyn + pad;
    uint32_t ub = u0 + pad;

    // layout: sHu 4x16K @0, sA2 4x16K @64K, sB 2x32K @128K, ctrl @192K
    uint32_t ctrl  = ub + 196608;
    uint32_t mbar0 = ctrl + 8;

    int wid = tid >> 5;
    int lane = tid & 31;

    if (tid == 0) {
        asm volatile("mbarrier.init.shared.b64 [%0], 1;" :: "r"(mbar0)     : "memory");
        asm volatile("mbarrier.init.shared.b64 [%0], 1;" :: "r"(mbar0 + 8) : "memory");
    }
    if (wid == 0) {
        asm volatile("tcgen05.alloc.cta_group::1.sync.aligned.shared::cta.b32 [%0], %1;"
                     :: "r"(ctrl), "r"(512u) : "memory");
        asm volatile("tcgen05.relinquish_alloc_permit.cta_group::1.sync.aligned;");
    }
    __syncthreads();
    uint32_t tmem;
    asm volatile("ld.shared.b32 %0, [%1];" : "=r"(tmem) : "r"(ctrl));

    // load hu tile (128 x 256 halves) into 4 chunk tiles
    #pragma unroll
    for (int i2 = 0; i2 < 16; i2++) {
        int g = tid + i2 * 256;          // 0..4095
        int r = g >> 5;                  // 0..127
        int f = g & 31;                  // col vec (8 halves)
        uint4 v = *(const uint4*)(g_hu + (size_t)(m0 + r) * Hdim + f * 8);
        uint32_t sob = (uint32_t)(r * 128 + (f & 7) * 16);
        sob ^= (sob >> 3) & 0x70u;
        *(uint4*)(base + (f >> 3) * 16384 + sob) = v;
    }

    int rB = tid >> 3, fB = tid & 7;
    uint32_t sobB = (uint32_t)(rB * 128 + fB * 16);
    sobB ^= (sobB >> 3) & 0x70u;

    int trow = (wid & 3) * 32 + lane;
    int colhalf = (wid >> 2) * 128;

    uint32_t D2 = tmem;
    uint32_t D1 = tmem + 256u;

    int cidx = 0;
    for (int p = 0; p < 4; p++) {
        // ---- GEMM1: D1 = hu @ u1t rows [p*256 .. +255] ----
        for (int c = 0; c < 4; c++) {
            int buf = cidx & 1;
            if (cidx >= 2) mbar_wait(mbar0 + 8u*buf, (uint32_t)(((cidx-2) >> 1) & 1));
            char* sB = base + 131072 + buf * 32768;
            // B tile: 256 rows x 64 halves (each thread 8 vectors: rows rB, rB+32,...)
            #pragma unroll
            for (int i2 = 0; i2 < 8; i2++) {
                int rr = rB + i2 * 32;
                uint4 bv = *(const uint4*)(u1t + (size_t)(p*256 + rr) * Hdim + c*64 + fB*8);
                uint32_t sob = (uint32_t)(rr * 128 + fB * 16);
                sob ^= (sob >> 3) & 0x70u;
                *(uint4*)(sB + sob) = bv;
            }
            asm volatile("fence.proxy.async.shared::cta;" ::: "memory");
            __syncthreads();
            if (tid == 0) {
                uint32_t aaddr = ub + (uint32_t)(c * 16384);
                uint32_t baddr = ub + (uint32_t)(131072 + buf * 32768);
                uint64_t adesc = DESC_BASE | (uint64_t)((aaddr >> 4) & 0x3FFFu);
                uint64_t bdesc = DESC_BASE | (uint64_t)((baddr >> 4) & 0x3FFFu);
                #pragma unroll
                for (int s = 0; s < 4; s++)
                    mma_f16_ss(D1, adesc + 2u*s, bdesc + 2u*s, MMA_IDESC, !(c == 0 && s == 0));
                asm volatile(
                    "tcgen05.commit.cta_group::1.mbarrier::arrive::one.shared::cluster.b64 [%0];"
                    :: "r"(mbar0 + 8u*buf) : "memory");
            }
            cidx++;
        }
        // wait all GEMM1 commits
        mbar_wait(mbar0 + 8u*((cidx-1)&1), (uint32_t)(((cidx-1) >> 1) & 1));
        mbar_wait(mbar0 + 8u*((cidx-2)&1), (uint32_t)(((cidx-2) >> 1) & 1));
        asm volatile("tcgen05.fence::after_thread_sync;" ::: "memory");

        // ---- epilogue1: gelu(D1 + bu1) -> sA2 (4 chunk tiles) ----
        #pragma unroll
        for (int cc2 = 0; cc2 < 4; cc2++) {
            int col = colhalf + cc2 * 32;
            uint32_t r[32];
            LDTM_X32(r, D1 + (uint32_t)col);
            asm volatile("tcgen05.wait::ld.sync.aligned;" ::: "memory");
            #pragma unroll
            for (int q = 0; q < 32; q += 8) {
                int ck = col + q;
                float o[8];
                #pragma unroll
                for (int e = 0; e < 8; e++)
                    o[e] = gelu_exact(__uint_as_float(r[q+e]) + __ldg(&bu1[p*256 + ck + e]));
                uint32_t sob = (uint32_t)(trow * 128 + ((ck >> 3) & 7) * 16);
                sob ^= (sob >> 3) & 0x70u;
                *(uint4*)(base + 65536 + (ck >> 6) * 16384 + sob) = pack8h(o);
            }
        }
        // sA2 stores are pre-fence of next chunk's fence/sync

        // ---- GEMM2: D2 += sA2 @ u2t[:, p*256 + c*64 ...] ----
        for (int c = 0; c < 4; c++) {
            int buf = cidx & 1;
            mbar_wait(mbar0 + 8u*buf, (uint32_t)(((cidx-2) >> 1) & 1));
            char* sB = base + 131072 + buf * 32768;
            #pragma unroll
            for (int i2 = 0; i2 < 8; i2++) {
                int rr = rB + i2 * 32;
                uint4 bv = *(const uint4*)(u2t + (size_t)rr * HU + p*256 + c*64 + fB*8);
                uint32_t sob = (uint32_t)(rr * 128 + fB * 16);
                sob ^= (sob >> 3) & 0x70u;
                *(uint4*)(sB + sob) = bv;
            }
            asm volatile("fence.proxy.async.shared::cta;" ::: "memory");
            __syncthreads();
            if (tid == 0) {
                uint32_t aaddr = ub + (uint32_t)(65536 + c * 16384);
                uint32_t baddr = ub + (uint32_t)(131072 + buf * 32768);
                uint64_t adesc = DESC_BASE | (uint64_t)((aaddr >> 4) & 0x3FFFu);
                uint64_t bdesc = DESC_BASE | (uint64_t)((baddr >> 4) & 0x3FFFu);
                #pragma unroll
                for (int s = 0; s < 4; s++)
                    mma_f16_ss(D2, adesc + 2u*s, bdesc + 2u*s, MMA_IDESC,
                               !(p == 0 && c == 0 && s == 0));
                asm volatile(
                    "tcgen05.commit.cta_group::1.mbarrier::arrive::one.shared::cluster.b64 [%0];"
                    :: "r"(mbar0 + 8u*buf) : "memory");
            }
            cidx++;
        }
    }
    mbar_wait(mbar0 + 8u*((cidx-1)&1), (uint32_t)(((cidx-1) >> 1) & 1));
    mbar_wait(mbar0 + 8u*((cidx-2)&1), (uint32_t)(((cidx-2) >> 1) & 1));
    asm volatile("tcgen05.fence::after_thread_sync;" ::: "memory");

    // ---- final epilogue: out = (h2 + D2 + bu2) * valid ----
    {
        int m = m0 + trow;
        float vf = g_valid[m] ? 1.0f : 0.0f;
        #pragma unroll
        for (int cc2 = 0; cc2 < 4; cc2++) {
            int col = colhalf + cc2 * 32;
            uint32_t r[32];
            LDTM_X32(r, D2 + (uint32_t)col);
            asm volatile("tcgen05.wait::ld.sync.aligned;" ::: "memory");
            const float* a2 = g_h2 + (size_t)m * Hdim + col;
            #pragma unroll
            for (int q = 0; q < 32; q += 4) {
                float4 av = *(const float4*)(a2 + q);
                float4 o;
                o.x = (av.x + __uint_as_float(r[q])   + __ldg(&bu2[col+q]))   * vf;
                o.y = (av.y + __uint_as_float(r[q+1]) + __ldg(&bu2[col+q+1])) * vf;
                o.z = (av.z + __uint_as_float(r[q+2]) + __ldg(&bu2[col+q+2])) * vf;
                o.w = (av.w + __uint_as_float(r[q+3]) + __ldg(&bu2[col+q+3])) * vf;
                *(float4*)(out + (size_t)m * Hdim + col + q) = o;
            }
        }
    }
    __syncthreads();
    if (wid == 0) {
        asm volatile("tcgen05.dealloc.cta_group::1.sync.aligned.b32 %0, %1;"
                     :: "r"(tmem), "r"(512u));
    }

#else  // -------- SIMT fallback: two naive GEMMs staged via g_T1 --------------
    float* As = (float*)dyn;
    float* Bs = (float*)(dyn + 8192);
    int tr = tid >> 4, tc = tid & 15;
    int lrow = tid >> 1;
    int lk   = (tid & 1) * 8;

    // GEMM1: T1 = gelu(hu @ u1t^T + bu1), N=1024 in 8 half-tiles
    for (int half = 0; half < 8; half++) {
        int n0h = half * 128;
        float acc[8][8] = {};
        for (int k0 = 0; k0 < Hdim; k0 += 16) {
            #pragma unroll
            for (int e = 0; e < 8; e++) {
                As[(lk+e)*128 + lrow] = __half2float(g_hu[(size_t)(m0 + lrow) * Hdim + k0 + lk + e]);
                Bs[(lk+e)*128 + lrow] = __half2float(u1t[(size_t)(n0h + lrow) * Hdim + k0 + lk + e]);
            }
            __syncthreads();
            #pragma unroll
            for (int k = 0; k < 16; k++) {
                float a[8], b[8];
                #pragma unroll
                for (int i2 = 0; i2 < 8; i2++) a[i2] = As[k*128 + tr*8 + i2];
                #pragma unroll
                for (int j2 = 0; j2 < 8; j2++) b[j2] = Bs[k*128 + tc*8 + j2];
                #pragma unroll
                for (int i2 = 0; i2 < 8; i2++)
                    #pragma unroll
                    for (int j2 = 0; j2 < 8; j2++)
                        acc[i2][j2] += a[i2] * b[j2];
            }
            __syncthreads();
        }
        int col0 = n0h + tc * 8;
        #pragma unroll
        for (int i2 = 0; i2 < 8; i2++) {
            int m = m0 + tr * 8 + i2;
            for (int j2 = 0; j2 < 8; j2++)
                g_T1[(size_t)m * HU + col0 + j2] =
                    __float2half(gelu_exact(acc[i2][j2] + bu1[col0 + j2]));
        }
        __syncthreads();
    }

    // GEMM2: out = (h2 + T1 @ u2t^T + bu2) * valid, N=256 in 2 half-tiles
    for (int half = 0; half < 2; half++) {
        int n0h = half * 128;
        float acc[8][8] = {};
        for (int k0 = 0; k0 < HU; k0 += 16) {
            #pragma unroll
            for (int e = 0; e < 8; e++) {
                As[(lk+e)*128 + lrow] = __half2float(g_T1[(size_t)(m0 + lrow) * HU + k0 + lk + e]);
                Bs[(lk+e)*128 + lrow] = __half2float(u2t[(size_t)(n0h + lrow) * HU + k0 + lk + e]);
            }
            __syncthreads();
            #pragma unroll
            for (int k = 0; k < 16; k++) {
                float a[8], b[8];
                #pragma unroll
                for (int i2 = 0; i2 < 8; i2++) a[i2] = As[k*128 + tr*8 + i2];
                #pragma unroll
                for (int j2 = 0; j2 < 8; j2++) b[j2] = Bs[k*128 + tc*8 + j2];
                #pragma unroll
                for (int i2 = 0; i2 < 8; i2++)
                    #pragma unroll
                    for (int j2 = 0; j2 < 8; j2++)
                        acc[i2][j2] += a[i2] * b[j2];
            }
            __syncthreads();
        }
        int col0 = n0h + tc * 8;
        #pragma unroll
        for (int i2 = 0; i2 < 8; i2++) {
            int m = m0 + tr * 8 + i2;
            float vf = g_valid[m] ? 1.0f : 0.0f;
            for (int j2 = 0; j2 < 8; j2++)
                out[(size_t)m * Hdim + col0 + j2] =
                    (g_h2[(size_t)m * Hdim + col0 + j2] + acc[i2][j2] + bu2[col0 + j2]) * vf;
        }
        __syncthreads();
    }
#endif
}

// ============================================================================
// dense tcgen05 f16 GEMM (PQ only), register-prefetched double-buffered.
// ============================================================================
template<int EPI>
__global__ void __launch_bounds__(256, 2)
mma_gemm(const __half* __restrict__ A, int lda,
         const __half* __restrict__ Bt,
         void* __restrict__ CoutV, int ldc,
         int K) {
    extern __shared__ char dyn[];
    int tid = threadIdx.x;
    int n0 = blockIdx.x * 256;
    int m0 = blockIdx.y * 128;

#if HAS_TC
    uint32_t u0 = smem_u32(dyn);
    uint32_t pad = (1024u - (u0 & 1023u)) & 1023u;
    char* base = dyn + pad;
    uint32_t ub = u0 + pad;

    uint32_t ctrl  = ub + 98304;
    uint32_t mbar0 = ctrl + 8;

    int wid = tid >> 5;
    int lane = tid & 31;

    if (tid == 0) {
        asm volatile("mbarrier.init.shared.b64 [%0], 1;" :: "r"(mbar0)     : "memory");
        asm volatile("mbarrier.init.shared.b64 [%0], 1;" :: "r"(mbar0 + 8) : "memory");
    }
    if (wid == 0) {
        asm volatile("tcgen05.alloc.cta_group::1.sync.aligned.shared::cta.b32 [%0], %1;"
                     :: "r"(ctrl), "r"(256u) : "memory");
        asm volatile("tcgen05.relinquish_alloc_permit.cta_group::1.sync.aligned;");
    }
    __syncthreads();
    uint32_t tmem;
    asm volatile("ld.shared.b32 %0, [%1];" : "=r"(tmem) : "r"(ctrl));

    int rA = tid >> 3, f4 = tid & 7;
    uint32_t soA = (uint32_t)(rA * 128 + f4 * 16);
    soA ^= (soA >> 3) & 0x70u;
    const __half* Abase = A + (size_t)(m0 + rA) * lda + f4 * 8;
    const __half* Bbase = Bt + (size_t)(n0 + rA) * K + f4 * 8;
    size_t strideA = (size_t)32 * lda;
    size_t strideB = (size_t)32 * K;

    uint4 ra[4], rb[8];
    const int NCH = K >> 6;

    #pragma unroll
    for (int i = 0; i < 4; i++) ra[i] = *(const uint4*)(Abase + i * strideA);
    #pragma unroll
    for (int i = 0; i < 8; i++) rb[i] = *(const uint4*)(Bbase + i * strideB);

    #pragma unroll 2
    for (int c = 0; c < NCH; c++) {
        int buf = c & 1;
        if (c >= 2) mbar_wait(mbar0 + 8u * buf, (uint32_t)(((c - 2) >> 1) & 1));
        char* sA = base + buf * 16384;
        char* sB = base + 32768 + buf * 32768;

        #pragma unroll
        for (int i = 0; i < 4; i++)
            *(uint4*)(sA + soA + (uint32_t)(i * 4096)) = ra[i];
        #pragma unroll
        for (int i = 0; i < 8; i++)
            *(uint4*)(sB + soA + (uint32_t)(i * 4096)) = rb[i];

        if (c + 1 < NCH) {
            const __half* An = Abase + (c + 1) * 64;
            const __half* Bn = Bbase + (c + 1) * 64;
            #pragma unroll
            for (int i = 0; i < 4; i++) ra[i] = *(const uint4*)(An + i * strideA);
            #pragma unroll
            for (int i = 0; i < 8; i++) rb[i] = *(const uint4*)(Bn + i * strideB);
        }

        asm volatile("fence.proxy.async.shared::cta;" ::: "memory");
        __syncthreads();

        if (tid == 0) {
            uint32_t aaddr = ub + (uint32_t)(buf * 16384);
            uint32_t baddr = ub + (uint32_t)(32768 + buf * 32768);
            uint64_t adesc = DESC_BASE | (uint64_t)((aaddr >> 4) & 0x3FFFu);
            uint64_t bdesc = DESC_BASE | (uint64_t)((baddr >> 4) & 0x3FFFu);
            #pragma unroll
            for (int s = 0; s < 4; s++) {
                mma_f16_ss(tmem, adesc + 2u * s, bdesc + 2u * s, MMA_IDESC,
                           !(c == 0 && s == 0));
            }
            asm volatile(
                "tcgen05.commit.cta_group::1.mbarrier::arrive::one.shared::cluster.b64 [%0];"
                :: "r"(mbar0 + 8u * buf) : "memory");
        }
    }
    mbar_wait(mbar0 + 8u * ((NCH - 2) & 1), (uint32_t)(((NCH - 2) >> 1) & 1));
    mbar_wait(mbar0 + 8u * ((NCH - 1) & 1), (uint32_t)(((NCH - 1) >> 1) & 1));
    asm volatile("tcgen05.fence::after_thread_sync;" ::: "memory");

    if (wid < 4) {
        int trow = wid * 32 + lane;
        int m = m0 + trow;
        #pragma unroll
        for (int cc = 0; cc < 256; cc += 32) {
            uint32_t r[32];
            LDTM_X32(r, tmem + (uint32_t)cc);
            asm volatile("tcgen05.wait::ld.sync.aligned;" ::: "memory");
            int col0 = n0 + cc;
            __half* Cout = (__half*)CoutV;
            #pragma unroll
            for (int j = 0; j < 32; j += 4) {
                float o[4] = {__uint_as_float(r[j]), __uint_as_float(r[j+1]),
                              __uint_as_float(r[j+2]), __uint_as_float(r[j+3])};
                st4h(Cout + (size_t)m * ldc + col0 + j, o);
            }
        }
    }
    __syncthreads();
    if (wid == 0) {
        asm volatile("tcgen05.dealloc.cta_group::1.sync.aligned.b32 %0, %1;"
                     :: "r"(tmem), "r"(256u));
    }

#else  // ---------------- SIMT fallback ----------------------------------------
    float* As = (float*)dyn;
    float* Bs = (float*)(dyn + 8192);

    int tr = tid >> 4, tc = tid & 15;
    int lrow = tid >> 1;
    int lk   = (tid & 1) * 8;

    for (int half = 0; half < 2; half++) {
        int n0h = n0 + half * 128;
        float acc[8][8] = {};
        for (int k0 = 0; k0 < K; k0 += 16) {
            #pragma unroll
            for (int e = 0; e < 8; e++) {
                As[(lk+e)*128 + lrow] = __half2float(A[(size_t)(m0 + lrow) * lda + k0 + lk + e]);
                Bs[(lk+e)*128 + lrow] = __half2float(Bt[(size_t)(n0h + lrow) * K + k0 + lk + e]);
            }
            __syncthreads();
            #pragma unroll
            for (int k = 0; k < 16; k++) {
                float a[8], b[8];
                #pragma unroll
                for (int i = 0; i < 8; i++) a[i] = As[k*128 + tr*8 + i];
                #pragma unroll
                for (int j = 0; j < 8; j++) b[j] = Bs[k*128 + tc*8 + j];
                #pragma unroll
                for (int i = 0; i < 8; i++)
                    #pragma unroll
                    for (int j = 0; j < 8; j++)
                        acc[i][j] += a[i] * b[j];
            }
            __syncthreads();
        }

        int col0 = n0h + tc * 8;
        __half* Cout = (__half*)CoutV;
        #pragma unroll
        for (int i = 0; i < 8; i++) {
            int m = m0 + tr * 8 + i;
            for (int j = 0; j < 8; j++)
                Cout[(size_t)m * ldc + col0 + j] = __float2half(acc[i][j]);
        }
        __syncthreads();
    }
#endif
}

// ---------------- launch -----------------------------------------------------
extern "C" void kernel_launch(void* const* d_in, const int* in_sizes, int n_in,
                              void* d_out, int out_size) {
    const float*         h      = (const float*)d_in[0];
    const float*         xyz    = (const float*)d_in[1];
    const unsigned char* validb = (const unsigned char*)d_in[2];
    const float*         ln_n_w = (const float*)d_in[3];
    const float*         ln_n_b = (const float*)d_in[4];
    const float*         w1     = (const float*)d_in[5];
    const float*         b1     = (const float*)d_in[6];
    const float*         w2     = (const float*)d_in[7];
    const float*         b2     = (const float*)d_in[8];
    const float*         ln_u_w = (const float*)d_in[9];
    const float*         ln_u_b = (const float*)d_in[10];
    const float*         u1     = (const float*)d_in[11];
    const float*         bu1    = (const float*)d_in[12];
    const float*         u2     = (const float*)d_in[13];
    const float*         bu2    = (const float*)d_in[14];
    float* out = (float*)d_out;

    __half *pHin, *pPQ, *pWabt, *pW2t, *pU1t, *pU2t;
    cudaGetSymbolAddress((void**)&pHin, g_hin);
    cudaGetSymbolAddress((void**)&pPQ,  g_PQ);
    cudaGetSymbolAddress((void**)&pWabt, g_wabt);
    cudaGetSymbolAddress((void**)&pW2t,  g_w2t);
    cudaGetSymbolAddress((void**)&pU1t,  g_u1t);
    cudaGetSymbolAddress((void**)&pU2t,  g_u2t);

    cudaFuncSetAttribute(mma_gemm<0>, cudaFuncAttributeMaxDynamicSharedMemorySize, SMEM_DYN);
    cudaFuncSetAttribute(edge_msg_kernel, cudaFuncAttributeMaxDynamicSharedMemorySize, SMEM_EDGE);
    cudaFuncSetAttribute(fused_mlp_kernel, cudaFuncAttributeMaxDynamicSharedMemorySize, SMEM_MLP);

    detect_vmode_kernel<<<1, 256>>>(validb);
    conv_valid_kernel<<<(NC + 255) / 256, 256>>>(validb);
    clear_pos_kernel<<<4*NC/256, 256>>>();
    transpose_all_kernel<<<917504/256, 256>>>(w1, w2, u1, u2);
    ln_kernel<<<NC/8, 256>>>(h, ln_n_w, ln_n_b, pHin);
    count_kernel<<<NB, 256>>>();
    // PQ = h_in @ [W1a | W1b]
    mma_gemm<0><<<dim3(4, NC/128), 256, SMEM_DYN>>>(pHin, Hdim, pWabt, pPQ, HU, Hdim);
    scan_kernel<<<1, 256>>>();
    scatter_kernel<<<NB, 256>>>();

    edge_msg_kernel<<<MAXE/128, 256, SMEM_EDGE>>>(xyz, w1, b1, pW2t);

    gather_ln_kernel<<<NC/8, 256>>>(h, b2, ln_u_w, ln_u_b);

    fused_mlp_kernel<<<NC/128, 256, SMEM_MLP>>>(pU1t, pU2t, bu1, bu2, out);
    (void)in_sizes; (void)n_in; (void)out_size;
}